// round 9
// baseline (speedup 1.0000x reference)
#include <cuda_runtime.h>
#include <cuda_bf16.h>
#include <math.h>
#include <stdint.h>

// Problem constants
#define B_    2
#define L_    4096
#define E_    1024
#define NI    2048      // N_INNER
#define NS    128       // N_STATE
#define NH    32        // N_HEAD
#define HD    64        // HEADDIM
#define NCONV 4
#define CH    64        // CHUNK
#define NC    64        // chunks per sequence (L/CHUNK)
#define CD    2304      // CONV_DIM = NI + 2*NS
#define DIN   4384      // 2*NI + 2*NS + NH
#define NPAD  4480      // DIN padded to multiple of 128
#define ROWS  (B_*L_)   // 8192

// ---------------- scratch (device globals; no allocation allowed) ----------
__device__ float g_zx[(size_t)ROWS * DIN];
__device__ float g_x [(size_t)ROWS * NI];
__device__ float g_Bm[(size_t)ROWS * NS];
__device__ float g_Cm[(size_t)ROWS * NS];
__device__ float g_dt[(size_t)ROWS * NH];
__device__ float g_G [(size_t)B_ * NC * CH * CH];
__device__ float g_st[(size_t)B_ * NC * NH * HD * NS];
__device__ float g_asum[B_ * NC * NH];
__device__ float g_yin[(size_t)ROWS * NI];

// bf16 hi/lo operand copies for tensor-core GEMMs
__device__ __nv_bfloat16 g_u_hi[(size_t)ROWS * E_];
__device__ __nv_bfloat16 g_u_lo[(size_t)ROWS * E_];
__device__ __nv_bfloat16 g_win_hi[(size_t)E_ * NPAD];
__device__ __nv_bfloat16 g_win_lo[(size_t)E_ * NPAD];
__device__ __nv_bfloat16 g_wout_hi[(size_t)NI * E_];
__device__ __nv_bfloat16 g_wout_lo[(size_t)NI * E_];
__device__ __nv_bfloat16 g_ynb_hi[(size_t)ROWS * NI];
__device__ __nv_bfloat16 g_ynb_lo[(size_t)ROWS * NI];

// ---------------- small helpers ----------------
__device__ __forceinline__ float siluf(float x) { return x / (1.f + expf(-x)); }
__device__ __forceinline__ float softplusf(float x) {
    return (x > 20.f) ? x : log1pf(expf(x));
}
__device__ __forceinline__ uint32_t smem_u32(const void* p) {
    uint32_t a;
    asm("{ .reg .u64 t; cvta.to.shared.u64 t, %1; cvt.u32.u64 %0, t; }" : "=r"(a) : "l"(p));
    return a;
}

// ---------------- packed f32x2 (Blackwell, base sm_100) ----------------
__device__ __forceinline__ uint64_t pack2(float x, float y) {
    uint64_t r;
    asm("mov.b64 %0, {%1, %2};" : "=l"(r) : "f"(x), "f"(y));
    return r;
}
__device__ __forceinline__ void unpack2(uint64_t v, float& x, float& y) {
    asm("mov.b64 {%0, %1}, %2;" : "=f"(x), "=f"(y) : "l"(v));
}
__device__ __forceinline__ void ffma2(uint64_t& d, uint64_t a, uint64_t b) {
    asm("fma.rn.f32x2 %0, %1, %2, %0;" : "+l"(d) : "l"(a), "l"(b));
}
__device__ __forceinline__ void fmul2(uint64_t& d, uint64_t a) {
    asm("mul.rn.f32x2 %0, %0, %1;" : "+l"(d) : "l"(a));
}

// ---------------- warp-MMA primitives (sm_80+, valid on base sm_100) -------
__device__ __forceinline__ void ldm_x4(uint32_t* r, uint32_t addr) {
    asm volatile("ldmatrix.sync.aligned.m8n8.x4.shared.b16 {%0,%1,%2,%3}, [%4];"
        : "=r"(r[0]), "=r"(r[1]), "=r"(r[2]), "=r"(r[3]) : "r"(addr));
}
__device__ __forceinline__ void ldm_x2t(uint32_t* r, uint32_t addr) {
    asm volatile("ldmatrix.sync.aligned.m8n8.x2.trans.shared.b16 {%0,%1}, [%2];"
        : "=r"(r[0]), "=r"(r[1]) : "r"(addr));
}
__device__ __forceinline__ void mma_bf16(float* c, const uint32_t* a, const uint32_t* b) {
    asm volatile(
        "mma.sync.aligned.m16n8k16.row.col.f32.bf16.bf16.f32 "
        "{%0,%1,%2,%3}, {%4,%5,%6,%7}, {%8,%9}, {%0,%1,%2,%3};"
        : "+f"(c[0]), "+f"(c[1]), "+f"(c[2]), "+f"(c[3])
        : "r"(a[0]), "r"(a[1]), "r"(a[2]), "r"(a[3]), "r"(b[0]), "r"(b[1]));
}
__device__ __forceinline__ void cp16(uint32_t dst, const void* src) {
    asm volatile("cp.async.cg.shared.global [%0], [%1], 16;" :: "r"(dst), "l"(src));
}
#define CP_COMMIT() asm volatile("cp.async.commit_group;" ::: "memory")
#define CP_WAIT(n)  asm volatile("cp.async.wait_group %0;" :: "n"(n) : "memory")

// ---------------- fp32 -> bf16 hi/lo conversion kernels ----------------
__global__ void cvt_hilo_kernel(const float* __restrict__ s,
                                __nv_bfloat16* __restrict__ hi,
                                __nv_bfloat16* __restrict__ lo, int n)
{
    int i = (blockIdx.x * blockDim.x + threadIdx.x) * 4;
    if (i >= n) return;
    float4 v = *(const float4*)(s + i);
    float f[4] = {v.x, v.y, v.z, v.w};
    ushort hh[4], ll[4];
#pragma unroll
    for (int j = 0; j < 4; j++) {
        __nv_bfloat16 h = __float2bfloat16_rn(f[j]);
        __nv_bfloat16 l = __float2bfloat16_rn(f[j] - __bfloat162float(h));
        hh[j] = __bfloat16_as_ushort(h);
        ll[j] = __bfloat16_as_ushort(l);
    }
    *(ushort4*)((ushort*)hi + i) = make_ushort4(hh[0], hh[1], hh[2], hh[3]);
    *(ushort4*)((ushort*)lo + i) = make_ushort4(ll[0], ll[1], ll[2], ll[3]);
}

// w_in [E_][DIN] -> padded [E_][NPAD] hi/lo (zero-fill cols >= DIN)
__global__ void cvt_win_kernel(const float* __restrict__ w) {
    int i4 = (blockIdx.x * blockDim.x + threadIdx.x) * 4;
    if (i4 >= E_ * NPAD) return;
    int row = i4 / NPAD, col = i4 % NPAD;
    float f[4];
    if (col + 3 < DIN) {
        float4 v = *(const float4*)(w + (size_t)row * DIN + col);
        f[0] = v.x; f[1] = v.y; f[2] = v.z; f[3] = v.w;
    } else {
#pragma unroll
        for (int j = 0; j < 4; j++) {
            int cc = col + j;
            f[j] = (cc < DIN) ? w[(size_t)row * DIN + cc] : 0.f;
        }
    }
    ushort hh[4], ll[4];
#pragma unroll
    for (int j = 0; j < 4; j++) {
        __nv_bfloat16 h = __float2bfloat16_rn(f[j]);
        __nv_bfloat16 l = __float2bfloat16_rn(f[j] - __bfloat162float(h));
        hh[j] = __bfloat16_as_ushort(h);
        ll[j] = __bfloat16_as_ushort(l);
    }
    *(ushort4*)((ushort*)g_win_hi + i4) = make_ushort4(hh[0], hh[1], hh[2], hh[3]);
    *(ushort4*)((ushort*)g_win_lo + i4) = make_ushort4(ll[0], ll[1], ll[2], ll[3]);
}

// ================= tensor-core GEMM: C[M,N] = A[M,K] @ B[K,N] ==============
// bf16x3 split (hi*hi + hi*lo + lo*hi), fp32 accumulate.
// Block tile 256x128, 512 threads (16 warps: 4m x 4n, 64x32 per warp).
// K-tile 32, cp.async 3-stage pipeline; next-stage loads issued BEFORE MMAs.
#define ST_A_LO 20480
#define ST_B_HI 40960
#define ST_B_LO 49664
#define ST_BYTES 58368
#define STG 3
#define GM_SMEM (STG * ST_BYTES)

__global__ void __launch_bounds__(512, 1) gemm_bf16(
    const __nv_bfloat16* __restrict__ Ah, const __nv_bfloat16* __restrict__ Al,
    const __nv_bfloat16* __restrict__ Bh, const __nv_bfloat16* __restrict__ Bl,
    float* __restrict__ C, int M, int N, int K, int ldB)
{
    extern __shared__ char smem[];
    const uint32_t sb = smem_u32(smem);
    const int tid = threadIdx.x;
    const int wid = tid >> 5, lane = tid & 31;
    const int m0 = blockIdx.y * 256;
    const int n0 = blockIdx.x * 128;
    const int warp_m = wid >> 2;
    const int warp_n = wid & 3;

    float acc[4][4][4];
#pragma unroll
    for (int i = 0; i < 4; i++)
#pragma unroll
        for (int j = 0; j < 4; j++)
#pragma unroll
            for (int k = 0; k < 4; k++) acc[i][j][k] = 0.f;

    const int KTn = K >> 5;

    const int arow0 = tid >> 2, ach0 = tid & 3;
    const int arow1 = (tid + 512) >> 2, ach1 = tid & 3;
    const int bkr = tid >> 4, bch = tid & 15;

#define LOAD_STAGE(KT_) do { \
    const int k0_ = (KT_) << 5; \
    const uint32_t st_ = sb + ((KT_) % STG) * ST_BYTES; \
    { size_t go = (size_t)(m0 + arow0) * K + k0_ + ach0 * 8; \
      uint32_t so = st_ + arow0 * 80 + ach0 * 16; \
      cp16(so, Ah + go); cp16(so + ST_A_LO, Al + go); } \
    { size_t go = (size_t)(m0 + arow1) * K + k0_ + ach1 * 8; \
      uint32_t so = st_ + arow1 * 80 + ach1 * 16; \
      cp16(so, Ah + go); cp16(so + ST_A_LO, Al + go); } \
    { size_t go = (size_t)(k0_ + bkr) * ldB + n0 + bch * 8; \
      uint32_t so = st_ + ST_B_HI + bkr * 272 + bch * 16; \
      cp16(so, Bh + go); cp16(so + 8704, Bl + go); } \
} while (0)

#pragma unroll
    for (int s = 0; s < STG - 1; s++) {
        if (s < KTn) LOAD_STAGE(s);
        CP_COMMIT();
    }

    for (int kt = 0; kt < KTn; kt++) {
        CP_WAIT(STG - 2);
        __syncthreads();
        // issue next-stage loads BEFORE MMAs (writes stage (kt+2)%3, reads kt)
        if (kt + STG - 1 < KTn) LOAD_STAGE(kt + STG - 1);
        CP_COMMIT();

        const uint32_t sAhi = sb + (kt % STG) * ST_BYTES;
        const uint32_t sAlo = sAhi + ST_A_LO;
        const uint32_t sBhi = sAhi + ST_B_HI;
        const uint32_t sBlo = sAhi + ST_B_LO;
#pragma unroll
        for (int ks = 0; ks < 2; ks++) {
            uint32_t a_hi[4][4], a_lo[4][4], b_hi[4][2], b_lo[4][2];
#pragma unroll
            for (int mi = 0; mi < 4; mi++) {
                int row = warp_m * 64 + mi * 16 + (lane & 15);
                uint32_t addr = row * 80 + ks * 32 + (lane >> 4) * 16;
                ldm_x4(a_hi[mi], sAhi + addr);
                ldm_x4(a_lo[mi], sAlo + addr);
            }
#pragma unroll
            for (int ni = 0; ni < 4; ni++) {
                int krow = ks * 16 + (lane & 15);
                int ncol = warp_n * 32 + ni * 8;
                uint32_t addr = krow * 272 + ncol * 2;
                ldm_x2t(b_hi[ni], sBhi + addr);
                ldm_x2t(b_lo[ni], sBlo + addr);
            }
#pragma unroll
            for (int mi = 0; mi < 4; mi++)
#pragma unroll
                for (int ni = 0; ni < 4; ni++) {
                    mma_bf16(acc[mi][ni], a_hi[mi], b_hi[ni]);
                    mma_bf16(acc[mi][ni], a_hi[mi], b_lo[ni]);
                    mma_bf16(acc[mi][ni], a_lo[mi], b_hi[ni]);
                }
        }
    }
#undef LOAD_STAGE

#pragma unroll
    for (int mi = 0; mi < 4; mi++) {
        int row = m0 + warp_m * 64 + mi * 16 + (lane >> 2);
#pragma unroll
        for (int ni = 0; ni < 4; ni++) {
            int col = n0 + warp_n * 32 + ni * 8 + (lane & 3) * 2;
            if (col < N) {
                *(float2*)(C + (size_t)row * N + col) =
                    make_float2(acc[mi][ni][0], acc[mi][ni][1]);
                *(float2*)(C + (size_t)(row + 8) * N + col) =
                    make_float2(acc[mi][ni][2], acc[mi][ni][3]);
            }
        }
    }
}

// ---------------- dt = softplus(raw + bias) ----------------
__global__ void dt_kernel(const float* __restrict__ dt_bias) {
    int i = blockIdx.x * blockDim.x + threadIdx.x;
    if (i >= ROWS * NH) return;
    int row = i / NH, h = i % NH;
    float x = g_zx[(size_t)row * DIN + (DIN - NH) + h] + dt_bias[h];
    g_dt[i] = softplusf(x);
}

// --- depthwise causal conv w4 + silu + split; 4 channels x 8 timesteps ----
__global__ void conv_kernel(const float* __restrict__ init_conv,
                            const float* __restrict__ conv_w,
                            const float* __restrict__ conv_b)
{
    int d4 = blockIdx.x * blockDim.x + threadIdx.x;
    if (d4 >= CD / 4) return;
    const int d = d4 * 4;
    const int t0 = blockIdx.y * 8;
    const int b = blockIdx.z;
    float4 cw[4];
#pragma unroll
    for (int j = 0; j < 4; j++) cw[j] = *(const float4*)(conv_w + (d + j) * 4);
    float4 bias = *(const float4*)(conv_b + d);
    float4 win[11];
#pragma unroll
    for (int i = 0; i < 11; i++) {
        int ti = t0 - 3 + i;
        if (ti >= 0) {
            win[i] = *(const float4*)(g_zx + (size_t)(b * L_ + ti) * DIN + NI + d);
        } else {
            win[i].x = init_conv[((size_t)b * CD + d + 0) * NCONV + (4 + ti)];
            win[i].y = init_conv[((size_t)b * CD + d + 1) * NCONV + (4 + ti)];
            win[i].z = init_conv[((size_t)b * CD + d + 2) * NCONV + (4 + ti)];
            win[i].w = init_conv[((size_t)b * CD + d + 3) * NCONV + (4 + ti)];
        }
    }
#pragma unroll
    for (int jt = 0; jt < 8; jt++) {
        float4 o;
        o.x = siluf(bias.x + cw[0].x*win[jt].x + cw[0].y*win[jt+1].x + cw[0].z*win[jt+2].x + cw[0].w*win[jt+3].x);
        o.y = siluf(bias.y + cw[1].x*win[jt].y + cw[1].y*win[jt+1].y + cw[1].z*win[jt+2].y + cw[1].w*win[jt+3].y);
        o.z = siluf(bias.z + cw[2].x*win[jt].z + cw[2].y*win[jt+1].z + cw[2].z*win[jt+2].z + cw[2].w*win[jt+3].z);
        o.w = siluf(bias.w + cw[3].x*win[jt].w + cw[3].y*win[jt+1].w + cw[3].z*win[jt+2].w + cw[3].w*win[jt+3].w);
        int row = b * L_ + t0 + jt;
        if (d < NI)           *(float4*)(g_x  + (size_t)row * NI + d) = o;
        else if (d < NI + NS) *(float4*)(g_Bm + (size_t)row * NS + (d - NI)) = o;
        else                  *(float4*)(g_Cm + (size_t)row * NS + (d - NI - NS)) = o;
    }
}

// ---------------- new_conv_state output ----------------
__global__ void convstate_kernel(float* __restrict__ out) {
    int i = blockIdx.x * blockDim.x + threadIdx.x;
    if (i >= B_ * CD * NCONV) return;
    int k = i % NCONV;
    int d = (i / NCONV) % CD;
    int b = i / (NCONV * CD);
    out[i] = g_zx[(size_t)(b * L_ + (L_ - 4 + k)) * DIN + NI + d];
}

// ---------------- per-chunk Gram matrix G[l][s] = sum_n C[l,n]B[s,n] -------
__global__ void __launch_bounds__(256) gmat_kernel() {
    const int bc = blockIdx.x;
    const int b = bc / NC, c = bc % NC;
    const int row0 = b * L_ + c * CH;
    const int tid = threadIdx.x;
    __shared__ float sC[64 * 33];
    __shared__ float sB[64 * 33];
    const int l = tid >> 2;
    const int s0 = (tid & 3) * 16;
    float acc[16];
#pragma unroll
    for (int j = 0; j < 16; j++) acc[j] = 0.f;
    for (int n0 = 0; n0 < NS; n0 += 32) {
        for (int i = tid; i < 64 * 32; i += 256) {
            int r = i >> 5, nn = i & 31;
            sC[r * 33 + nn] = g_Cm[(size_t)(row0 + r) * NS + n0 + nn];
            sB[r * 33 + nn] = g_Bm[(size_t)(row0 + r) * NS + n0 + nn];
        }
        __syncthreads();
        for (int nn = 0; nn < 32; nn++) {
            float cv = sC[l * 33 + nn];
#pragma unroll
            for (int j = 0; j < 16; j++) acc[j] += cv * sB[(s0 + j) * 33 + nn];
        }
        __syncthreads();
    }
    float* Gp = g_G + (size_t)bc * (CH * CH);
#pragma unroll
    for (int j = 0; j < 16; j++) Gp[l * 64 + s0 + j] = acc[j];
}

// ------- per-chunk states[p][n] = sum_l B[l,n]*decay[l]*dt[l]*x[l,p] -------
// xs: [64 l][68 pad] of x*w ; sB: [64 l][132 pad] of B (full 128 n)
#define STATES_SMEM ((64*68 + 64*132) * 4)
__global__ void __launch_bounds__(256) states_kernel(const float* __restrict__ A_log) {
    extern __shared__ float sm[];
    float* xs = sm;             // [64][68]
    float* sB = sm + 64 * 68;   // [64][132]
    __shared__ float sdt[64], w[64];
    __shared__ float asum_s;
    const int h = blockIdx.x, c = blockIdx.y, b = blockIdx.z;
    const int tid = threadIdx.x;
    const int row0 = b * L_ + c * CH;
    if (tid < 64) sdt[tid] = g_dt[(size_t)(row0 + tid) * NH + h];
    __syncthreads();
    if (tid == 0) {
        float A = -expf(A_log[h]);
        float s = 0.f;
        for (int l = 0; l < 64; l++) { s += A * sdt[l]; w[l] = s; }  // w = acs (temp)
        asum_s = s;
        g_asum[(b * NC + c) * NH + h] = s;
    }
    __syncthreads();
    float wv = (tid < 64) ? expf(asum_s - w[tid]) * sdt[tid] : 0.f;
    __syncthreads();
    if (tid < 64) w[tid] = wv;
    __syncthreads();

    for (int i = tid; i < 64 * 16; i += 256) {
        int l = i >> 4, q = i & 15;
        float4 v = *(const float4*)(g_x + (size_t)(row0 + l) * NI + h * HD + q * 4);
        float wl = w[l];
        *(float4*)(xs + l * 68 + q * 4) = make_float4(v.x * wl, v.y * wl, v.z * wl, v.w * wl);
    }
    for (int i = tid; i < 64 * 32; i += 256) {
        int l = i >> 5, q = i & 31;
        *(float4*)(sB + l * 132 + q * 4) =
            *(const float4*)(g_Bm + (size_t)(row0 + l) * NS + q * 4);
    }
    __syncthreads();

    const int pg = tid >> 5;   // 8 p-groups of 8
    const int ng = tid & 31;   // 32 n-pairs (x2 halves)
    uint64_t acc2[4][4];       // [p-pair][n: bA.x,bA.y,bB.x,bB.y]
    const uint64_t z2 = pack2(0.f, 0.f);
#pragma unroll
    for (int i = 0; i < 4; i++)
#pragma unroll
        for (int j = 0; j < 4; j++) acc2[i][j] = z2;

    for (int l = 0; l < 64; l++) {
        const ulonglong2* xr = (const ulonglong2*)(xs + l * 68 + pg * 8);
        ulonglong2 xa = xr[0], xb = xr[1];
        float2 bA = *(const float2*)(sB + l * 132 + 2 * ng);
        float2 bB = *(const float2*)(sB + l * 132 + 64 + 2 * ng);
        uint64_t bb0 = pack2(bA.x, bA.x), bb1 = pack2(bA.y, bA.y);
        uint64_t bb2 = pack2(bB.x, bB.x), bb3 = pack2(bB.y, bB.y);
        uint64_t xv[4] = {xa.x, xa.y, xb.x, xb.y};
#pragma unroll
        for (int i = 0; i < 4; i++) {
            ffma2(acc2[i][0], xv[i], bb0);
            ffma2(acc2[i][1], xv[i], bb1);
            ffma2(acc2[i][2], xv[i], bb2);
            ffma2(acc2[i][3], xv[i], bb3);
        }
    }
    float* outp = g_st + (size_t)((b * NC + c) * NH + h) * HD * NS;
#pragma unroll
    for (int i = 0; i < 4; i++) {
        float a0e, a0o, a1e, a1o, a2e, a2o, a3e, a3o;
        unpack2(acc2[i][0], a0e, a0o);
        unpack2(acc2[i][1], a1e, a1o);
        unpack2(acc2[i][2], a2e, a2o);
        unpack2(acc2[i][3], a3e, a3o);
        int pe = pg * 8 + i * 2, po = pe + 1;
        *(float2*)(outp + (size_t)pe * NS + 2 * ng)      = make_float2(a0e, a1e);
        *(float2*)(outp + (size_t)pe * NS + 64 + 2 * ng) = make_float2(a2e, a3e);
        *(float2*)(outp + (size_t)po * NS + 2 * ng)      = make_float2(a0o, a1o);
        *(float2*)(outp + (size_t)po * NS + 64 + 2 * ng) = make_float2(a2o, a3o);
    }
}

// ---------------- cross-chunk state scan ----------------
__global__ void __launch_bounds__(256) scan_kernel(const float* __restrict__ init_ssm,
                                                   float* __restrict__ final_out)
{
    const int seg = blockIdx.x;
    const int h = blockIdx.y, b = blockIdx.z;
    const int tid = threadIdx.x;
    const int e = seg * 1024 + tid * 4;
    const size_t base_bh = (size_t)(b * NH + h) * HD * NS;
    float4 S = *reinterpret_cast<const float4*>(init_ssm + base_bh + e);
    for (int c = 0; c < NC; c++) {
        float dec = expf(g_asum[(b * NC + c) * NH + h]);
        float* ptr = g_st + (size_t)((b * NC + c) * NH + h) * HD * NS + e;
        float4 cs = *reinterpret_cast<float4*>(ptr);
        *reinterpret_cast<float4*>(ptr) = S;
        S.x = dec * S.x + cs.x;
        S.y = dec * S.y + cs.y;
        S.z = dec * S.z + cs.z;
        S.w = dec * S.w + cs.w;
    }
    *reinterpret_cast<float4*>(final_out + base_bh + e) = S;
}

// ---------------- Y = (G∘L)@xdt + exp(Acs)*(C @ Sprev^T) + x*D ------------
#define Y_SMEM ((128*68 + 64*132) * 4)
__global__ void __launch_bounds__(256) y_kernel(const float* __restrict__ A_log,
                                                const float* __restrict__ Dp)
{
    extern __shared__ float sm[];
    float* shA = sm;             // [128][68]
    float* sC  = sm + 128 * 68;  // [64][132]
    __shared__ float acs[64], sdt[64];
    const int h = blockIdx.x, c = blockIdx.y, b = blockIdx.z;
    const int tid = threadIdx.x;
    const int row0 = b * L_ + c * CH;
    if (tid < 64) sdt[tid] = g_dt[(size_t)(row0 + tid) * NH + h];
    __syncthreads();
    if (tid == 0) {
        float A = -expf(A_log[h]);
        float s = 0.f;
        for (int l = 0; l < 64; l++) { s += A * sdt[l]; acs[l] = s; }
    }
    __syncthreads();

    const float* Sp = g_st + (size_t)((b * NC + c) * NH + h) * HD * NS;
    for (int i = tid; i < 64 * 32; i += 256) {
        int l = i >> 5, q = i & 31;
        *(float4*)(sC + l * 132 + q * 4) =
            *(const float4*)(g_Cm + (size_t)(row0 + l) * NS + q * 4);
    }
    for (int i = tid; i < 64 * 32; i += 256) {
        int p = i >> 5, q = i & 31;
        float4 v = *(const float4*)(Sp + (size_t)p * NS + q * 4);
        shA[(q * 4 + 0) * 68 + p] = v.x;
        shA[(q * 4 + 1) * 68 + p] = v.y;
        shA[(q * 4 + 2) * 68 + p] = v.z;
        shA[(q * 4 + 3) * 68 + p] = v.w;
    }
    __syncthreads();

    const int l = tid >> 2;
    const int p0 = (tid & 3) * 16;
    uint64_t acc2[8];
    const uint64_t z2 = pack2(0.f, 0.f);
#pragma unroll
    for (int j = 0; j < 8; j++) acc2[j] = z2;

    // phase 1: Y_off[l][p] = sum_n C[l][n] * S^T[n][p]
    for (int nn = 0; nn < 128; nn++) {
        float cv = sC[l * 132 + nn];
        uint64_t cc = pack2(cv, cv);
        const ulonglong2* sr = (const ulonglong2*)(shA + nn * 68 + p0);
        ulonglong2 q0 = sr[0], q1 = sr[1], q2 = sr[2], q3 = sr[3];
        ffma2(acc2[0], cc, q0.x); ffma2(acc2[1], cc, q0.y);
        ffma2(acc2[2], cc, q1.x); ffma2(acc2[3], cc, q1.y);
        ffma2(acc2[4], cc, q2.x); ffma2(acc2[5], cc, q2.y);
        ffma2(acc2[6], cc, q3.x); ffma2(acc2[7], cc, q3.y);
    }
    {
        float eAl = expf(acs[l]);
        uint64_t ee = pack2(eAl, eAl);
#pragma unroll
        for (int j = 0; j < 8; j++) fmul2(acc2[j], ee);
    }
    __syncthreads();   // done reading shA as S^T

    // phase 2: build sM = G*exp(acs[r]-acs[s]) masked, sxdt = x*dt [s][p]
    const float* Gp = g_G + (size_t)(b * NC + c) * (CH * CH);
    for (int i = tid; i < 64 * 64; i += 256) {
        int r = i >> 6, s = i & 63;
        shA[r * 68 + s] = (s <= r) ? Gp[r * 64 + s] * expf(acs[r] - acs[s]) : 0.f;
    }
    float* sxdt = shA + 64 * 68;
    for (int i = tid; i < 64 * 16; i += 256) {
        int s = i >> 4, q = i & 15;
        float4 v = *(const float4*)(g_x + (size_t)(row0 + s) * NI + h * HD + q * 4);
        float d = sdt[s];
        *(float4*)(sxdt + s * 68 + q * 4) = make_float4(v.x * d, v.y * d, v.z * d, v.w * d);
    }
    __syncthreads();

    for (int s = 0; s < 64; s++) {
        float gv = shA[l * 68 + s];
        uint64_t gg = pack2(gv, gv);
        const ulonglong2* xr = (const ulonglong2*)(sxdt + s * 68 + p0);
        ulonglong2 q0 = xr[0], q1 = xr[1], q2 = xr[2], q3 = xr[3];
        ffma2(acc2[0], gg, q0.x); ffma2(acc2[1], gg, q0.y);
        ffma2(acc2[2], gg, q1.x); ffma2(acc2[3], gg, q1.y);
        ffma2(acc2[4], gg, q2.x); ffma2(acc2[5], gg, q2.y);
        ffma2(acc2[6], gg, q3.x); ffma2(acc2[7], gg, q3.y);
    }

    float acc[16];
#pragma unroll
    for (int j = 0; j < 8; j++) unpack2(acc2[j], acc[2 * j], acc[2 * j + 1]);

    float Dv = Dp[h];
    float* yrow = g_yin + (size_t)(row0 + l) * NI + h * HD + p0;
    const float* xrow = g_x + (size_t)(row0 + l) * NI + h * HD + p0;
#pragma unroll
    for (int j4 = 0; j4 < 4; j4++) {
        float4 xv = *(const float4*)(xrow + j4 * 4);
        float4 o = make_float4(acc[j4*4+0] + xv.x * Dv, acc[j4*4+1] + xv.y * Dv,
                               acc[j4*4+2] + xv.z * Dv, acc[j4*4+3] + xv.w * Dv);
        *(float4*)(yrow + j4 * 4) = o;
    }
}

// ------ gate with silu(z), RMSNorm, * norm_w; emit bf16 hi/lo directly ------
__global__ void __launch_bounds__(256) gate_rms_kernel(const float* __restrict__ norm_w) {
    const int row = blockIdx.x;
    const int tid = threadIdx.x;
    const float* zrow = g_zx + (size_t)row * DIN;
    const float* yrow = g_yin + (size_t)row * NI;
    float v[8];
    float ss = 0.f;
#pragma unroll
    for (int i = 0; i < 8; i++) {
        int idx = tid + i * 256;
        float z = zrow[idx];
        float val = yrow[idx] * siluf(z);
        v[i] = val;
        ss += val * val;
    }
    __shared__ float red[256];
    red[tid] = ss;
    __syncthreads();
    for (int s = 128; s > 0; s >>= 1) {
        if (tid < s) red[tid] += red[tid + s];
        __syncthreads();
    }
    float scale = rsqrtf(red[0] / (float)NI + 1e-5f);
#pragma unroll
    for (int i = 0; i < 8; i++) {
        int idx = tid + i * 256;
        float o = v[i] * scale * norm_w[idx];
        __nv_bfloat16 h = __float2bfloat16_rn(o);
        __nv_bfloat16 lo = __float2bfloat16_rn(o - __bfloat162float(h));
        g_ynb_hi[(size_t)row * NI + idx] = h;
        g_ynb_lo[(size_t)row * NI + idx] = lo;
    }
}

// ---------------- launch ----------------
template <typename T>
static T* symaddr(const void* sym) {
    void* p = nullptr;
    cudaGetSymbolAddress(&p, sym);
    return (T*)p;
}

extern "C" void kernel_launch(void* const* d_in, const int* in_sizes, int n_in,
                              void* d_out, int out_size)
{
    const float* u         = (const float*)d_in[0];
    const float* init_conv = (const float*)d_in[1];
    const float* init_ssm  = (const float*)d_in[2];
    const float* w_in      = (const float*)d_in[3];
    const float* conv_w    = (const float*)d_in[4];
    const float* conv_b    = (const float*)d_in[5];
    const float* dt_bias   = (const float*)d_in[6];
    const float* A_log     = (const float*)d_in[7];
    const float* Dp        = (const float*)d_in[8];
    const float* norm_w    = (const float*)d_in[9];
    const float* w_out     = (const float*)d_in[10];

    float* out       = (float*)d_out;
    float* out_y     = out;
    float* out_conv  = out + (size_t)ROWS * E_;
    float* out_final = out_conv + (size_t)B_ * CD * NCONV;

    float* pzx = symaddr<float>(g_zx);
    __nv_bfloat16* p_u_hi  = symaddr<__nv_bfloat16>(g_u_hi);
    __nv_bfloat16* p_u_lo  = symaddr<__nv_bfloat16>(g_u_lo);
    __nv_bfloat16* p_win_hi  = symaddr<__nv_bfloat16>(g_win_hi);
    __nv_bfloat16* p_win_lo  = symaddr<__nv_bfloat16>(g_win_lo);
    __nv_bfloat16* p_wout_hi = symaddr<__nv_bfloat16>(g_wout_hi);
    __nv_bfloat16* p_wout_lo = symaddr<__nv_bfloat16>(g_wout_lo);
    __nv_bfloat16* p_yn_hi = symaddr<__nv_bfloat16>(g_ynb_hi);
    __nv_bfloat16* p_yn_lo = symaddr<__nv_bfloat16>(g_ynb_lo);

    cudaFuncSetAttribute(gemm_bf16, cudaFuncAttributeMaxDynamicSharedMemorySize, GM_SMEM);
    cudaFuncSetAttribute(states_kernel, cudaFuncAttributeMaxDynamicSharedMemorySize, STATES_SMEM);
    cudaFuncSetAttribute(y_kernel, cudaFuncAttributeMaxDynamicSharedMemorySize, Y_SMEM);

    // 0) operand conversions to bf16 hi/lo
    cvt_hilo_kernel<<<(ROWS * E_ / 4 + 511) / 512, 512>>>(u, p_u_hi, p_u_lo, ROWS * E_);
    cvt_win_kernel<<<(E_ * NPAD / 4 + 511) / 512, 512>>>(w_in);
    cvt_hilo_kernel<<<(NI * E_ / 4 + 511) / 512, 512>>>(w_out, p_wout_hi, p_wout_lo, NI * E_);

    // 1) in-projection
    gemm_bf16<<<dim3(NPAD / 128, ROWS / 256), 512, GM_SMEM>>>(
        p_u_hi, p_u_lo, p_win_hi, p_win_lo, pzx, ROWS, DIN, E_, NPAD);
    // 2) dt
    dt_kernel<<<(ROWS * NH + 255) / 256, 256>>>(dt_bias);
    // 3) conv + silu + split (4 channels x 8 timesteps per thread)
    conv_kernel<<<dim3((CD / 4 + 255) / 256, L_ / 8, B_), 256>>>(init_conv, conv_w, conv_b);
    // 4) new_conv_state output
    convstate_kernel<<<(B_ * CD * NCONV + 255) / 256, 256>>>(out_conv);
    // 5) per-chunk Gram matrix
    gmat_kernel<<<B_ * NC, 256>>>();
    // 6) per-chunk states
    states_kernel<<<dim3(NH, NC, B_), 256, STATES_SMEM>>>(A_log);
    // 7) cross-chunk scan
    scan_kernel<<<dim3(8, NH, B_), 256>>>(init_ssm, out_final);
    // 8) Y
    y_kernel<<<dim3(NH, NC, B_), 256, Y_SMEM>>>(A_log, Dp);
    // 9) gate + rmsnorm
    gate_rms_kernel<<<ROWS, 256>>>(norm_w);
    // 10) out-projection
    gemm_bf16<<<dim3(E_ / 128, ROWS / 256), 512, GM_SMEM>>>(
        p_yn_hi, p_yn_lo, p_wout_hi, p_wout_lo, out_y, ROWS, E_, NI, E_);
}

// round 10
// speedup vs baseline: 1.0256x; 1.0256x over previous
#include <cuda_runtime.h>
#include <cuda_bf16.h>
#include <math.h>
#include <stdint.h>

// Problem constants
#define B_    2
#define L_    4096
#define E_    1024
#define NI    2048      // N_INNER
#define NS    128       // N_STATE
#define NH    32        // N_HEAD
#define HD    64        // HEADDIM
#define NCONV 4
#define CH    64        // CHUNK
#define NC    64        // chunks per sequence (L/CHUNK)
#define CD    2304      // CONV_DIM = NI + 2*NS
#define DIN   4384      // 2*NI + 2*NS + NH
#define NPAD  4480      // DIN padded to multiple of 128
#define ROWS  (B_*L_)   // 8192

// ---------------- scratch (device globals; no allocation allowed) ----------
__device__ float g_zx[(size_t)ROWS * DIN];
__device__ float g_x [(size_t)ROWS * NI];
__device__ float g_Bm[(size_t)ROWS * NS];
__device__ float g_Cm[(size_t)ROWS * NS];
__device__ float g_dt[(size_t)ROWS * NH];
__device__ float g_G [(size_t)B_ * NC * CH * CH];
__device__ float g_st[(size_t)B_ * NC * NH * HD * NS];
__device__ float g_asum[B_ * NC * NH];
__device__ float g_yin[(size_t)ROWS * NI];

// bf16 hi/lo operand copies for tensor-core GEMMs
__device__ __nv_bfloat16 g_u_hi[(size_t)ROWS * E_];
__device__ __nv_bfloat16 g_u_lo[(size_t)ROWS * E_];
__device__ __nv_bfloat16 g_win_hi[(size_t)E_ * NPAD];
__device__ __nv_bfloat16 g_win_lo[(size_t)E_ * NPAD];
__device__ __nv_bfloat16 g_wout_hi[(size_t)NI * E_];
__device__ __nv_bfloat16 g_wout_lo[(size_t)NI * E_];
__device__ __nv_bfloat16 g_ynb_hi[(size_t)ROWS * NI];
__device__ __nv_bfloat16 g_ynb_lo[(size_t)ROWS * NI];

// ---------------- small helpers ----------------
__device__ __forceinline__ float siluf(float x) { return x / (1.f + expf(-x)); }
__device__ __forceinline__ float softplusf(float x) {
    return (x > 20.f) ? x : log1pf(expf(x));
}
__device__ __forceinline__ uint32_t smem_u32(const void* p) {
    uint32_t a;
    asm("{ .reg .u64 t; cvta.to.shared.u64 t, %1; cvt.u32.u64 %0, t; }" : "=r"(a) : "l"(p));
    return a;
}

// ---------------- packed f32x2 (Blackwell, base sm_100) ----------------
__device__ __forceinline__ uint64_t pack2(float x, float y) {
    uint64_t r;
    asm("mov.b64 %0, {%1, %2};" : "=l"(r) : "f"(x), "f"(y));
    return r;
}
__device__ __forceinline__ void unpack2(uint64_t v, float& x, float& y) {
    asm("mov.b64 {%0, %1}, %2;" : "=f"(x), "=f"(y) : "l"(v));
}
__device__ __forceinline__ void ffma2(uint64_t& d, uint64_t a, uint64_t b) {
    asm("fma.rn.f32x2 %0, %1, %2, %0;" : "+l"(d) : "l"(a), "l"(b));
}
__device__ __forceinline__ void fmul2(uint64_t& d, uint64_t a) {
    asm("mul.rn.f32x2 %0, %0, %1;" : "+l"(d) : "l"(a));
}

// ---------------- warp-MMA primitives (sm_80+, valid on base sm_100) -------
__device__ __forceinline__ void ldm_x4(uint32_t* r, uint32_t addr) {
    asm volatile("ldmatrix.sync.aligned.m8n8.x4.shared.b16 {%0,%1,%2,%3}, [%4];"
        : "=r"(r[0]), "=r"(r[1]), "=r"(r[2]), "=r"(r[3]) : "r"(addr));
}
__device__ __forceinline__ void ldm_x2t(uint32_t* r, uint32_t addr) {
    asm volatile("ldmatrix.sync.aligned.m8n8.x2.trans.shared.b16 {%0,%1}, [%2];"
        : "=r"(r[0]), "=r"(r[1]) : "r"(addr));
}
__device__ __forceinline__ void mma_bf16(float* c, const uint32_t* a, const uint32_t* b) {
    asm volatile(
        "mma.sync.aligned.m16n8k16.row.col.f32.bf16.bf16.f32 "
        "{%0,%1,%2,%3}, {%4,%5,%6,%7}, {%8,%9}, {%0,%1,%2,%3};"
        : "+f"(c[0]), "+f"(c[1]), "+f"(c[2]), "+f"(c[3])
        : "r"(a[0]), "r"(a[1]), "r"(a[2]), "r"(a[3]), "r"(b[0]), "r"(b[1]));
}
__device__ __forceinline__ void cp16(uint32_t dst, const void* src) {
    asm volatile("cp.async.cg.shared.global [%0], [%1], 16;" :: "r"(dst), "l"(src));
}
#define CP_COMMIT() asm volatile("cp.async.commit_group;" ::: "memory")
#define CP_WAIT(n)  asm volatile("cp.async.wait_group %0;" :: "n"(n) : "memory")

// ---------------- fp32 -> bf16 hi/lo conversion kernels ----------------
__global__ void cvt_hilo_kernel(const float* __restrict__ s,
                                __nv_bfloat16* __restrict__ hi,
                                __nv_bfloat16* __restrict__ lo, int n)
{
    int i = (blockIdx.x * blockDim.x + threadIdx.x) * 4;
    if (i >= n) return;
    float4 v = *(const float4*)(s + i);
    float f[4] = {v.x, v.y, v.z, v.w};
    ushort hh[4], ll[4];
#pragma unroll
    for (int j = 0; j < 4; j++) {
        __nv_bfloat16 h = __float2bfloat16_rn(f[j]);
        __nv_bfloat16 l = __float2bfloat16_rn(f[j] - __bfloat162float(h));
        hh[j] = __bfloat16_as_ushort(h);
        ll[j] = __bfloat16_as_ushort(l);
    }
    *(ushort4*)((ushort*)hi + i) = make_ushort4(hh[0], hh[1], hh[2], hh[3]);
    *(ushort4*)((ushort*)lo + i) = make_ushort4(ll[0], ll[1], ll[2], ll[3]);
}

// w_in [E_][DIN] -> padded [E_][NPAD] hi/lo (zero-fill cols >= DIN)
__global__ void cvt_win_kernel(const float* __restrict__ w) {
    int i4 = (blockIdx.x * blockDim.x + threadIdx.x) * 4;
    if (i4 >= E_ * NPAD) return;
    int row = i4 / NPAD, col = i4 % NPAD;
    float f[4];
    if (col + 3 < DIN) {
        float4 v = *(const float4*)(w + (size_t)row * DIN + col);
        f[0] = v.x; f[1] = v.y; f[2] = v.z; f[3] = v.w;
    } else {
#pragma unroll
        for (int j = 0; j < 4; j++) {
            int cc = col + j;
            f[j] = (cc < DIN) ? w[(size_t)row * DIN + cc] : 0.f;
        }
    }
    ushort hh[4], ll[4];
#pragma unroll
    for (int j = 0; j < 4; j++) {
        __nv_bfloat16 h = __float2bfloat16_rn(f[j]);
        __nv_bfloat16 l = __float2bfloat16_rn(f[j] - __bfloat162float(h));
        hh[j] = __bfloat16_as_ushort(h);
        ll[j] = __bfloat16_as_ushort(l);
    }
    *(ushort4*)((ushort*)g_win_hi + i4) = make_ushort4(hh[0], hh[1], hh[2], hh[3]);
    *(ushort4*)((ushort*)g_win_lo + i4) = make_ushort4(ll[0], ll[1], ll[2], ll[3]);
}

// ================= tensor-core GEMM: C[M,N] = A[M,K] @ B[K,N] ==============
// bf16x3 split (hi*hi + hi*lo + lo*hi), fp32 accumulate.
// Block tile 256x128, 512 threads (16 warps: 4m x 4n, 64x32 per warp).
// K-tile 32, cp.async 3-stage pipeline (loads issued AFTER MMAs — R8 order).
#define ST_A_LO 20480
#define ST_B_HI 40960
#define ST_B_LO 49664
#define ST_BYTES 58368
#define STG 3
#define GM_SMEM (STG * ST_BYTES)

__global__ void __launch_bounds__(512, 1) gemm_bf16(
    const __nv_bfloat16* __restrict__ Ah, const __nv_bfloat16* __restrict__ Al,
    const __nv_bfloat16* __restrict__ Bh, const __nv_bfloat16* __restrict__ Bl,
    float* __restrict__ C, int M, int N, int K, int ldB)
{
    extern __shared__ char smem[];
    const uint32_t sb = smem_u32(smem);
    const int tid = threadIdx.x;
    const int wid = tid >> 5, lane = tid & 31;
    const int m0 = blockIdx.y * 256;
    const int n0 = blockIdx.x * 128;
    const int warp_m = wid >> 2;
    const int warp_n = wid & 3;

    float acc[4][4][4];
#pragma unroll
    for (int i = 0; i < 4; i++)
#pragma unroll
        for (int j = 0; j < 4; j++)
#pragma unroll
            for (int k = 0; k < 4; k++) acc[i][j][k] = 0.f;

    const int KTn = K >> 5;

    const int arow0 = tid >> 2, ach0 = tid & 3;
    const int arow1 = (tid + 512) >> 2, ach1 = tid & 3;
    const int bkr = tid >> 4, bch = tid & 15;

#define LOAD_STAGE(KT_) do { \
    const int k0_ = (KT_) << 5; \
    const uint32_t st_ = sb + ((KT_) % STG) * ST_BYTES; \
    { size_t go = (size_t)(m0 + arow0) * K + k0_ + ach0 * 8; \
      uint32_t so = st_ + arow0 * 80 + ach0 * 16; \
      cp16(so, Ah + go); cp16(so + ST_A_LO, Al + go); } \
    { size_t go = (size_t)(m0 + arow1) * K + k0_ + ach1 * 8; \
      uint32_t so = st_ + arow1 * 80 + ach1 * 16; \
      cp16(so, Ah + go); cp16(so + ST_A_LO, Al + go); } \
    { size_t go = (size_t)(k0_ + bkr) * ldB + n0 + bch * 8; \
      uint32_t so = st_ + ST_B_HI + bkr * 272 + bch * 16; \
      cp16(so, Bh + go); cp16(so + 8704, Bl + go); } \
} while (0)

#pragma unroll
    for (int s = 0; s < STG - 1; s++) {
        if (s < KTn) LOAD_STAGE(s);
        CP_COMMIT();
    }

    for (int kt = 0; kt < KTn; kt++) {
        CP_WAIT(STG - 2);
        __syncthreads();
        const uint32_t sAhi = sb + (kt % STG) * ST_BYTES;
        const uint32_t sAlo = sAhi + ST_A_LO;
        const uint32_t sBhi = sAhi + ST_B_HI;
        const uint32_t sBlo = sAhi + ST_B_LO;
#pragma unroll
        for (int ks = 0; ks < 2; ks++) {
            uint32_t a_hi[4][4], a_lo[4][4], b_hi[4][2], b_lo[4][2];
#pragma unroll
            for (int mi = 0; mi < 4; mi++) {
                int row = warp_m * 64 + mi * 16 + (lane & 15);
                uint32_t addr = row * 80 + ks * 32 + (lane >> 4) * 16;
                ldm_x4(a_hi[mi], sAhi + addr);
                ldm_x4(a_lo[mi], sAlo + addr);
            }
#pragma unroll
            for (int ni = 0; ni < 4; ni++) {
                int krow = ks * 16 + (lane & 15);
                int ncol = warp_n * 32 + ni * 8;
                uint32_t addr = krow * 272 + ncol * 2;
                ldm_x2t(b_hi[ni], sBhi + addr);
                ldm_x2t(b_lo[ni], sBlo + addr);
            }
#pragma unroll
            for (int mi = 0; mi < 4; mi++)
#pragma unroll
                for (int ni = 0; ni < 4; ni++) {
                    mma_bf16(acc[mi][ni], a_hi[mi], b_hi[ni]);
                    mma_bf16(acc[mi][ni], a_hi[mi], b_lo[ni]);
                    mma_bf16(acc[mi][ni], a_lo[mi], b_hi[ni]);
                }
        }
        if (kt + STG - 1 < KTn) LOAD_STAGE(kt + STG - 1);
        CP_COMMIT();
    }
#undef LOAD_STAGE

#pragma unroll
    for (int mi = 0; mi < 4; mi++) {
        int row = m0 + warp_m * 64 + mi * 16 + (lane >> 2);
#pragma unroll
        for (int ni = 0; ni < 4; ni++) {
            int col = n0 + warp_n * 32 + ni * 8 + (lane & 3) * 2;
            if (col < N) {
                *(float2*)(C + (size_t)row * N + col) =
                    make_float2(acc[mi][ni][0], acc[mi][ni][1]);
                *(float2*)(C + (size_t)(row + 8) * N + col) =
                    make_float2(acc[mi][ni][2], acc[mi][ni][3]);
            }
        }
    }
}

// ---------------- dt = softplus(raw + bias) ----------------
__global__ void dt_kernel(const float* __restrict__ dt_bias) {
    int i = blockIdx.x * blockDim.x + threadIdx.x;
    if (i >= ROWS * NH) return;
    int row = i / NH, h = i % NH;
    float x = g_zx[(size_t)row * DIN + (DIN - NH) + h] + dt_bias[h];
    g_dt[i] = softplusf(x);
}

// --- depthwise causal conv w4 + silu + split; 4 channels x 8 timesteps ----
__global__ void conv_kernel(const float* __restrict__ init_conv,
                            const float* __restrict__ conv_w,
                            const float* __restrict__ conv_b)
{
    int d4 = blockIdx.x * blockDim.x + threadIdx.x;
    if (d4 >= CD / 4) return;
    const int d = d4 * 4;
    const int t0 = blockIdx.y * 8;
    const int b = blockIdx.z;
    float4 cw[4];
#pragma unroll
    for (int j = 0; j < 4; j++) cw[j] = *(const float4*)(conv_w + (d + j) * 4);
    float4 bias = *(const float4*)(conv_b + d);
    float4 win[11];
#pragma unroll
    for (int i = 0; i < 11; i++) {
        int ti = t0 - 3 + i;
        if (ti >= 0) {
            win[i] = *(const float4*)(g_zx + (size_t)(b * L_ + ti) * DIN + NI + d);
        } else {
            win[i].x = init_conv[((size_t)b * CD + d + 0) * NCONV + (4 + ti)];
            win[i].y = init_conv[((size_t)b * CD + d + 1) * NCONV + (4 + ti)];
            win[i].z = init_conv[((size_t)b * CD + d + 2) * NCONV + (4 + ti)];
            win[i].w = init_conv[((size_t)b * CD + d + 3) * NCONV + (4 + ti)];
        }
    }
#pragma unroll
    for (int jt = 0; jt < 8; jt++) {
        float4 o;
        o.x = siluf(bias.x + cw[0].x*win[jt].x + cw[0].y*win[jt+1].x + cw[0].z*win[jt+2].x + cw[0].w*win[jt+3].x);
        o.y = siluf(bias.y + cw[1].x*win[jt].y + cw[1].y*win[jt+1].y + cw[1].z*win[jt+2].y + cw[1].w*win[jt+3].y);
        o.z = siluf(bias.z + cw[2].x*win[jt].z + cw[2].y*win[jt+1].z + cw[2].z*win[jt+2].z + cw[2].w*win[jt+3].z);
        o.w = siluf(bias.w + cw[3].x*win[jt].w + cw[3].y*win[jt+1].w + cw[3].z*win[jt+2].w + cw[3].w*win[jt+3].w);
        int row = b * L_ + t0 + jt;
        if (d < NI)           *(float4*)(g_x  + (size_t)row * NI + d) = o;
        else if (d < NI + NS) *(float4*)(g_Bm + (size_t)row * NS + (d - NI)) = o;
        else                  *(float4*)(g_Cm + (size_t)row * NS + (d - NI - NS)) = o;
    }
}

// ---------------- new_conv_state output ----------------
__global__ void convstate_kernel(float* __restrict__ out) {
    int i = blockIdx.x * blockDim.x + threadIdx.x;
    if (i >= B_ * CD * NCONV) return;
    int k = i % NCONV;
    int d = (i / NCONV) % CD;
    int b = i / (NCONV * CD);
    out[i] = g_zx[(size_t)(b * L_ + (L_ - 4 + k)) * DIN + NI + d];
}

// ---------------- per-chunk Gram matrix G[l][s] = sum_n C[l,n]B[s,n] -------
__global__ void __launch_bounds__(256) gmat_kernel() {
    const int bc = blockIdx.x;
    const int b = bc / NC, c = bc % NC;
    const int row0 = b * L_ + c * CH;
    const int tid = threadIdx.x;
    __shared__ float sC[64 * 33];
    __shared__ float sB[64 * 33];
    const int l = tid >> 2;
    const int s0 = (tid & 3) * 16;
    float acc[16];
#pragma unroll
    for (int j = 0; j < 16; j++) acc[j] = 0.f;
    for (int n0 = 0; n0 < NS; n0 += 32) {
        for (int i = tid; i < 64 * 32; i += 256) {
            int r = i >> 5, nn = i & 31;
            sC[r * 33 + nn] = g_Cm[(size_t)(row0 + r) * NS + n0 + nn];
            sB[r * 33 + nn] = g_Bm[(size_t)(row0 + r) * NS + n0 + nn];
        }
        __syncthreads();
        for (int nn = 0; nn < 32; nn++) {
            float cv = sC[l * 33 + nn];
#pragma unroll
            for (int j = 0; j < 16; j++) acc[j] += cv * sB[(s0 + j) * 33 + nn];
        }
        __syncthreads();
    }
    float* Gp = g_G + (size_t)bc * (CH * CH);
#pragma unroll
    for (int j = 0; j < 16; j++) Gp[l * 64 + s0 + j] = acc[j];
}

// ------- per-chunk states[p][n] = sum_l B[l,n]*decay[l]*dt[l]*x[l,p] -------
#define STATES_SMEM ((64*68 + 64*132) * 4)
__global__ void __launch_bounds__(256) states_kernel(const float* __restrict__ A_log) {
    extern __shared__ float sm[];
    float* xs = sm;             // [64][68]
    float* sB = sm + 64 * 68;   // [64][132]
    __shared__ float sdt[64], w[64];
    __shared__ float asum_s;
    const int h = blockIdx.x, c = blockIdx.y, b = blockIdx.z;
    const int tid = threadIdx.x;
    const int row0 = b * L_ + c * CH;
    if (tid < 64) sdt[tid] = g_dt[(size_t)(row0 + tid) * NH + h];
    __syncthreads();
    if (tid == 0) {
        float A = -expf(A_log[h]);
        float s = 0.f;
        for (int l = 0; l < 64; l++) { s += A * sdt[l]; w[l] = s; }  // w = acs (temp)
        asum_s = s;
        g_asum[(b * NC + c) * NH + h] = s;
    }
    __syncthreads();
    float wv = (tid < 64) ? expf(asum_s - w[tid]) * sdt[tid] : 0.f;
    __syncthreads();
    if (tid < 64) w[tid] = wv;
    __syncthreads();

    for (int i = tid; i < 64 * 16; i += 256) {
        int l = i >> 4, q = i & 15;
        float4 v = *(const float4*)(g_x + (size_t)(row0 + l) * NI + h * HD + q * 4);
        float wl = w[l];
        *(float4*)(xs + l * 68 + q * 4) = make_float4(v.x * wl, v.y * wl, v.z * wl, v.w * wl);
    }
    for (int i = tid; i < 64 * 32; i += 256) {
        int l = i >> 5, q = i & 31;
        *(float4*)(sB + l * 132 + q * 4) =
            *(const float4*)(g_Bm + (size_t)(row0 + l) * NS + q * 4);
    }
    __syncthreads();

    const int pg = tid >> 5;   // 8 p-groups of 8
    const int ng = tid & 31;   // 32 n-pairs (x2 halves)
    uint64_t acc2[4][4];
    const uint64_t z2 = pack2(0.f, 0.f);
#pragma unroll
    for (int i = 0; i < 4; i++)
#pragma unroll
        for (int j = 0; j < 4; j++) acc2[i][j] = z2;

    for (int l = 0; l < 64; l++) {
        const ulonglong2* xr = (const ulonglong2*)(xs + l * 68 + pg * 8);
        ulonglong2 xa = xr[0], xb = xr[1];
        float2 bA = *(const float2*)(sB + l * 132 + 2 * ng);
        float2 bB = *(const float2*)(sB + l * 132 + 64 + 2 * ng);
        uint64_t bb0 = pack2(bA.x, bA.x), bb1 = pack2(bA.y, bA.y);
        uint64_t bb2 = pack2(bB.x, bB.x), bb3 = pack2(bB.y, bB.y);
        uint64_t xv[4] = {xa.x, xa.y, xb.x, xb.y};
#pragma unroll
        for (int i = 0; i < 4; i++) {
            ffma2(acc2[i][0], xv[i], bb0);
            ffma2(acc2[i][1], xv[i], bb1);
            ffma2(acc2[i][2], xv[i], bb2);
            ffma2(acc2[i][3], xv[i], bb3);
        }
    }
    float* outp = g_st + (size_t)((b * NC + c) * NH + h) * HD * NS;
#pragma unroll
    for (int i = 0; i < 4; i++) {
        float a0e, a0o, a1e, a1o, a2e, a2o, a3e, a3o;
        unpack2(acc2[i][0], a0e, a0o);
        unpack2(acc2[i][1], a1e, a1o);
        unpack2(acc2[i][2], a2e, a2o);
        unpack2(acc2[i][3], a3e, a3o);
        int pe = pg * 8 + i * 2, po = pe + 1;
        *(float2*)(outp + (size_t)pe * NS + 2 * ng)      = make_float2(a0e, a1e);
        *(float2*)(outp + (size_t)pe * NS + 64 + 2 * ng) = make_float2(a2e, a3e);
        *(float2*)(outp + (size_t)po * NS + 2 * ng)      = make_float2(a0o, a1o);
        *(float2*)(outp + (size_t)po * NS + 64 + 2 * ng) = make_float2(a2o, a3o);
    }
}

// ---------------- cross-chunk state scan ----------------
__global__ void __launch_bounds__(256) scan_kernel(const float* __restrict__ init_ssm,
                                                   float* __restrict__ final_out)
{
    const int seg = blockIdx.x;
    const int h = blockIdx.y, b = blockIdx.z;
    const int tid = threadIdx.x;
    const int e = seg * 1024 + tid * 4;
    const size_t base_bh = (size_t)(b * NH + h) * HD * NS;
    float4 S = *reinterpret_cast<const float4*>(init_ssm + base_bh + e);
    for (int c = 0; c < NC; c++) {
        float dec = expf(g_asum[(b * NC + c) * NH + h]);
        float* ptr = g_st + (size_t)((b * NC + c) * NH + h) * HD * NS + e;
        float4 cs = *reinterpret_cast<float4*>(ptr);
        *reinterpret_cast<float4*>(ptr) = S;
        S.x = dec * S.x + cs.x;
        S.y = dec * S.y + cs.y;
        S.z = dec * S.z + cs.z;
        S.w = dec * S.w + cs.w;
    }
    *reinterpret_cast<float4*>(final_out + base_bh + e) = S;
}

// ---------------- Y = (G∘L)@xdt + exp(Acs)*(C @ Sprev^T) + x*D ------------
#define Y_SMEM ((128*68 + 64*132) * 4)
__global__ void __launch_bounds__(256) y_kernel(const float* __restrict__ A_log,
                                                const float* __restrict__ Dp)
{
    extern __shared__ float sm[];
    float* shA = sm;             // [128][68]
    float* sC  = sm + 128 * 68;  // [64][132]
    __shared__ float acs[64], sdt[64];
    const int h = blockIdx.x, c = blockIdx.y, b = blockIdx.z;
    const int tid = threadIdx.x;
    const int row0 = b * L_ + c * CH;
    if (tid < 64) sdt[tid] = g_dt[(size_t)(row0 + tid) * NH + h];
    __syncthreads();
    if (tid == 0) {
        float A = -expf(A_log[h]);
        float s = 0.f;
        for (int l = 0; l < 64; l++) { s += A * sdt[l]; acs[l] = s; }
    }
    __syncthreads();

    const float* Sp = g_st + (size_t)((b * NC + c) * NH + h) * HD * NS;
    for (int i = tid; i < 64 * 32; i += 256) {
        int l = i >> 5, q = i & 31;
        *(float4*)(sC + l * 132 + q * 4) =
            *(const float4*)(g_Cm + (size_t)(row0 + l) * NS + q * 4);
    }
    for (int i = tid; i < 64 * 32; i += 256) {
        int p = i >> 5, q = i & 31;
        float4 v = *(const float4*)(Sp + (size_t)p * NS + q * 4);
        shA[(q * 4 + 0) * 68 + p] = v.x;
        shA[(q * 4 + 1) * 68 + p] = v.y;
        shA[(q * 4 + 2) * 68 + p] = v.z;
        shA[(q * 4 + 3) * 68 + p] = v.w;
    }
    __syncthreads();

    const int l = tid >> 2;
    const int p0 = (tid & 3) * 16;
    uint64_t acc2[8];
    const uint64_t z2 = pack2(0.f, 0.f);
#pragma unroll
    for (int j = 0; j < 8; j++) acc2[j] = z2;

    // phase 1: Y_off[l][p] = sum_n C[l][n] * S^T[n][p]
    for (int nn = 0; nn < 128; nn++) {
        float cv = sC[l * 132 + nn];
        uint64_t cc = pack2(cv, cv);
        const ulonglong2* sr = (const ulonglong2*)(shA + nn * 68 + p0);
        ulonglong2 q0 = sr[0], q1 = sr[1], q2 = sr[2], q3 = sr[3];
        ffma2(acc2[0], cc, q0.x); ffma2(acc2[1], cc, q0.y);
        ffma2(acc2[2], cc, q1.x); ffma2(acc2[3], cc, q1.y);
        ffma2(acc2[4], cc, q2.x); ffma2(acc2[5], cc, q2.y);
        ffma2(acc2[6], cc, q3.x); ffma2(acc2[7], cc, q3.y);
    }
    {
        float eAl = expf(acs[l]);
        uint64_t ee = pack2(eAl, eAl);
#pragma unroll
        for (int j = 0; j < 8; j++) fmul2(acc2[j], ee);
    }
    __syncthreads();   // done reading shA as S^T

    // phase 2: build sM = G*exp(acs[r]-acs[s]) masked, sxdt = x*dt [s][p]
    const float* Gp = g_G + (size_t)(b * NC + c) * (CH * CH);
    for (int i = tid; i < 64 * 64; i += 256) {
        int r = i >> 6, s = i & 63;
        shA[r * 68 + s] = (s <= r) ? Gp[r * 64 + s] * expf(acs[r] - acs[s]) : 0.f;
    }
    float* sxdt = shA + 64 * 68;
    for (int i = tid; i < 64 * 16; i += 256) {
        int s = i >> 4, q = i & 15;
        float4 v = *(const float4*)(g_x + (size_t)(row0 + s) * NI + h * HD + q * 4);
        float d = sdt[s];
        *(float4*)(sxdt + s * 68 + q * 4) = make_float4(v.x * d, v.y * d, v.z * d, v.w * d);
    }
    __syncthreads();

    for (int s = 0; s < 64; s++) {
        float gv = shA[l * 68 + s];
        uint64_t gg = pack2(gv, gv);
        const ulonglong2* xr = (const ulonglong2*)(sxdt + s * 68 + p0);
        ulonglong2 q0 = xr[0], q1 = xr[1], q2 = xr[2], q3 = xr[3];
        ffma2(acc2[0], gg, q0.x); ffma2(acc2[1], gg, q0.y);
        ffma2(acc2[2], gg, q1.x); ffma2(acc2[3], gg, q1.y);
        ffma2(acc2[4], gg, q2.x); ffma2(acc2[5], gg, q2.y);
        ffma2(acc2[6], gg, q3.x); ffma2(acc2[7], gg, q3.y);
    }

    float acc[16];
#pragma unroll
    for (int j = 0; j < 8; j++) unpack2(acc2[j], acc[2 * j], acc[2 * j + 1]);

    float Dv = Dp[h];
    float* yrow = g_yin + (size_t)(row0 + l) * NI + h * HD + p0;
    const float* xrow = g_x + (size_t)(row0 + l) * NI + h * HD + p0;
#pragma unroll
    for (int j4 = 0; j4 < 4; j4++) {
        float4 xv = *(const float4*)(xrow + j4 * 4);
        float4 o = make_float4(acc[j4*4+0] + xv.x * Dv, acc[j4*4+1] + xv.y * Dv,
                               acc[j4*4+2] + xv.z * Dv, acc[j4*4+3] + xv.w * Dv);
        *(float4*)(yrow + j4 * 4) = o;
    }
}

// ------ gate with silu(z), RMSNorm, * norm_w; emit bf16 hi/lo directly ------
__global__ void __launch_bounds__(256) gate_rms_kernel(const float* __restrict__ norm_w) {
    const int row = blockIdx.x;
    const int tid = threadIdx.x;
    const float* zrow = g_zx + (size_t)row * DIN;
    const float* yrow = g_yin + (size_t)row * NI;
    float v[8];
    float ss = 0.f;
#pragma unroll
    for (int i = 0; i < 8; i++) {
        int idx = tid + i * 256;
        float z = zrow[idx];
        float val = yrow[idx] * siluf(z);
        v[i] = val;
        ss += val * val;
    }
    __shared__ float red[256];
    red[tid] = ss;
    __syncthreads();
    for (int s = 128; s > 0; s >>= 1) {
        if (tid < s) red[tid] += red[tid + s];
        __syncthreads();
    }
    float scale = rsqrtf(red[0] / (float)NI + 1e-5f);
#pragma unroll
    for (int i = 0; i < 8; i++) {
        int idx = tid + i * 256;
        float o = v[i] * scale * norm_w[idx];
        __nv_bfloat16 h = __float2bfloat16_rn(o);
        __nv_bfloat16 lo = __float2bfloat16_rn(o - __bfloat162float(h));
        g_ynb_hi[(size_t)row * NI + idx] = h;
        g_ynb_lo[(size_t)row * NI + idx] = lo;
    }
}

// ---------------- launch ----------------
template <typename T>
static T* symaddr(const void* sym) {
    void* p = nullptr;
    cudaGetSymbolAddress(&p, sym);
    return (T*)p;
}

extern "C" void kernel_launch(void* const* d_in, const int* in_sizes, int n_in,
                              void* d_out, int out_size)
{
    const float* u         = (const float*)d_in[0];
    const float* init_conv = (const float*)d_in[1];
    const float* init_ssm  = (const float*)d_in[2];
    const float* w_in      = (const float*)d_in[3];
    const float* conv_w    = (const float*)d_in[4];
    const float* conv_b    = (const float*)d_in[5];
    const float* dt_bias   = (const float*)d_in[6];
    const float* A_log     = (const float*)d_in[7];
    const float* Dp        = (const float*)d_in[8];
    const float* norm_w    = (const float*)d_in[9];
    const float* w_out     = (const float*)d_in[10];

    float* out       = (float*)d_out;
    float* out_y     = out;
    float* out_conv  = out + (size_t)ROWS * E_;
    float* out_final = out_conv + (size_t)B_ * CD * NCONV;

    float* pzx = symaddr<float>(g_zx);
    __nv_bfloat16* p_u_hi  = symaddr<__nv_bfloat16>(g_u_hi);
    __nv_bfloat16* p_u_lo  = symaddr<__nv_bfloat16>(g_u_lo);
    __nv_bfloat16* p_win_hi  = symaddr<__nv_bfloat16>(g_win_hi);
    __nv_bfloat16* p_win_lo  = symaddr<__nv_bfloat16>(g_win_lo);
    __nv_bfloat16* p_wout_hi = symaddr<__nv_bfloat16>(g_wout_hi);
    __nv_bfloat16* p_wout_lo = symaddr<__nv_bfloat16>(g_wout_lo);
    __nv_bfloat16* p_yn_hi = symaddr<__nv_bfloat16>(g_ynb_hi);
    __nv_bfloat16* p_yn_lo = symaddr<__nv_bfloat16>(g_ynb_lo);

    cudaFuncSetAttribute(gemm_bf16, cudaFuncAttributeMaxDynamicSharedMemorySize, GM_SMEM);
    cudaFuncSetAttribute(states_kernel, cudaFuncAttributeMaxDynamicSharedMemorySize, STATES_SMEM);
    cudaFuncSetAttribute(y_kernel, cudaFuncAttributeMaxDynamicSharedMemorySize, Y_SMEM);

    // 0) operand conversions to bf16 hi/lo
    cvt_hilo_kernel<<<(ROWS * E_ / 4 + 511) / 512, 512>>>(u, p_u_hi, p_u_lo, ROWS * E_);
    cvt_win_kernel<<<(E_ * NPAD / 4 + 511) / 512, 512>>>(w_in);
    cvt_hilo_kernel<<<(NI * E_ / 4 + 511) / 512, 512>>>(w_out, p_wout_hi, p_wout_lo, NI * E_);

    // 1) in-projection
    gemm_bf16<<<dim3(NPAD / 128, ROWS / 256), 512, GM_SMEM>>>(
        p_u_hi, p_u_lo, p_win_hi, p_win_lo, pzx, ROWS, DIN, E_, NPAD);
    // 2) dt
    dt_kernel<<<(ROWS * NH + 255) / 256, 256>>>(dt_bias);
    // 3) conv + silu + split (4 channels x 8 timesteps per thread)
    conv_kernel<<<dim3((CD / 4 + 255) / 256, L_ / 8, B_), 256>>>(init_conv, conv_w, conv_b);
    // 4) new_conv_state output
    convstate_kernel<<<(B_ * CD * NCONV + 255) / 256, 256>>>(out_conv);
    // 5) per-chunk Gram matrix
    gmat_kernel<<<B_ * NC, 256>>>();
    // 6) per-chunk states
    states_kernel<<<dim3(NH, NC, B_), 256, STATES_SMEM>>>(A_log);
    // 7) cross-chunk scan
    scan_kernel<<<dim3(8, NH, B_), 256>>>(init_ssm, out_final);
    // 8) Y
    y_kernel<<<dim3(NH, NC, B_), 256, Y_SMEM>>>(A_log, Dp);
    // 9) gate + rmsnorm
    gate_rms_kernel<<<ROWS, 256>>>(norm_w);
    // 10) out-projection
    gemm_bf16<<<dim3(E_ / 128, ROWS / 256), 512, GM_SMEM>>>(
        p_yn_hi, p_yn_lo, p_wout_hi, p_wout_lo, out_y, ROWS, E_, NI, E_);
}

// round 12
// speedup vs baseline: 1.0915x; 1.0643x over previous
#include <cuda_runtime.h>
#include <cuda_bf16.h>
#include <cuda_fp16.h>
#include <math.h>
#include <stdint.h>

// Problem constants
#define B_    2
#define L_    4096
#define E_    1024
#define NI    2048      // N_INNER
#define NS    128       // N_STATE
#define NH    32        // N_HEAD
#define HD    64        // HEADDIM
#define NCONV 4
#define CH    64        // CHUNK
#define NC    64        // chunks per sequence (L/CHUNK)
#define CD    2304      // CONV_DIM = NI + 2*NS
#define DIN   4384      // 2*NI + 2*NS + NH
#define NPAD  4480      // DIN padded to multiple of 128
#define ROWS  (B_*L_)   // 8192

// ---------------- scratch (device globals; no allocation allowed) ----------
__device__ float g_zx[(size_t)ROWS * DIN];
__device__ float g_x [(size_t)ROWS * NI];
__device__ float g_Bm[(size_t)ROWS * NS];
__device__ float g_Cm[(size_t)ROWS * NS];
__device__ float g_dt[(size_t)ROWS * NH];
__device__ float g_G [(size_t)B_ * NC * CH * CH];
__device__ __half g_st[(size_t)B_ * NC * NH * HD * NS];   // fp16 chunk/prev states
__device__ float g_asum[B_ * NC * NH];
__device__ float g_yin[(size_t)ROWS * NI];

// bf16 hi/lo operand copies for tensor-core GEMMs
__device__ __nv_bfloat16 g_u_hi[(size_t)ROWS * E_];
__device__ __nv_bfloat16 g_u_lo[(size_t)ROWS * E_];
__device__ __nv_bfloat16 g_win_hi[(size_t)E_ * NPAD];
__device__ __nv_bfloat16 g_win_lo[(size_t)E_ * NPAD];
__device__ __nv_bfloat16 g_wout_hi[(size_t)NI * E_];
__device__ __nv_bfloat16 g_wout_lo[(size_t)NI * E_];
__device__ __nv_bfloat16 g_ynb_hi[(size_t)ROWS * NI];
__device__ __nv_bfloat16 g_ynb_lo[(size_t)ROWS * NI];

// ---------------- small helpers ----------------
__device__ __forceinline__ float siluf(float x) { return x / (1.f + expf(-x)); }
__device__ __forceinline__ float softplusf(float x) {
    return (x > 20.f) ? x : log1pf(expf(x));
}
__device__ __forceinline__ uint32_t smem_u32(const void* p) {
    uint32_t a;
    asm("{ .reg .u64 t; cvta.to.shared.u64 t, %1; cvt.u32.u64 %0, t; }" : "=r"(a) : "l"(p));
    return a;
}

// ---------------- packed f32x2 (Blackwell, base sm_100) ----------------
__device__ __forceinline__ uint64_t pack2(float x, float y) {
    uint64_t r;
    asm("mov.b64 %0, {%1, %2};" : "=l"(r) : "f"(x), "f"(y));
    return r;
}
__device__ __forceinline__ void unpack2(uint64_t v, float& x, float& y) {
    asm("mov.b64 {%0, %1}, %2;" : "=f"(x), "=f"(y) : "l"(v));
}
__device__ __forceinline__ void ffma2(uint64_t& d, uint64_t a, uint64_t b) {
    asm("fma.rn.f32x2 %0, %1, %2, %0;" : "+l"(d) : "l"(a), "l"(b));
}
__device__ __forceinline__ void fmul2(uint64_t& d, uint64_t a) {
    asm("mul.rn.f32x2 %0, %0, %1;" : "+l"(d) : "l"(a));
}

// ---------------- warp-MMA primitives (sm_80+, valid on base sm_100) -------
__device__ __forceinline__ void ldm_x4(uint32_t* r, uint32_t addr) {
    asm volatile("ldmatrix.sync.aligned.m8n8.x4.shared.b16 {%0,%1,%2,%3}, [%4];"
        : "=r"(r[0]), "=r"(r[1]), "=r"(r[2]), "=r"(r[3]) : "r"(addr));
}
__device__ __forceinline__ void ldm_x2t(uint32_t* r, uint32_t addr) {
    asm volatile("ldmatrix.sync.aligned.m8n8.x2.trans.shared.b16 {%0,%1}, [%2];"
        : "=r"(r[0]), "=r"(r[1]) : "r"(addr));
}
__device__ __forceinline__ void mma_bf16(float* c, const uint32_t* a, const uint32_t* b) {
    asm volatile(
        "mma.sync.aligned.m16n8k16.row.col.f32.bf16.bf16.f32 "
        "{%0,%1,%2,%3}, {%4,%5,%6,%7}, {%8,%9}, {%0,%1,%2,%3};"
        : "+f"(c[0]), "+f"(c[1]), "+f"(c[2]), "+f"(c[3])
        : "r"(a[0]), "r"(a[1]), "r"(a[2]), "r"(a[3]), "r"(b[0]), "r"(b[1]));
}
__device__ __forceinline__ void cp16(uint32_t dst, const void* src) {
    asm volatile("cp.async.cg.shared.global [%0], [%1], 16;" :: "r"(dst), "l"(src));
}
#define CP_COMMIT() asm volatile("cp.async.commit_group;" ::: "memory")
#define CP_WAIT(n)  asm volatile("cp.async.wait_group %0;" :: "n"(n) : "memory")

// ---------------- fp32 -> bf16 hi/lo conversion kernels ----------------
__global__ void cvt_hilo_kernel(const float* __restrict__ s,
                                __nv_bfloat16* __restrict__ hi,
                                __nv_bfloat16* __restrict__ lo, int n)
{
    int i = (blockIdx.x * blockDim.x + threadIdx.x) * 4;
    if (i >= n) return;
    float4 v = *(const float4*)(s + i);
    float f[4] = {v.x, v.y, v.z, v.w};
    ushort hh[4], ll[4];
#pragma unroll
    for (int j = 0; j < 4; j++) {
        __nv_bfloat16 h = __float2bfloat16_rn(f[j]);
        __nv_bfloat16 l = __float2bfloat16_rn(f[j] - __bfloat162float(h));
        hh[j] = __bfloat16_as_ushort(h);
        ll[j] = __bfloat16_as_ushort(l);
    }
    *(ushort4*)((ushort*)hi + i) = make_ushort4(hh[0], hh[1], hh[2], hh[3]);
    *(ushort4*)((ushort*)lo + i) = make_ushort4(ll[0], ll[1], ll[2], ll[3]);
}

// w_in [E_][DIN] -> padded [E_][NPAD] hi/lo (zero-fill cols >= DIN)
__global__ void cvt_win_kernel(const float* __restrict__ w) {
    int i4 = (blockIdx.x * blockDim.x + threadIdx.x) * 4;
    if (i4 >= E_ * NPAD) return;
    int row = i4 / NPAD, col = i4 % NPAD;
    float f[4];
    if (col + 3 < DIN) {
        float4 v = *(const float4*)(w + (size_t)row * DIN + col);
        f[0] = v.x; f[1] = v.y; f[2] = v.z; f[3] = v.w;
    } else {
#pragma unroll
        for (int j = 0; j < 4; j++) {
            int cc = col + j;
            f[j] = (cc < DIN) ? w[(size_t)row * DIN + cc] : 0.f;
        }
    }
    ushort hh[4], ll[4];
#pragma unroll
    for (int j = 0; j < 4; j++) {
        __nv_bfloat16 h = __float2bfloat16_rn(f[j]);
        __nv_bfloat16 l = __float2bfloat16_rn(f[j] - __bfloat162float(h));
        hh[j] = __bfloat16_as_ushort(h);
        ll[j] = __bfloat16_as_ushort(l);
    }
    *(ushort4*)((ushort*)g_win_hi + i4) = make_ushort4(hh[0], hh[1], hh[2], hh[3]);
    *(ushort4*)((ushort*)g_win_lo + i4) = make_ushort4(ll[0], ll[1], ll[2], ll[3]);
}

// ================= tensor-core GEMM: C[M,N] = A[M,K] @ B[K,N] ==============
// bf16x3 split (hi*hi + hi*lo + lo*hi), fp32 accumulate.
// Block tile 256x128, 512 threads (16 warps: 4m x 4n, 64x32 per warp).
// K-tile 32, cp.async 3-stage pipeline (loads issued AFTER MMAs — R8 order).
#define ST_A_LO 20480
#define ST_B_HI 40960
#define ST_B_LO 49664
#define ST_BYTES 58368
#define STG 3
#define GM_SMEM (STG * ST_BYTES)

__global__ void __launch_bounds__(512, 1) gemm_bf16(
    const __nv_bfloat16* __restrict__ Ah, const __nv_bfloat16* __restrict__ Al,
    const __nv_bfloat16* __restrict__ Bh, const __nv_bfloat16* __restrict__ Bl,
    float* __restrict__ C, int M, int N, int K, int ldB)
{
    extern __shared__ char smem[];
    const uint32_t sb = smem_u32(smem);
    const int tid = threadIdx.x;
    const int wid = tid >> 5, lane = tid & 31;
    const int m0 = blockIdx.y * 256;
    const int n0 = blockIdx.x * 128;
    const int warp_m = wid >> 2;
    const int warp_n = wid & 3;

    float acc[4][4][4];
#pragma unroll
    for (int i = 0; i < 4; i++)
#pragma unroll
        for (int j = 0; j < 4; j++)
#pragma unroll
            for (int k = 0; k < 4; k++) acc[i][j][k] = 0.f;

    const int KTn = K >> 5;

    const int arow0 = tid >> 2, ach0 = tid & 3;
    const int arow1 = (tid + 512) >> 2, ach1 = tid & 3;
    const int bkr = tid >> 4, bch = tid & 15;

#define LOAD_STAGE(KT_) do { \
    const int k0_ = (KT_) << 5; \
    const uint32_t st_ = sb + ((KT_) % STG) * ST_BYTES; \
    { size_t go = (size_t)(m0 + arow0) * K + k0_ + ach0 * 8; \
      uint32_t so = st_ + arow0 * 80 + ach0 * 16; \
      cp16(so, Ah + go); cp16(so + ST_A_LO, Al + go); } \
    { size_t go = (size_t)(m0 + arow1) * K + k0_ + ach1 * 8; \
      uint32_t so = st_ + arow1 * 80 + ach1 * 16; \
      cp16(so, Ah + go); cp16(so + ST_A_LO, Al + go); } \
    { size_t go = (size_t)(k0_ + bkr) * ldB + n0 + bch * 8; \
      uint32_t so = st_ + ST_B_HI + bkr * 272 + bch * 16; \
      cp16(so, Bh + go); cp16(so + 8704, Bl + go); } \
} while (0)

#pragma unroll
    for (int s = 0; s < STG - 1; s++) {
        if (s < KTn) LOAD_STAGE(s);
        CP_COMMIT();
    }

    for (int kt = 0; kt < KTn; kt++) {
        CP_WAIT(STG - 2);
        __syncthreads();
        const uint32_t sAhi = sb + (kt % STG) * ST_BYTES;
        const uint32_t sAlo = sAhi + ST_A_LO;
        const uint32_t sBhi = sAhi + ST_B_HI;
        const uint32_t sBlo = sAhi + ST_B_LO;
#pragma unroll
        for (int ks = 0; ks < 2; ks++) {
            uint32_t a_hi[4][4], a_lo[4][4], b_hi[4][2], b_lo[4][2];
#pragma unroll
            for (int mi = 0; mi < 4; mi++) {
                int row = warp_m * 64 + mi * 16 + (lane & 15);
                uint32_t addr = row * 80 + ks * 32 + (lane >> 4) * 16;
                ldm_x4(a_hi[mi], sAhi + addr);
                ldm_x4(a_lo[mi], sAlo + addr);
            }
#pragma unroll
            for (int ni = 0; ni < 4; ni++) {
                int krow = ks * 16 + (lane & 15);
                int ncol = warp_n * 32 + ni * 8;
                uint32_t addr = krow * 272 + ncol * 2;
                ldm_x2t(b_hi[ni], sBhi + addr);
                ldm_x2t(b_lo[ni], sBlo + addr);
            }
#pragma unroll
            for (int mi = 0; mi < 4; mi++)
#pragma unroll
                for (int ni = 0; ni < 4; ni++) {
                    mma_bf16(acc[mi][ni], a_hi[mi], b_hi[ni]);
                    mma_bf16(acc[mi][ni], a_hi[mi], b_lo[ni]);
                    mma_bf16(acc[mi][ni], a_lo[mi], b_hi[ni]);
                }
        }
        if (kt + STG - 1 < KTn) LOAD_STAGE(kt + STG - 1);
        CP_COMMIT();
    }
#undef LOAD_STAGE

#pragma unroll
    for (int mi = 0; mi < 4; mi++) {
        int row = m0 + warp_m * 64 + mi * 16 + (lane >> 2);
#pragma unroll
        for (int ni = 0; ni < 4; ni++) {
            int col = n0 + warp_n * 32 + ni * 8 + (lane & 3) * 2;
            if (col < N) {
                *(float2*)(C + (size_t)row * N + col) =
                    make_float2(acc[mi][ni][0], acc[mi][ni][1]);
                *(float2*)(C + (size_t)(row + 8) * N + col) =
                    make_float2(acc[mi][ni][2], acc[mi][ni][3]);
            }
        }
    }
}

// ---------------- dt = softplus(raw + bias) ----------------
__global__ void dt_kernel(const float* __restrict__ dt_bias) {
    int i = blockIdx.x * blockDim.x + threadIdx.x;
    if (i >= ROWS * NH) return;
    int row = i / NH, h = i % NH;
    float x = g_zx[(size_t)row * DIN + (DIN - NH) + h] + dt_bias[h];
    g_dt[i] = softplusf(x);
}

// --- depthwise causal conv w4 + silu + split; 4 channels x 8 timesteps ----
__global__ void conv_kernel(const float* __restrict__ init_conv,
                            const float* __restrict__ conv_w,
                            const float* __restrict__ conv_b)
{
    int d4 = blockIdx.x * blockDim.x + threadIdx.x;
    if (d4 >= CD / 4) return;
    const int d = d4 * 4;
    const int t0 = blockIdx.y * 8;
    const int b = blockIdx.z;
    float4 cw[4];
#pragma unroll
    for (int j = 0; j < 4; j++) cw[j] = *(const float4*)(conv_w + (d + j) * 4);
    float4 bias = *(const float4*)(conv_b + d);
    float4 win[11];
#pragma unroll
    for (int i = 0; i < 11; i++) {
        int ti = t0 - 3 + i;
        if (ti >= 0) {
            win[i] = *(const float4*)(g_zx + (size_t)(b * L_ + ti) * DIN + NI + d);
        } else {
            win[i].x = init_conv[((size_t)b * CD + d + 0) * NCONV + (4 + ti)];
            win[i].y = init_conv[((size_t)b * CD + d + 1) * NCONV + (4 + ti)];
            win[i].z = init_conv[((size_t)b * CD + d + 2) * NCONV + (4 + ti)];
            win[i].w = init_conv[((size_t)b * CD + d + 3) * NCONV + (4 + ti)];
        }
    }
#pragma unroll
    for (int jt = 0; jt < 8; jt++) {
        float4 o;
        o.x = siluf(bias.x + cw[0].x*win[jt].x + cw[0].y*win[jt+1].x + cw[0].z*win[jt+2].x + cw[0].w*win[jt+3].x);
        o.y = siluf(bias.y + cw[1].x*win[jt].y + cw[1].y*win[jt+1].y + cw[1].z*win[jt+2].y + cw[1].w*win[jt+3].y);
        o.z = siluf(bias.z + cw[2].x*win[jt].z + cw[2].y*win[jt+1].z + cw[2].z*win[jt+2].z + cw[2].w*win[jt+3].z);
        o.w = siluf(bias.w + cw[3].x*win[jt].w + cw[3].y*win[jt+1].w + cw[3].z*win[jt+2].w + cw[3].w*win[jt+3].w);
        int row = b * L_ + t0 + jt;
        if (d < NI)           *(float4*)(g_x  + (size_t)row * NI + d) = o;
        else if (d < NI + NS) *(float4*)(g_Bm + (size_t)row * NS + (d - NI)) = o;
        else                  *(float4*)(g_Cm + (size_t)row * NS + (d - NI - NS)) = o;
    }
}

// ---------------- new_conv_state output ----------------
__global__ void convstate_kernel(float* __restrict__ out) {
    int i = blockIdx.x * blockDim.x + threadIdx.x;
    if (i >= B_ * CD * NCONV) return;
    int k = i % NCONV;
    int d = (i / NCONV) % CD;
    int b = i / (NCONV * CD);
    out[i] = g_zx[(size_t)(b * L_ + (L_ - 4 + k)) * DIN + NI + d];
}

// ---------------- per-chunk Gram matrix G[l][s] = sum_n C[l,n]B[s,n] -------
__global__ void __launch_bounds__(256) gmat_kernel() {
    const int bc = blockIdx.x;
    const int b = bc / NC, c = bc % NC;
    const int row0 = b * L_ + c * CH;
    const int tid = threadIdx.x;
    __shared__ float sC[64 * 33];
    __shared__ float sB[64 * 33];
    const int l = tid >> 2;
    const int s0 = (tid & 3) * 16;
    float acc[16];
#pragma unroll
    for (int j = 0; j < 16; j++) acc[j] = 0.f;
    for (int n0 = 0; n0 < NS; n0 += 32) {
        for (int i = tid; i < 64 * 32; i += 256) {
            int r = i >> 5, nn = i & 31;
            sC[r * 33 + nn] = g_Cm[(size_t)(row0 + r) * NS + n0 + nn];
            sB[r * 33 + nn] = g_Bm[(size_t)(row0 + r) * NS + n0 + nn];
        }
        __syncthreads();
        for (int nn = 0; nn < 32; nn++) {
            float cv = sC[l * 33 + nn];
#pragma unroll
            for (int j = 0; j < 16; j++) acc[j] += cv * sB[(s0 + j) * 33 + nn];
        }
        __syncthreads();
    }
    float* Gp = g_G + (size_t)bc * (CH * CH);
#pragma unroll
    for (int j = 0; j < 16; j++) Gp[l * 64 + s0 + j] = acc[j];
}

// ------- per-chunk states[p][n] = sum_l B[l,n]*decay[l]*dt[l]*x[l,p] -------
#define STATES_SMEM ((64*68 + 64*132) * 4)
__global__ void __launch_bounds__(256) states_kernel(const float* __restrict__ A_log) {
    extern __shared__ float sm[];
    float* xs = sm;             // [64][68]
    float* sB = sm + 64 * 68;   // [64][132]
    __shared__ float sdt[64], w[64];
    __shared__ float asum_s;
    const int h = blockIdx.x, c = blockIdx.y, b = blockIdx.z;
    const int tid = threadIdx.x;
    const int row0 = b * L_ + c * CH;
    if (tid < 64) sdt[tid] = g_dt[(size_t)(row0 + tid) * NH + h];
    __syncthreads();
    if (tid == 0) {
        float A = -expf(A_log[h]);
        float s = 0.f;
        for (int l = 0; l < 64; l++) { s += A * sdt[l]; w[l] = s; }  // w = acs (temp)
        asum_s = s;
        g_asum[(b * NC + c) * NH + h] = s;
    }
    __syncthreads();
    float wv = (tid < 64) ? expf(asum_s - w[tid]) * sdt[tid] : 0.f;
    __syncthreads();
    if (tid < 64) w[tid] = wv;
    __syncthreads();

    for (int i = tid; i < 64 * 16; i += 256) {
        int l = i >> 4, q = i & 15;
        float4 v = *(const float4*)(g_x + (size_t)(row0 + l) * NI + h * HD + q * 4);
        float wl = w[l];
        *(float4*)(xs + l * 68 + q * 4) = make_float4(v.x * wl, v.y * wl, v.z * wl, v.w * wl);
    }
    for (int i = tid; i < 64 * 32; i += 256) {
        int l = i >> 5, q = i & 31;
        *(float4*)(sB + l * 132 + q * 4) =
            *(const float4*)(g_Bm + (size_t)(row0 + l) * NS + q * 4);
    }
    __syncthreads();

    const int pg = tid >> 5;   // 8 p-groups of 8
    const int ng = tid & 31;   // 32 n-pairs (x2 halves)
    uint64_t acc2[4][4];
    const uint64_t z2 = pack2(0.f, 0.f);
#pragma unroll
    for (int i = 0; i < 4; i++)
#pragma unroll
        for (int j = 0; j < 4; j++) acc2[i][j] = z2;

    for (int l = 0; l < 64; l++) {
        const ulonglong2* xr = (const ulonglong2*)(xs + l * 68 + pg * 8);
        ulonglong2 xa = xr[0], xb = xr[1];
        float2 bA = *(const float2*)(sB + l * 132 + 2 * ng);
        float2 bB = *(const float2*)(sB + l * 132 + 64 + 2 * ng);
        uint64_t bb0 = pack2(bA.x, bA.x), bb1 = pack2(bA.y, bA.y);
        uint64_t bb2 = pack2(bB.x, bB.x), bb3 = pack2(bB.y, bB.y);
        uint64_t xv[4] = {xa.x, xa.y, xb.x, xb.y};
#pragma unroll
        for (int i = 0; i < 4; i++) {
            ffma2(acc2[i][0], xv[i], bb0);
            ffma2(acc2[i][1], xv[i], bb1);
            ffma2(acc2[i][2], xv[i], bb2);
            ffma2(acc2[i][3], xv[i], bb3);
        }
    }
    __half* outp = g_st + (size_t)((b * NC + c) * NH + h) * HD * NS;
#pragma unroll
    for (int i = 0; i < 4; i++) {
        float a0e, a0o, a1e, a1o, a2e, a2o, a3e, a3o;
        unpack2(acc2[i][0], a0e, a0o);
        unpack2(acc2[i][1], a1e, a1o);
        unpack2(acc2[i][2], a2e, a2o);
        unpack2(acc2[i][3], a3e, a3o);
        int pe = pg * 8 + i * 2, po = pe + 1;
        *(__half2*)(outp + (size_t)pe * NS + 2 * ng)      = __floats2half2_rn(a0e, a1e);
        *(__half2*)(outp + (size_t)pe * NS + 64 + 2 * ng) = __floats2half2_rn(a2e, a3e);
        *(__half2*)(outp + (size_t)po * NS + 2 * ng)      = __floats2half2_rn(a0o, a1o);
        *(__half2*)(outp + (size_t)po * NS + 64 + 2 * ng) = __floats2half2_rn(a2o, a3o);
    }
}

// ---------------- cross-chunk state scan (fp16 storage, fp32 accumulate) ---
__global__ void __launch_bounds__(256) scan_kernel(const float* __restrict__ init_ssm,
                                                   float* __restrict__ final_out)
{
    const int seg = blockIdx.x;
    const int h = blockIdx.y, b = blockIdx.z;
    const int tid = threadIdx.x;
    const int e = seg * 1024 + tid * 4;
    const size_t base_bh = (size_t)(b * NH + h) * HD * NS;
    float4 S = *reinterpret_cast<const float4*>(init_ssm + base_bh + e);
    for (int c = 0; c < NC; c++) {
        float dec = expf(g_asum[(b * NC + c) * NH + h]);
        __half* ptr = g_st + (size_t)((b * NC + c) * NH + h) * HD * NS + e;
        uint2 raw = *reinterpret_cast<uint2*>(ptr);
        __half2 h0 = *reinterpret_cast<__half2*>(&raw.x);
        __half2 h1 = *reinterpret_cast<__half2*>(&raw.y);
        float2 f0 = __half22float2(h0);
        float2 f1 = __half22float2(h1);
        __half2 s0 = __floats2half2_rn(S.x, S.y);
        __half2 s1 = __floats2half2_rn(S.z, S.w);
        uint2 sr;
        sr.x = *reinterpret_cast<uint32_t*>(&s0);
        sr.y = *reinterpret_cast<uint32_t*>(&s1);
        *reinterpret_cast<uint2*>(ptr) = sr;   // prev-state for chunk c (fp16)
        S.x = dec * S.x + f0.x;
        S.y = dec * S.y + f0.y;
        S.z = dec * S.z + f1.x;
        S.w = dec * S.w + f1.y;
    }
    *reinterpret_cast<float4*>(final_out + base_bh + e) = S;
}

// ---------------- Y = (G∘L)@xdt + exp(Acs)*(C @ Sprev^T) + x*D ------------
#define Y_SMEM ((128*68 + 64*132) * 4)
__global__ void __launch_bounds__(256) y_kernel(const float* __restrict__ A_log,
                                                const float* __restrict__ Dp)
{
    extern __shared__ float sm[];
    float* shA = sm;             // [128][68]
    float* sC  = sm + 128 * 68;  // [64][132]
    __shared__ float acs[64], sdt[64];
    const int h = blockIdx.x, c = blockIdx.y, b = blockIdx.z;
    const int tid = threadIdx.x;
    const int row0 = b * L_ + c * CH;
    if (tid < 64) sdt[tid] = g_dt[(size_t)(row0 + tid) * NH + h];
    __syncthreads();
    if (tid == 0) {
        float A = -expf(A_log[h]);
        float s = 0.f;
        for (int l = 0; l < 64; l++) { s += A * sdt[l]; acs[l] = s; }
    }
    __syncthreads();

    const __half* Sp = g_st + (size_t)((b * NC + c) * NH + h) * HD * NS;
    for (int i = tid; i < 64 * 32; i += 256) {
        int l = i >> 5, q = i & 31;
        *(float4*)(sC + l * 132 + q * 4) =
            *(const float4*)(g_Cm + (size_t)(row0 + l) * NS + q * 4);
    }
    for (int i = tid; i < 64 * 32; i += 256) {
        int p = i >> 5, q = i & 31;
        uint2 raw = *reinterpret_cast<const uint2*>(Sp + (size_t)p * NS + q * 4);
        __half2 h0 = *reinterpret_cast<__half2*>(&raw.x);
        __half2 h1 = *reinterpret_cast<__half2*>(&raw.y);
        float2 f0 = __half22float2(h0);
        float2 f1 = __half22float2(h1);
        shA[(q * 4 + 0) * 68 + p] = f0.x;
        shA[(q * 4 + 1) * 68 + p] = f0.y;
        shA[(q * 4 + 2) * 68 + p] = f1.x;
        shA[(q * 4 + 3) * 68 + p] = f1.y;
    }
    __syncthreads();

    const int l = tid >> 2;
    const int p0 = (tid & 3) * 16;
    uint64_t acc2[8];
    const uint64_t z2 = pack2(0.f, 0.f);
#pragma unroll
    for (int j = 0; j < 8; j++) acc2[j] = z2;

    // phase 1: Y_off[l][p] = sum_n C[l][n] * S^T[n][p]
    for (int nn = 0; nn < 128; nn++) {
        float cv = sC[l * 132 + nn];
        uint64_t cc = pack2(cv, cv);
        const ulonglong2* sr = (const ulonglong2*)(shA + nn * 68 + p0);
        ulonglong2 q0 = sr[0], q1 = sr[1], q2 = sr[2], q3 = sr[3];
        ffma2(acc2[0], cc, q0.x); ffma2(acc2[1], cc, q0.y);
        ffma2(acc2[2], cc, q1.x); ffma2(acc2[3], cc, q1.y);
        ffma2(acc2[4], cc, q2.x); ffma2(acc2[5], cc, q2.y);
        ffma2(acc2[6], cc, q3.x); ffma2(acc2[7], cc, q3.y);
    }
    {
        float eAl = expf(acs[l]);
        uint64_t ee = pack2(eAl, eAl);
#pragma unroll
        for (int j = 0; j < 8; j++) fmul2(acc2[j], ee);
    }
    __syncthreads();   // done reading shA as S^T

    // phase 2: build sM = G*exp(acs[r]-acs[s]) masked, sxdt = x*dt [s][p]
    const float* Gp = g_G + (size_t)(b * NC + c) * (CH * CH);
    for (int i = tid; i < 64 * 64; i += 256) {
        int r = i >> 6, s = i & 63;
        shA[r * 68 + s] = (s <= r) ? Gp[r * 64 + s] * expf(acs[r] - acs[s]) : 0.f;
    }
    float* sxdt = shA + 64 * 68;
    for (int i = tid; i < 64 * 16; i += 256) {
        int s = i >> 4, q = i & 15;
        float4 v = *(const float4*)(g_x + (size_t)(row0 + s) * NI + h * HD + q * 4);
        float d = sdt[s];
        *(float4*)(sxdt + s * 68 + q * 4) = make_float4(v.x * d, v.y * d, v.z * d, v.w * d);
    }
    __syncthreads();

    for (int s = 0; s < 64; s++) {
        float gv = shA[l * 68 + s];
        uint64_t gg = pack2(gv, gv);
        const ulonglong2* xr = (const ulonglong2*)(sxdt + s * 68 + p0);
        ulonglong2 q0 = xr[0], q1 = xr[1], q2 = xr[2], q3 = xr[3];
        ffma2(acc2[0], gg, q0.x); ffma2(acc2[1], gg, q0.y);
        ffma2(acc2[2], gg, q1.x); ffma2(acc2[3], gg, q1.y);
        ffma2(acc2[4], gg, q2.x); ffma2(acc2[5], gg, q2.y);
        ffma2(acc2[6], gg, q3.x); ffma2(acc2[7], gg, q3.y);
    }

    float acc[16];
#pragma unroll
    for (int j = 0; j < 8; j++) unpack2(acc2[j], acc[2 * j], acc[2 * j + 1]);

    float Dv = Dp[h];
    float* yrow = g_yin + (size_t)(row0 + l) * NI + h * HD + p0;
    const float* xrow = g_x + (size_t)(row0 + l) * NI + h * HD + p0;
#pragma unroll
    for (int j4 = 0; j4 < 4; j4++) {
        float4 xv = *(const float4*)(xrow + j4 * 4);
        float4 o = make_float4(acc[j4*4+0] + xv.x * Dv, acc[j4*4+1] + xv.y * Dv,
                               acc[j4*4+2] + xv.z * Dv, acc[j4*4+3] + xv.w * Dv);
        *(float4*)(yrow + j4 * 4) = o;
    }
}

// ------ gate with silu(z), RMSNorm, * norm_w; emit bf16 hi/lo directly ------
__global__ void __launch_bounds__(256) gate_rms_kernel(const float* __restrict__ norm_w) {
    const int row = blockIdx.x;
    const int tid = threadIdx.x;
    const float* zrow = g_zx + (size_t)row * DIN;
    const float* yrow = g_yin + (size_t)row * NI;
    float v[8];
    float ss = 0.f;
#pragma unroll
    for (int i = 0; i < 8; i++) {
        int idx = tid + i * 256;
        float z = zrow[idx];
        float val = yrow[idx] * siluf(z);
        v[i] = val;
        ss += val * val;
    }
    __shared__ float red[256];
    red[tid] = ss;
    __syncthreads();
    for (int s = 128; s > 0; s >>= 1) {
        if (tid < s) red[tid] += red[tid + s];
        __syncthreads();
    }
    float scale = rsqrtf(red[0] / (float)NI + 1e-5f);
#pragma unroll
    for (int i = 0; i < 8; i++) {
        int idx = tid + i * 256;
        float o = v[i] * scale * norm_w[idx];
        __nv_bfloat16 h = __float2bfloat16_rn(o);
        __nv_bfloat16 lo = __float2bfloat16_rn(o - __bfloat162float(h));
        g_ynb_hi[(size_t)row * NI + idx] = h;
        g_ynb_lo[(size_t)row * NI + idx] = lo;
    }
}

// ---------------- launch ----------------
template <typename T>
static T* symaddr(const void* sym) {
    void* p = nullptr;
    cudaGetSymbolAddress(&p, sym);
    return (T*)p;
}

extern "C" void kernel_launch(void* const* d_in, const int* in_sizes, int n_in,
                              void* d_out, int out_size)
{
    const float* u         = (const float*)d_in[0];
    const float* init_conv = (const float*)d_in[1];
    const float* init_ssm  = (const float*)d_in[2];
    const float* w_in      = (const float*)d_in[3];
    const float* conv_w    = (const float*)d_in[4];
    const float* conv_b    = (const float*)d_in[5];
    const float* dt_bias   = (const float*)d_in[6];
    const float* A_log     = (const float*)d_in[7];
    const float* Dp        = (const float*)d_in[8];
    const float* norm_w    = (const float*)d_in[9];
    const float* w_out     = (const float*)d_in[10];

    float* out       = (float*)d_out;
    float* out_y     = out;
    float* out_conv  = out + (size_t)ROWS * E_;
    float* out_final = out_conv + (size_t)B_ * CD * NCONV;

    float* pzx = symaddr<float>(g_zx);
    __nv_bfloat16* p_u_hi  = symaddr<__nv_bfloat16>(g_u_hi);
    __nv_bfloat16* p_u_lo  = symaddr<__nv_bfloat16>(g_u_lo);
    __nv_bfloat16* p_win_hi  = symaddr<__nv_bfloat16>(g_win_hi);
    __nv_bfloat16* p_win_lo  = symaddr<__nv_bfloat16>(g_win_lo);
    __nv_bfloat16* p_wout_hi = symaddr<__nv_bfloat16>(g_wout_hi);
    __nv_bfloat16* p_wout_lo = symaddr<__nv_bfloat16>(g_wout_lo);
    __nv_bfloat16* p_yn_hi = symaddr<__nv_bfloat16>(g_ynb_hi);
    __nv_bfloat16* p_yn_lo = symaddr<__nv_bfloat16>(g_ynb_lo);

    cudaFuncSetAttribute(gemm_bf16, cudaFuncAttributeMaxDynamicSharedMemorySize, GM_SMEM);
    cudaFuncSetAttribute(states_kernel, cudaFuncAttributeMaxDynamicSharedMemorySize, STATES_SMEM);
    cudaFuncSetAttribute(y_kernel, cudaFuncAttributeMaxDynamicSharedMemorySize, Y_SMEM);

    // 0) operand conversions to bf16 hi/lo
    cvt_hilo_kernel<<<(ROWS * E_ / 4 + 511) / 512, 512>>>(u, p_u_hi, p_u_lo, ROWS * E_);
    cvt_win_kernel<<<(E_ * NPAD / 4 + 511) / 512, 512>>>(w_in);
    cvt_hilo_kernel<<<(NI * E_ / 4 + 511) / 512, 512>>>(w_out, p_wout_hi, p_wout_lo, NI * E_);

    // 1) in-projection
    gemm_bf16<<<dim3(NPAD / 128, ROWS / 256), 512, GM_SMEM>>>(
        p_u_hi, p_u_lo, p_win_hi, p_win_lo, pzx, ROWS, DIN, E_, NPAD);
    // 2) dt
    dt_kernel<<<(ROWS * NH + 255) / 256, 256>>>(dt_bias);
    // 3) conv + silu + split (4 channels x 8 timesteps per thread)
    conv_kernel<<<dim3((CD / 4 + 255) / 256, L_ / 8, B_), 256>>>(init_conv, conv_w, conv_b);
    // 4) new_conv_state output
    convstate_kernel<<<(B_ * CD * NCONV + 255) / 256, 256>>>(out_conv);
    // 5) per-chunk Gram matrix
    gmat_kernel<<<B_ * NC, 256>>>();
    // 6) per-chunk states (fp16 output)
    states_kernel<<<dim3(NH, NC, B_), 256, STATES_SMEM>>>(A_log);
    // 7) cross-chunk scan (fp16 storage)
    scan_kernel<<<dim3(8, NH, B_), 256>>>(init_ssm, out_final);
    // 8) Y
    y_kernel<<<dim3(NH, NC, B_), 256, Y_SMEM>>>(A_log, Dp);
    // 9) gate + rmsnorm
    gate_rms_kernel<<<ROWS, 256>>>(norm_w);
    // 10) out-projection
    gemm_bf16<<<dim3(E_ / 128, ROWS / 256), 512, GM_SMEM>>>(
        p_yn_hi, p_yn_lo, p_wout_hi, p_wout_lo, out_y, ROWS, E_, NI, E_);
}

// round 13
// speedup vs baseline: 1.1417x; 1.0460x over previous
#include <cuda_runtime.h>
#include <cuda_bf16.h>
#include <cuda_fp16.h>
#include <math.h>
#include <stdint.h>

// Problem constants
#define B_    2
#define L_    4096
#define E_    1024
#define NI    2048      // N_INNER
#define NS    128       // N_STATE
#define NH    32        // N_HEAD
#define HD    64        // HEADDIM
#define NCONV 4
#define CH    64        // CHUNK
#define NC    64        // chunks per sequence (L/CHUNK)
#define CD    2304      // CONV_DIM = NI + 2*NS
#define DIN   4384      // 2*NI + 2*NS + NH
#define NPAD  4480      // DIN padded to multiple of 128
#define ROWS  (B_*L_)   // 8192

// ---------------- scratch (device globals; no allocation allowed) ----------
__device__ float g_zx[(size_t)ROWS * DIN];
__device__ __half g_x [(size_t)ROWS * NI];                // fp16 conv output (x part)
__device__ float g_Bm[(size_t)ROWS * NS];
__device__ float g_Cm[(size_t)ROWS * NS];
__device__ float g_dt[(size_t)ROWS * NH];
__device__ float g_G [(size_t)B_ * NC * CH * CH];
__device__ __half g_st[(size_t)B_ * NC * NH * HD * NS];   // fp16 chunk/prev states
__device__ float g_asum[B_ * NC * NH];
__device__ __half g_yin[(size_t)ROWS * NI];               // fp16 pre-gate y

// bf16 hi/lo operand copies for tensor-core GEMMs
__device__ __nv_bfloat16 g_u_hi[(size_t)ROWS * E_];
__device__ __nv_bfloat16 g_u_lo[(size_t)ROWS * E_];
__device__ __nv_bfloat16 g_win_hi[(size_t)E_ * NPAD];
__device__ __nv_bfloat16 g_win_lo[(size_t)E_ * NPAD];
__device__ __nv_bfloat16 g_wout_hi[(size_t)NI * E_];
__device__ __nv_bfloat16 g_wout_lo[(size_t)NI * E_];
__device__ __nv_bfloat16 g_ynb_hi[(size_t)ROWS * NI];
__device__ __nv_bfloat16 g_ynb_lo[(size_t)ROWS * NI];

// ---------------- small helpers ----------------
__device__ __forceinline__ float siluf(float x) { return x / (1.f + expf(-x)); }
__device__ __forceinline__ float softplusf(float x) {
    return (x > 20.f) ? x : log1pf(expf(x));
}
__device__ __forceinline__ uint32_t smem_u32(const void* p) {
    uint32_t a;
    asm("{ .reg .u64 t; cvta.to.shared.u64 t, %1; cvt.u32.u64 %0, t; }" : "=r"(a) : "l"(p));
    return a;
}
// load 4 halves (8B) -> 4 floats
__device__ __forceinline__ float4 ldh4(const __half* p) {
    uint2 raw = *reinterpret_cast<const uint2*>(p);
    __half2 h0 = *reinterpret_cast<__half2*>(&raw.x);
    __half2 h1 = *reinterpret_cast<__half2*>(&raw.y);
    float2 f0 = __half22float2(h0);
    float2 f1 = __half22float2(h1);
    return make_float4(f0.x, f0.y, f1.x, f1.y);
}
// store 4 floats as 4 halves (8B)
__device__ __forceinline__ void sth4(__half* p, float4 v) {
    __half2 h0 = __floats2half2_rn(v.x, v.y);
    __half2 h1 = __floats2half2_rn(v.z, v.w);
    uint2 raw;
    raw.x = *reinterpret_cast<uint32_t*>(&h0);
    raw.y = *reinterpret_cast<uint32_t*>(&h1);
    *reinterpret_cast<uint2*>(p) = raw;
}

// ---------------- packed f32x2 (Blackwell, base sm_100) ----------------
__device__ __forceinline__ uint64_t pack2(float x, float y) {
    uint64_t r;
    asm("mov.b64 %0, {%1, %2};" : "=l"(r) : "f"(x), "f"(y));
    return r;
}
__device__ __forceinline__ void unpack2(uint64_t v, float& x, float& y) {
    asm("mov.b64 {%0, %1}, %2;" : "=f"(x), "=f"(y) : "l"(v));
}
__device__ __forceinline__ void ffma2(uint64_t& d, uint64_t a, uint64_t b) {
    asm("fma.rn.f32x2 %0, %1, %2, %0;" : "+l"(d) : "l"(a), "l"(b));
}
__device__ __forceinline__ void fmul2(uint64_t& d, uint64_t a) {
    asm("mul.rn.f32x2 %0, %0, %1;" : "+l"(d) : "l"(a));
}

// ---------------- warp-MMA primitives (sm_80+, valid on base sm_100) -------
__device__ __forceinline__ void ldm_x4(uint32_t* r, uint32_t addr) {
    asm volatile("ldmatrix.sync.aligned.m8n8.x4.shared.b16 {%0,%1,%2,%3}, [%4];"
        : "=r"(r[0]), "=r"(r[1]), "=r"(r[2]), "=r"(r[3]) : "r"(addr));
}
__device__ __forceinline__ void ldm_x2t(uint32_t* r, uint32_t addr) {
    asm volatile("ldmatrix.sync.aligned.m8n8.x2.trans.shared.b16 {%0,%1}, [%2];"
        : "=r"(r[0]), "=r"(r[1]) : "r"(addr));
}
__device__ __forceinline__ void mma_bf16(float* c, const uint32_t* a, const uint32_t* b) {
    asm volatile(
        "mma.sync.aligned.m16n8k16.row.col.f32.bf16.bf16.f32 "
        "{%0,%1,%2,%3}, {%4,%5,%6,%7}, {%8,%9}, {%0,%1,%2,%3};"
        : "+f"(c[0]), "+f"(c[1]), "+f"(c[2]), "+f"(c[3])
        : "r"(a[0]), "r"(a[1]), "r"(a[2]), "r"(a[3]), "r"(b[0]), "r"(b[1]));
}
__device__ __forceinline__ void cp16(uint32_t dst, const void* src) {
    asm volatile("cp.async.cg.shared.global [%0], [%1], 16;" :: "r"(dst), "l"(src));
}
#define CP_COMMIT() asm volatile("cp.async.commit_group;" ::: "memory")
#define CP_WAIT(n)  asm volatile("cp.async.wait_group %0;" :: "n"(n) : "memory")

// ---------------- fp32 -> bf16 hi/lo conversion kernels ----------------
__global__ void cvt_hilo_kernel(const float* __restrict__ s,
                                __nv_bfloat16* __restrict__ hi,
                                __nv_bfloat16* __restrict__ lo, int n)
{
    int i = (blockIdx.x * blockDim.x + threadIdx.x) * 4;
    if (i >= n) return;
    float4 v = *(const float4*)(s + i);
    float f[4] = {v.x, v.y, v.z, v.w};
    ushort hh[4], ll[4];
#pragma unroll
    for (int j = 0; j < 4; j++) {
        __nv_bfloat16 h = __float2bfloat16_rn(f[j]);
        __nv_bfloat16 l = __float2bfloat16_rn(f[j] - __bfloat162float(h));
        hh[j] = __bfloat16_as_ushort(h);
        ll[j] = __bfloat16_as_ushort(l);
    }
    *(ushort4*)((ushort*)hi + i) = make_ushort4(hh[0], hh[1], hh[2], hh[3]);
    *(ushort4*)((ushort*)lo + i) = make_ushort4(ll[0], ll[1], ll[2], ll[3]);
}

// w_in [E_][DIN] -> padded [E_][NPAD] hi/lo (zero-fill cols >= DIN)
__global__ void cvt_win_kernel(const float* __restrict__ w) {
    int i4 = (blockIdx.x * blockDim.x + threadIdx.x) * 4;
    if (i4 >= E_ * NPAD) return;
    int row = i4 / NPAD, col = i4 % NPAD;
    float f[4];
    if (col + 3 < DIN) {
        float4 v = *(const float4*)(w + (size_t)row * DIN + col);
        f[0] = v.x; f[1] = v.y; f[2] = v.z; f[3] = v.w;
    } else {
#pragma unroll
        for (int j = 0; j < 4; j++) {
            int cc = col + j;
            f[j] = (cc < DIN) ? w[(size_t)row * DIN + cc] : 0.f;
        }
    }
    ushort hh[4], ll[4];
#pragma unroll
    for (int j = 0; j < 4; j++) {
        __nv_bfloat16 h = __float2bfloat16_rn(f[j]);
        __nv_bfloat16 l = __float2bfloat16_rn(f[j] - __bfloat162float(h));
        hh[j] = __bfloat16_as_ushort(h);
        ll[j] = __bfloat16_as_ushort(l);
    }
    *(ushort4*)((ushort*)g_win_hi + i4) = make_ushort4(hh[0], hh[1], hh[2], hh[3]);
    *(ushort4*)((ushort*)g_win_lo + i4) = make_ushort4(ll[0], ll[1], ll[2], ll[3]);
}

// ================= tensor-core GEMM: C[M,N] = A[M,K] @ B[K,N] ==============
// bf16x3 split (hi*hi + hi*lo + lo*hi), fp32 accumulate.
// Block tile 256x128, 512 threads (16 warps: 4m x 4n, 64x32 per warp).
// K-tile 32, cp.async 3-stage pipeline (loads issued AFTER MMAs — R8 order).
#define ST_A_LO 20480
#define ST_B_HI 40960
#define ST_B_LO 49664
#define ST_BYTES 58368
#define STG 3
#define GM_SMEM (STG * ST_BYTES)

__global__ void __launch_bounds__(512, 1) gemm_bf16(
    const __nv_bfloat16* __restrict__ Ah, const __nv_bfloat16* __restrict__ Al,
    const __nv_bfloat16* __restrict__ Bh, const __nv_bfloat16* __restrict__ Bl,
    float* __restrict__ C, int M, int N, int K, int ldB)
{
    extern __shared__ char smem[];
    const uint32_t sb = smem_u32(smem);
    const int tid = threadIdx.x;
    const int wid = tid >> 5, lane = tid & 31;
    const int m0 = blockIdx.y * 256;
    const int n0 = blockIdx.x * 128;
    const int warp_m = wid >> 2;
    const int warp_n = wid & 3;

    float acc[4][4][4];
#pragma unroll
    for (int i = 0; i < 4; i++)
#pragma unroll
        for (int j = 0; j < 4; j++)
#pragma unroll
            for (int k = 0; k < 4; k++) acc[i][j][k] = 0.f;

    const int KTn = K >> 5;

    const int arow0 = tid >> 2, ach0 = tid & 3;
    const int arow1 = (tid + 512) >> 2, ach1 = tid & 3;
    const int bkr = tid >> 4, bch = tid & 15;

#define LOAD_STAGE(KT_) do { \
    const int k0_ = (KT_) << 5; \
    const uint32_t st_ = sb + ((KT_) % STG) * ST_BYTES; \
    { size_t go = (size_t)(m0 + arow0) * K + k0_ + ach0 * 8; \
      uint32_t so = st_ + arow0 * 80 + ach0 * 16; \
      cp16(so, Ah + go); cp16(so + ST_A_LO, Al + go); } \
    { size_t go = (size_t)(m0 + arow1) * K + k0_ + ach1 * 8; \
      uint32_t so = st_ + arow1 * 80 + ach1 * 16; \
      cp16(so, Ah + go); cp16(so + ST_A_LO, Al + go); } \
    { size_t go = (size_t)(k0_ + bkr) * ldB + n0 + bch * 8; \
      uint32_t so = st_ + ST_B_HI + bkr * 272 + bch * 16; \
      cp16(so, Bh + go); cp16(so + 8704, Bl + go); } \
} while (0)

#pragma unroll
    for (int s = 0; s < STG - 1; s++) {
        if (s < KTn) LOAD_STAGE(s);
        CP_COMMIT();
    }

    for (int kt = 0; kt < KTn; kt++) {
        CP_WAIT(STG - 2);
        __syncthreads();
        const uint32_t sAhi = sb + (kt % STG) * ST_BYTES;
        const uint32_t sAlo = sAhi + ST_A_LO;
        const uint32_t sBhi = sAhi + ST_B_HI;
        const uint32_t sBlo = sAhi + ST_B_LO;
#pragma unroll
        for (int ks = 0; ks < 2; ks++) {
            uint32_t a_hi[4][4], a_lo[4][4], b_hi[4][2], b_lo[4][2];
#pragma unroll
            for (int mi = 0; mi < 4; mi++) {
                int row = warp_m * 64 + mi * 16 + (lane & 15);
                uint32_t addr = row * 80 + ks * 32 + (lane >> 4) * 16;
                ldm_x4(a_hi[mi], sAhi + addr);
                ldm_x4(a_lo[mi], sAlo + addr);
            }
#pragma unroll
            for (int ni = 0; ni < 4; ni++) {
                int krow = ks * 16 + (lane & 15);
                int ncol = warp_n * 32 + ni * 8;
                uint32_t addr = krow * 272 + ncol * 2;
                ldm_x2t(b_hi[ni], sBhi + addr);
                ldm_x2t(b_lo[ni], sBlo + addr);
            }
#pragma unroll
            for (int mi = 0; mi < 4; mi++)
#pragma unroll
                for (int ni = 0; ni < 4; ni++) {
                    mma_bf16(acc[mi][ni], a_hi[mi], b_hi[ni]);
                    mma_bf16(acc[mi][ni], a_hi[mi], b_lo[ni]);
                    mma_bf16(acc[mi][ni], a_lo[mi], b_hi[ni]);
                }
        }
        if (kt + STG - 1 < KTn) LOAD_STAGE(kt + STG - 1);
        CP_COMMIT();
    }
#undef LOAD_STAGE

#pragma unroll
    for (int mi = 0; mi < 4; mi++) {
        int row = m0 + warp_m * 64 + mi * 16 + (lane >> 2);
#pragma unroll
        for (int ni = 0; ni < 4; ni++) {
            int col = n0 + warp_n * 32 + ni * 8 + (lane & 3) * 2;
            if (col < N) {
                *(float2*)(C + (size_t)row * N + col) =
                    make_float2(acc[mi][ni][0], acc[mi][ni][1]);
                *(float2*)(C + (size_t)(row + 8) * N + col) =
                    make_float2(acc[mi][ni][2], acc[mi][ni][3]);
            }
        }
    }
}

// ---------------- dt = softplus(raw + bias) ----------------
__global__ void dt_kernel(const float* __restrict__ dt_bias) {
    int i = blockIdx.x * blockDim.x + threadIdx.x;
    if (i >= ROWS * NH) return;
    int row = i / NH, h = i % NH;
    float x = g_zx[(size_t)row * DIN + (DIN - NH) + h] + dt_bias[h];
    g_dt[i] = softplusf(x);
}

// --- depthwise causal conv w4 + silu + split; 4 channels x 8 timesteps ----
__global__ void conv_kernel(const float* __restrict__ init_conv,
                            const float* __restrict__ conv_w,
                            const float* __restrict__ conv_b)
{
    int d4 = blockIdx.x * blockDim.x + threadIdx.x;
    if (d4 >= CD / 4) return;
    const int d = d4 * 4;
    const int t0 = blockIdx.y * 8;
    const int b = blockIdx.z;
    float4 cw[4];
#pragma unroll
    for (int j = 0; j < 4; j++) cw[j] = *(const float4*)(conv_w + (d + j) * 4);
    float4 bias = *(const float4*)(conv_b + d);
    float4 win[11];
#pragma unroll
    for (int i = 0; i < 11; i++) {
        int ti = t0 - 3 + i;
        if (ti >= 0) {
            win[i] = *(const float4*)(g_zx + (size_t)(b * L_ + ti) * DIN + NI + d);
        } else {
            win[i].x = init_conv[((size_t)b * CD + d + 0) * NCONV + (4 + ti)];
            win[i].y = init_conv[((size_t)b * CD + d + 1) * NCONV + (4 + ti)];
            win[i].z = init_conv[((size_t)b * CD + d + 2) * NCONV + (4 + ti)];
            win[i].w = init_conv[((size_t)b * CD + d + 3) * NCONV + (4 + ti)];
        }
    }
#pragma unroll
    for (int jt = 0; jt < 8; jt++) {
        float4 o;
        o.x = siluf(bias.x + cw[0].x*win[jt].x + cw[0].y*win[jt+1].x + cw[0].z*win[jt+2].x + cw[0].w*win[jt+3].x);
        o.y = siluf(bias.y + cw[1].x*win[jt].y + cw[1].y*win[jt+1].y + cw[1].z*win[jt+2].y + cw[1].w*win[jt+3].y);
        o.z = siluf(bias.z + cw[2].x*win[jt].z + cw[2].y*win[jt+1].z + cw[2].z*win[jt+2].z + cw[2].w*win[jt+3].z);
        o.w = siluf(bias.w + cw[3].x*win[jt].w + cw[3].y*win[jt+1].w + cw[3].z*win[jt+2].w + cw[3].w*win[jt+3].w);
        int row = b * L_ + t0 + jt;
        if (d < NI)           sth4(g_x + (size_t)row * NI + d, o);
        else if (d < NI + NS) *(float4*)(g_Bm + (size_t)row * NS + (d - NI)) = o;
        else                  *(float4*)(g_Cm + (size_t)row * NS + (d - NI - NS)) = o;
    }
}

// ---------------- new_conv_state output ----------------
__global__ void convstate_kernel(float* __restrict__ out) {
    int i = blockIdx.x * blockDim.x + threadIdx.x;
    if (i >= B_ * CD * NCONV) return;
    int k = i % NCONV;
    int d = (i / NCONV) % CD;
    int b = i / (NCONV * CD);
    out[i] = g_zx[(size_t)(b * L_ + (L_ - 4 + k)) * DIN + NI + d];
}

// ---------------- per-chunk Gram matrix G[l][s] = sum_n C[l,n]B[s,n] -------
__global__ void __launch_bounds__(256) gmat_kernel() {
    const int bc = blockIdx.x;
    const int b = bc / NC, c = bc % NC;
    const int row0 = b * L_ + c * CH;
    const int tid = threadIdx.x;
    __shared__ float sC[64 * 33];
    __shared__ float sB[64 * 33];
    const int l = tid >> 2;
    const int s0 = (tid & 3) * 16;
    float acc[16];
#pragma unroll
    for (int j = 0; j < 16; j++) acc[j] = 0.f;
    for (int n0 = 0; n0 < NS; n0 += 32) {
        for (int i = tid; i < 64 * 32; i += 256) {
            int r = i >> 5, nn = i & 31;
            sC[r * 33 + nn] = g_Cm[(size_t)(row0 + r) * NS + n0 + nn];
            sB[r * 33 + nn] = g_Bm[(size_t)(row0 + r) * NS + n0 + nn];
        }
        __syncthreads();
        for (int nn = 0; nn < 32; nn++) {
            float cv = sC[l * 33 + nn];
#pragma unroll
            for (int j = 0; j < 16; j++) acc[j] += cv * sB[(s0 + j) * 33 + nn];
        }
        __syncthreads();
    }
    float* Gp = g_G + (size_t)bc * (CH * CH);
#pragma unroll
    for (int j = 0; j < 16; j++) Gp[l * 64 + s0 + j] = acc[j];
}

// ------- per-chunk states[p][n] = sum_l B[l,n]*decay[l]*dt[l]*x[l,p] -------
#define STATES_SMEM ((64*68 + 64*132) * 4)
__global__ void __launch_bounds__(256) states_kernel(const float* __restrict__ A_log) {
    extern __shared__ float sm[];
    float* xs = sm;             // [64][68]
    float* sB = sm + 64 * 68;   // [64][132]
    __shared__ float sdt[64], w[64];
    __shared__ float asum_s;
    const int h = blockIdx.x, c = blockIdx.y, b = blockIdx.z;
    const int tid = threadIdx.x;
    const int row0 = b * L_ + c * CH;
    if (tid < 64) sdt[tid] = g_dt[(size_t)(row0 + tid) * NH + h];
    __syncthreads();
    if (tid == 0) {
        float A = -expf(A_log[h]);
        float s = 0.f;
        for (int l = 0; l < 64; l++) { s += A * sdt[l]; w[l] = s; }  // w = acs (temp)
        asum_s = s;
        g_asum[(b * NC + c) * NH + h] = s;
    }
    __syncthreads();
    float wv = (tid < 64) ? expf(asum_s - w[tid]) * sdt[tid] : 0.f;
    __syncthreads();
    if (tid < 64) w[tid] = wv;
    __syncthreads();

    for (int i = tid; i < 64 * 16; i += 256) {
        int l = i >> 4, q = i & 15;
        float4 v = ldh4(g_x + (size_t)(row0 + l) * NI + h * HD + q * 4);
        float wl = w[l];
        *(float4*)(xs + l * 68 + q * 4) = make_float4(v.x * wl, v.y * wl, v.z * wl, v.w * wl);
    }
    for (int i = tid; i < 64 * 32; i += 256) {
        int l = i >> 5, q = i & 31;
        *(float4*)(sB + l * 132 + q * 4) =
            *(const float4*)(g_Bm + (size_t)(row0 + l) * NS + q * 4);
    }
    __syncthreads();

    const int pg = tid >> 5;   // 8 p-groups of 8
    const int ng = tid & 31;   // 32 n-pairs (x2 halves)
    uint64_t acc2[4][4];
    const uint64_t z2 = pack2(0.f, 0.f);
#pragma unroll
    for (int i = 0; i < 4; i++)
#pragma unroll
        for (int j = 0; j < 4; j++) acc2[i][j] = z2;

    for (int l = 0; l < 64; l++) {
        const ulonglong2* xr = (const ulonglong2*)(xs + l * 68 + pg * 8);
        ulonglong2 xa = xr[0], xb = xr[1];
        float2 bA = *(const float2*)(sB + l * 132 + 2 * ng);
        float2 bB = *(const float2*)(sB + l * 132 + 64 + 2 * ng);
        uint64_t bb0 = pack2(bA.x, bA.x), bb1 = pack2(bA.y, bA.y);
        uint64_t bb2 = pack2(bB.x, bB.x), bb3 = pack2(bB.y, bB.y);
        uint64_t xv[4] = {xa.x, xa.y, xb.x, xb.y};
#pragma unroll
        for (int i = 0; i < 4; i++) {
            ffma2(acc2[i][0], xv[i], bb0);
            ffma2(acc2[i][1], xv[i], bb1);
            ffma2(acc2[i][2], xv[i], bb2);
            ffma2(acc2[i][3], xv[i], bb3);
        }
    }
    __half* outp = g_st + (size_t)((b * NC + c) * NH + h) * HD * NS;
#pragma unroll
    for (int i = 0; i < 4; i++) {
        float a0e, a0o, a1e, a1o, a2e, a2o, a3e, a3o;
        unpack2(acc2[i][0], a0e, a0o);
        unpack2(acc2[i][1], a1e, a1o);
        unpack2(acc2[i][2], a2e, a2o);
        unpack2(acc2[i][3], a3e, a3o);
        int pe = pg * 8 + i * 2, po = pe + 1;
        *(__half2*)(outp + (size_t)pe * NS + 2 * ng)      = __floats2half2_rn(a0e, a1e);
        *(__half2*)(outp + (size_t)pe * NS + 64 + 2 * ng) = __floats2half2_rn(a2e, a3e);
        *(__half2*)(outp + (size_t)po * NS + 2 * ng)      = __floats2half2_rn(a0o, a1o);
        *(__half2*)(outp + (size_t)po * NS + 64 + 2 * ng) = __floats2half2_rn(a2o, a3o);
    }
}

// ------- cross-chunk state scan (fp16 storage, fp32 accumulate, prefetch) ---
__global__ void __launch_bounds__(256) scan_kernel(const float* __restrict__ init_ssm,
                                                   float* __restrict__ final_out)
{
    const int seg = blockIdx.x;
    const int h = blockIdx.y, b = blockIdx.z;
    const int tid = threadIdx.x;
    const int e = seg * 1024 + tid * 4;
    const size_t base_bh = (size_t)(b * NH + h) * HD * NS;
    const size_t stride_c = (size_t)NH * HD * NS;
    __half* p0 = g_st + (size_t)(b * NC) * stride_c + (size_t)h * HD * NS + e;
    float4 S = *reinterpret_cast<const float4*>(init_ssm + base_bh + e);
    uint2 raw = *reinterpret_cast<uint2*>(p0);
    for (int c = 0; c < NC; c++) {
        uint2 nxt;
        if (c + 1 < NC)
            nxt = *reinterpret_cast<uint2*>(p0 + (size_t)(c + 1) * stride_c);
        float dec = expf(g_asum[(b * NC + c) * NH + h]);
        __half2 h0 = *reinterpret_cast<__half2*>(&raw.x);
        __half2 h1 = *reinterpret_cast<__half2*>(&raw.y);
        float2 f0 = __half22float2(h0);
        float2 f1 = __half22float2(h1);
        __half2 s0 = __floats2half2_rn(S.x, S.y);
        __half2 s1 = __floats2half2_rn(S.z, S.w);
        uint2 sr;
        sr.x = *reinterpret_cast<uint32_t*>(&s0);
        sr.y = *reinterpret_cast<uint32_t*>(&s1);
        *reinterpret_cast<uint2*>(p0 + (size_t)c * stride_c) = sr;
        S.x = dec * S.x + f0.x;
        S.y = dec * S.y + f0.y;
        S.z = dec * S.z + f1.x;
        S.w = dec * S.w + f1.y;
        raw = nxt;
    }
    *reinterpret_cast<float4*>(final_out + base_bh + e) = S;
}

// ---------------- Y = (G∘L)@xdt + exp(Acs)*(C @ Sprev^T) + x*D ------------
#define Y_SMEM ((128*68 + 64*132) * 4)
__global__ void __launch_bounds__(256) y_kernel(const float* __restrict__ A_log,
                                                const float* __restrict__ Dp)
{
    extern __shared__ float sm[];
    float* shA = sm;             // [128][68]
    float* sC  = sm + 128 * 68;  // [64][132]
    __shared__ float acs[64], sdt[64];
    const int h = blockIdx.x, c = blockIdx.y, b = blockIdx.z;
    const int tid = threadIdx.x;
    const int row0 = b * L_ + c * CH;
    if (tid < 64) sdt[tid] = g_dt[(size_t)(row0 + tid) * NH + h];
    __syncthreads();
    if (tid == 0) {
        float A = -expf(A_log[h]);
        float s = 0.f;
        for (int l = 0; l < 64; l++) { s += A * sdt[l]; acs[l] = s; }
    }
    __syncthreads();

    const __half* Sp = g_st + (size_t)((b * NC + c) * NH + h) * HD * NS;
    for (int i = tid; i < 64 * 32; i += 256) {
        int l = i >> 5, q = i & 31;
        *(float4*)(sC + l * 132 + q * 4) =
            *(const float4*)(g_Cm + (size_t)(row0 + l) * NS + q * 4);
    }
    for (int i = tid; i < 64 * 32; i += 256) {
        int p = i >> 5, q = i & 31;
        float4 v = ldh4(Sp + (size_t)p * NS + q * 4);
        shA[(q * 4 + 0) * 68 + p] = v.x;
        shA[(q * 4 + 1) * 68 + p] = v.y;
        shA[(q * 4 + 2) * 68 + p] = v.z;
        shA[(q * 4 + 3) * 68 + p] = v.w;
    }
    __syncthreads();

    const int l = tid >> 2;
    const int p0 = (tid & 3) * 16;
    uint64_t acc2[8];
    const uint64_t z2 = pack2(0.f, 0.f);
#pragma unroll
    for (int j = 0; j < 8; j++) acc2[j] = z2;

    // phase 1: Y_off[l][p] = sum_n C[l][n] * S^T[n][p]
    for (int nn = 0; nn < 128; nn++) {
        float cv = sC[l * 132 + nn];
        uint64_t cc = pack2(cv, cv);
        const ulonglong2* sr = (const ulonglong2*)(shA + nn * 68 + p0);
        ulonglong2 q0 = sr[0], q1 = sr[1], q2 = sr[2], q3 = sr[3];
        ffma2(acc2[0], cc, q0.x); ffma2(acc2[1], cc, q0.y);
        ffma2(acc2[2], cc, q1.x); ffma2(acc2[3], cc, q1.y);
        ffma2(acc2[4], cc, q2.x); ffma2(acc2[5], cc, q2.y);
        ffma2(acc2[6], cc, q3.x); ffma2(acc2[7], cc, q3.y);
    }
    {
        float eAl = expf(acs[l]);
        uint64_t ee = pack2(eAl, eAl);
#pragma unroll
        for (int j = 0; j < 8; j++) fmul2(acc2[j], ee);
    }
    __syncthreads();   // done reading shA as S^T

    // phase 2: build sM = G*exp(acs[r]-acs[s]) masked, sxdt = x*dt [s][p]
    const float* Gp = g_G + (size_t)(b * NC + c) * (CH * CH);
    for (int i = tid; i < 64 * 64; i += 256) {
        int r = i >> 6, s = i & 63;
        shA[r * 68 + s] = (s <= r) ? Gp[r * 64 + s] * expf(acs[r] - acs[s]) : 0.f;
    }
    float* sxdt = shA + 64 * 68;
    for (int i = tid; i < 64 * 16; i += 256) {
        int s = i >> 4, q = i & 15;
        float4 v = ldh4(g_x + (size_t)(row0 + s) * NI + h * HD + q * 4);
        float d = sdt[s];
        *(float4*)(sxdt + s * 68 + q * 4) = make_float4(v.x * d, v.y * d, v.z * d, v.w * d);
    }
    __syncthreads();

    for (int s = 0; s < 64; s++) {
        float gv = shA[l * 68 + s];
        uint64_t gg = pack2(gv, gv);
        const ulonglong2* xr = (const ulonglong2*)(sxdt + s * 68 + p0);
        ulonglong2 q0 = xr[0], q1 = xr[1], q2 = xr[2], q3 = xr[3];
        ffma2(acc2[0], gg, q0.x); ffma2(acc2[1], gg, q0.y);
        ffma2(acc2[2], gg, q1.x); ffma2(acc2[3], gg, q1.y);
        ffma2(acc2[4], gg, q2.x); ffma2(acc2[5], gg, q2.y);
        ffma2(acc2[6], gg, q3.x); ffma2(acc2[7], gg, q3.y);
    }

    float acc[16];
#pragma unroll
    for (int j = 0; j < 8; j++) unpack2(acc2[j], acc[2 * j], acc[2 * j + 1]);

    float Dv = Dp[h];
    __half* yrow = g_yin + (size_t)(row0 + l) * NI + h * HD + p0;
    const __half* xrow = g_x + (size_t)(row0 + l) * NI + h * HD + p0;
#pragma unroll
    for (int j4 = 0; j4 < 4; j4++) {
        float4 xv = ldh4(xrow + j4 * 4);
        float4 o = make_float4(acc[j4*4+0] + xv.x * Dv, acc[j4*4+1] + xv.y * Dv,
                               acc[j4*4+2] + xv.z * Dv, acc[j4*4+3] + xv.w * Dv);
        sth4(yrow + j4 * 4, o);
    }
}

// ------ gate with silu(z), RMSNorm, * norm_w; emit bf16 hi/lo directly ------
__global__ void __launch_bounds__(256) gate_rms_kernel(const float* __restrict__ norm_w) {
    const int row = blockIdx.x;
    const int tid = threadIdx.x;
    const float* zrow = g_zx + (size_t)row * DIN;
    const __half* yrow = g_yin + (size_t)row * NI;
    float v[8];
    float ss = 0.f;
#pragma unroll
    for (int i = 0; i < 8; i++) {
        int idx = tid + i * 256;
        float z = zrow[idx];
        float val = __half2float(yrow[idx]) * siluf(z);
        v[i] = val;
        ss += val * val;
    }
    __shared__ float red[256];
    red[tid] = ss;
    __syncthreads();
    for (int s = 128; s > 0; s >>= 1) {
        if (tid < s) red[tid] += red[tid + s];
        __syncthreads();
    }
    float scale = rsqrtf(red[0] / (float)NI + 1e-5f);
#pragma unroll
    for (int i = 0; i < 8; i++) {
        int idx = tid + i * 256;
        float o = v[i] * scale * norm_w[idx];
        __nv_bfloat16 h = __float2bfloat16_rn(o);
        __nv_bfloat16 lo = __float2bfloat16_rn(o - __bfloat162float(h));
        g_ynb_hi[(size_t)row * NI + idx] = h;
        g_ynb_lo[(size_t)row * NI + idx] = lo;
    }
}

// ---------------- launch ----------------
template <typename T>
static T* symaddr(const void* sym) {
    void* p = nullptr;
    cudaGetSymbolAddress(&p, sym);
    return (T*)p;
}

extern "C" void kernel_launch(void* const* d_in, const int* in_sizes, int n_in,
                              void* d_out, int out_size)
{
    const float* u         = (const float*)d_in[0];
    const float* init_conv = (const float*)d_in[1];
    const float* init_ssm  = (const float*)d_in[2];
    const float* w_in      = (const float*)d_in[3];
    const float* conv_w    = (const float*)d_in[4];
    const float* conv_b    = (const float*)d_in[5];
    const float* dt_bias   = (const float*)d_in[6];
    const float* A_log     = (const float*)d_in[7];
    const float* Dp        = (const float*)d_in[8];
    const float* norm_w    = (const float*)d_in[9];
    const float* w_out     = (const float*)d_in[10];

    float* out       = (float*)d_out;
    float* out_y     = out;
    float* out_conv  = out + (size_t)ROWS * E_;
    float* out_final = out_conv + (size_t)B_ * CD * NCONV;

    float* pzx = symaddr<float>(g_zx);
    __nv_bfloat16* p_u_hi  = symaddr<__nv_bfloat16>(g_u_hi);
    __nv_bfloat16* p_u_lo  = symaddr<__nv_bfloat16>(g_u_lo);
    __nv_bfloat16* p_win_hi  = symaddr<__nv_bfloat16>(g_win_hi);
    __nv_bfloat16* p_win_lo  = symaddr<__nv_bfloat16>(g_win_lo);
    __nv_bfloat16* p_wout_hi = symaddr<__nv_bfloat16>(g_wout_hi);
    __nv_bfloat16* p_wout_lo = symaddr<__nv_bfloat16>(g_wout_lo);
    __nv_bfloat16* p_yn_hi = symaddr<__nv_bfloat16>(g_ynb_hi);
    __nv_bfloat16* p_yn_lo = symaddr<__nv_bfloat16>(g_ynb_lo);

    cudaFuncSetAttribute(gemm_bf16, cudaFuncAttributeMaxDynamicSharedMemorySize, GM_SMEM);
    cudaFuncSetAttribute(states_kernel, cudaFuncAttributeMaxDynamicSharedMemorySize, STATES_SMEM);
    cudaFuncSetAttribute(y_kernel, cudaFuncAttributeMaxDynamicSharedMemorySize, Y_SMEM);

    // 0) operand conversions to bf16 hi/lo
    cvt_hilo_kernel<<<(ROWS * E_ / 4 + 511) / 512, 512>>>(u, p_u_hi, p_u_lo, ROWS * E_);
    cvt_win_kernel<<<(E_ * NPAD / 4 + 511) / 512, 512>>>(w_in);
    cvt_hilo_kernel<<<(NI * E_ / 4 + 511) / 512, 512>>>(w_out, p_wout_hi, p_wout_lo, NI * E_);

    // 1) in-projection
    gemm_bf16<<<dim3(NPAD / 128, ROWS / 256), 512, GM_SMEM>>>(
        p_u_hi, p_u_lo, p_win_hi, p_win_lo, pzx, ROWS, DIN, E_, NPAD);
    // 2) dt
    dt_kernel<<<(ROWS * NH + 255) / 256, 256>>>(dt_bias);
    // 3) conv + silu + split (4 channels x 8 timesteps per thread)
    conv_kernel<<<dim3((CD / 4 + 255) / 256, L_ / 8, B_), 256>>>(init_conv, conv_w, conv_b);
    // 4) new_conv_state output
    convstate_kernel<<<(B_ * CD * NCONV + 255) / 256, 256>>>(out_conv);
    // 5) per-chunk Gram matrix
    gmat_kernel<<<B_ * NC, 256>>>();
    // 6) per-chunk states (fp16 output)
    states_kernel<<<dim3(NH, NC, B_), 256, STATES_SMEM>>>(A_log);
    // 7) cross-chunk scan (fp16 storage, prefetch)
    scan_kernel<<<dim3(8, NH, B_), 256>>>(init_ssm, out_final);
    // 8) Y (fp16 x/yin)
    y_kernel<<<dim3(NH, NC, B_), 256, Y_SMEM>>>(A_log, Dp);
    // 9) gate + rmsnorm
    gate_rms_kernel<<<ROWS, 256>>>(norm_w);
    // 10) out-projection
    gemm_bf16<<<dim3(E_ / 128, ROWS / 256), 512, GM_SMEM>>>(
        p_yn_hi, p_yn_lo, p_wout_hi, p_wout_lo, out_y, ROWS, E_, NI, E_);
}

// round 14
// speedup vs baseline: 1.3032x; 1.1415x over previous
#include <cuda_runtime.h>
#include <cuda_bf16.h>
#include <cuda_fp16.h>
#include <math.h>
#include <stdint.h>

// Problem constants
#define B_    2
#define L_    4096
#define E_    1024
#define NI    2048      // N_INNER
#define NS    128       // N_STATE
#define NH    32        // N_HEAD
#define HD    64        // HEADDIM
#define NCONV 4
#define CH    64        // CHUNK
#define NC    64        // chunks per sequence (L/CHUNK)
#define CD    2304      // CONV_DIM = NI + 2*NS
#define DIN   4384      // 2*NI + 2*NS + NH
#define NPAD  4480      // DIN padded to multiple of 128
#define ROWS  (B_*L_)   // 8192

// ---------------- scratch (device globals; no allocation allowed) ----------
__device__ float g_zx[(size_t)ROWS * DIN];
__device__ __half g_x [(size_t)ROWS * NI];                // fp16 conv output (x part)
__device__ float g_Bm[(size_t)ROWS * NS];
__device__ float g_Cm[(size_t)ROWS * NS];
__device__ float g_dt[(size_t)ROWS * NH];
__device__ float g_G [(size_t)B_ * NC * CH * CH];
__device__ __half g_st[(size_t)B_ * NC * NH * HD * NS];   // fp16 chunk/prev states
__device__ float g_asum[B_ * NC * NH];
__device__ __half g_yin[(size_t)ROWS * NI];               // fp16 pre-gate y

// fp16 operand copies for tensor-core GEMMs (A single, B hi/lo split)
__device__ __half g_u_h [(size_t)ROWS * E_];
__device__ __half g_win_hi[(size_t)E_ * NPAD];
__device__ __half g_win_lo[(size_t)E_ * NPAD];
__device__ __half g_wout_hi[(size_t)NI * E_];
__device__ __half g_wout_lo[(size_t)NI * E_];
__device__ __half g_ynb[(size_t)ROWS * NI];

// ---------------- small helpers ----------------
__device__ __forceinline__ float siluf(float x) { return x / (1.f + expf(-x)); }
__device__ __forceinline__ float softplusf(float x) {
    return (x > 20.f) ? x : log1pf(expf(x));
}
__device__ __forceinline__ uint32_t smem_u32(const void* p) {
    uint32_t a;
    asm("{ .reg .u64 t; cvta.to.shared.u64 t, %1; cvt.u32.u64 %0, t; }" : "=r"(a) : "l"(p));
    return a;
}
// load 4 halves (8B) -> 4 floats
__device__ __forceinline__ float4 ldh4(const __half* p) {
    uint2 raw = *reinterpret_cast<const uint2*>(p);
    __half2 h0 = *reinterpret_cast<__half2*>(&raw.x);
    __half2 h1 = *reinterpret_cast<__half2*>(&raw.y);
    float2 f0 = __half22float2(h0);
    float2 f1 = __half22float2(h1);
    return make_float4(f0.x, f0.y, f1.x, f1.y);
}
// store 4 floats as 4 halves (8B)
__device__ __forceinline__ void sth4(__half* p, float4 v) {
    __half2 h0 = __floats2half2_rn(v.x, v.y);
    __half2 h1 = __floats2half2_rn(v.z, v.w);
    uint2 raw;
    raw.x = *reinterpret_cast<uint32_t*>(&h0);
    raw.y = *reinterpret_cast<uint32_t*>(&h1);
    *reinterpret_cast<uint2*>(p) = raw;
}

// ---------------- packed f32x2 (Blackwell, base sm_100) ----------------
__device__ __forceinline__ uint64_t pack2(float x, float y) {
    uint64_t r;
    asm("mov.b64 %0, {%1, %2};" : "=l"(r) : "f"(x), "f"(y));
    return r;
}
__device__ __forceinline__ void unpack2(uint64_t v, float& x, float& y) {
    asm("mov.b64 {%0, %1}, %2;" : "=f"(x), "=f"(y) : "l"(v));
}
__device__ __forceinline__ void ffma2(uint64_t& d, uint64_t a, uint64_t b) {
    asm("fma.rn.f32x2 %0, %1, %2, %0;" : "+l"(d) : "l"(a), "l"(b));
}
__device__ __forceinline__ void fmul2(uint64_t& d, uint64_t a) {
    asm("mul.rn.f32x2 %0, %0, %1;" : "+l"(d) : "l"(a));
}

// ---------------- warp-MMA primitives (sm_80+, valid on base sm_100) -------
__device__ __forceinline__ void ldm_x4(uint32_t* r, uint32_t addr) {
    asm volatile("ldmatrix.sync.aligned.m8n8.x4.shared.b16 {%0,%1,%2,%3}, [%4];"
        : "=r"(r[0]), "=r"(r[1]), "=r"(r[2]), "=r"(r[3]) : "r"(addr));
}
__device__ __forceinline__ void ldm_x2t(uint32_t* r, uint32_t addr) {
    asm volatile("ldmatrix.sync.aligned.m8n8.x2.trans.shared.b16 {%0,%1}, [%2];"
        : "=r"(r[0]), "=r"(r[1]) : "r"(addr));
}
__device__ __forceinline__ void mma_f16(float* c, const uint32_t* a, const uint32_t* b) {
    asm volatile(
        "mma.sync.aligned.m16n8k16.row.col.f32.f16.f16.f32 "
        "{%0,%1,%2,%3}, {%4,%5,%6,%7}, {%8,%9}, {%0,%1,%2,%3};"
        : "+f"(c[0]), "+f"(c[1]), "+f"(c[2]), "+f"(c[3])
        : "r"(a[0]), "r"(a[1]), "r"(a[2]), "r"(a[3]), "r"(b[0]), "r"(b[1]));
}
__device__ __forceinline__ void cp16(uint32_t dst, const void* src) {
    asm volatile("cp.async.cg.shared.global [%0], [%1], 16;" :: "r"(dst), "l"(src));
}
#define CP_COMMIT() asm volatile("cp.async.commit_group;" ::: "memory")
#define CP_WAIT(n)  asm volatile("cp.async.wait_group %0;" :: "n"(n) : "memory")

// ---------------- fp32 -> fp16 conversion kernels ----------------
__global__ void cvt_f16_kernel(const float* __restrict__ s, __half* __restrict__ dst, int n) {
    int i = (blockIdx.x * blockDim.x + threadIdx.x) * 4;
    if (i >= n) return;
    float4 v = *(const float4*)(s + i);
    sth4(dst + i, v);
}

__global__ void cvt_hilo16_kernel(const float* __restrict__ s,
                                  __half* __restrict__ hi, __half* __restrict__ lo, int n)
{
    int i = (blockIdx.x * blockDim.x + threadIdx.x) * 4;
    if (i >= n) return;
    float4 v = *(const float4*)(s + i);
    float f[4] = {v.x, v.y, v.z, v.w};
    float fh[4], fl[4];
#pragma unroll
    for (int j = 0; j < 4; j++) {
        __half h = __float2half_rn(f[j]);
        fh[j] = __half2float(h);
        fl[j] = f[j] - fh[j];
    }
    sth4(hi + i, make_float4(fh[0], fh[1], fh[2], fh[3]));
    sth4(lo + i, make_float4(fl[0], fl[1], fl[2], fl[3]));
}

// w_in [E_][DIN] -> padded [E_][NPAD] fp16 hi/lo (zero-fill cols >= DIN)
__global__ void cvt_win16_kernel(const float* __restrict__ w) {
    int i4 = (blockIdx.x * blockDim.x + threadIdx.x) * 4;
    if (i4 >= E_ * NPAD) return;
    int row = i4 / NPAD, col = i4 % NPAD;
    float f[4];
    if (col + 3 < DIN) {
        float4 v = *(const float4*)(w + (size_t)row * DIN + col);
        f[0] = v.x; f[1] = v.y; f[2] = v.z; f[3] = v.w;
    } else {
#pragma unroll
        for (int j = 0; j < 4; j++) {
            int cc = col + j;
            f[j] = (cc < DIN) ? w[(size_t)row * DIN + cc] : 0.f;
        }
    }
    float fh[4], fl[4];
#pragma unroll
    for (int j = 0; j < 4; j++) {
        __half h = __float2half_rn(f[j]);
        fh[j] = __half2float(h);
        fl[j] = f[j] - fh[j];
    }
    sth4(g_win_hi + i4, make_float4(fh[0], fh[1], fh[2], fh[3]));
    sth4(g_win_lo + i4, make_float4(fl[0], fl[1], fl[2], fl[3]));
}

// ================= tensor-core GEMM: C[M,N] = A[M,K] @ B[K,N] ==============
// fp16 asymmetric split: A single fp16, B fp16 hi+lo; C = A*(Bhi+Blo), fp32 acc.
// Dropped term A_lo*B ~ 2^-12 relative. 2 MMA passes (vs 3 for bf16x3).
// Block tile 256x128, 512 threads (16 warps 4x4, 64x32/warp), K-tile 32, 4-stage cp.async.
// Stage: A[256][40]h (20480) | Bhi[32][136]h (8704) | Blo (8704) = 37888 B
#define ST_B_HI 20480
#define ST_B_LO 29184
#define ST_BYTES 37888
#define STG 4
#define GM_SMEM (STG * ST_BYTES)

__global__ void __launch_bounds__(512, 1) gemm_f16(
    const __half* __restrict__ A,
    const __half* __restrict__ Bh, const __half* __restrict__ Bl,
    float* __restrict__ C, int M, int N, int K, int ldB)
{
    extern __shared__ char smem[];
    const uint32_t sb = smem_u32(smem);
    const int tid = threadIdx.x;
    const int wid = tid >> 5, lane = tid & 31;
    const int m0 = blockIdx.y * 256;
    const int n0 = blockIdx.x * 128;
    const int warp_m = wid >> 2;
    const int warp_n = wid & 3;

    float acc[4][4][4];
#pragma unroll
    for (int i = 0; i < 4; i++)
#pragma unroll
        for (int j = 0; j < 4; j++)
#pragma unroll
            for (int k = 0; k < 4; k++) acc[i][j][k] = 0.f;

    const int KTn = K >> 5;

    // A: 1024 chunks (256 rows x 4x16B); thread does c=tid, tid+512
    const int arow0 = tid >> 2, ach0 = tid & 3;
    const int arow1 = (tid + 512) >> 2, ach1 = tid & 3;
    // B: 512 positions (32 rows x 16x16B); thread does hi+lo at c=tid
    const int bkr = tid >> 4, bch = tid & 15;

#define LOAD_STAGE(KT_) do { \
    const int k0_ = (KT_) << 5; \
    const uint32_t st_ = sb + ((KT_) % STG) * ST_BYTES; \
    { size_t go = (size_t)(m0 + arow0) * K + k0_ + ach0 * 8; \
      cp16(st_ + arow0 * 80 + ach0 * 16, A + go); } \
    { size_t go = (size_t)(m0 + arow1) * K + k0_ + ach1 * 8; \
      cp16(st_ + arow1 * 80 + ach1 * 16, A + go); } \
    { size_t go = (size_t)(k0_ + bkr) * ldB + n0 + bch * 8; \
      uint32_t so = st_ + ST_B_HI + bkr * 272 + bch * 16; \
      cp16(so, Bh + go); cp16(so + 8704, Bl + go); } \
} while (0)

#pragma unroll
    for (int s = 0; s < STG - 1; s++) {
        if (s < KTn) LOAD_STAGE(s);
        CP_COMMIT();
    }

    for (int kt = 0; kt < KTn; kt++) {
        CP_WAIT(STG - 2);
        __syncthreads();
        const uint32_t sA   = sb + (kt % STG) * ST_BYTES;
        const uint32_t sBhi = sA + ST_B_HI;
        const uint32_t sBlo = sA + ST_B_LO;
#pragma unroll
        for (int ks = 0; ks < 2; ks++) {
            uint32_t a[4][4], b_hi[4][2], b_lo[4][2];
#pragma unroll
            for (int mi = 0; mi < 4; mi++) {
                int row = warp_m * 64 + mi * 16 + (lane & 15);
                uint32_t addr = row * 80 + ks * 32 + (lane >> 4) * 16;
                ldm_x4(a[mi], sA + addr);
            }
#pragma unroll
            for (int ni = 0; ni < 4; ni++) {
                int krow = ks * 16 + (lane & 15);
                int ncol = warp_n * 32 + ni * 8;
                uint32_t addr = krow * 272 + ncol * 2;
                ldm_x2t(b_hi[ni], sBhi + addr);
                ldm_x2t(b_lo[ni], sBlo + addr);
            }
#pragma unroll
            for (int mi = 0; mi < 4; mi++)
#pragma unroll
                for (int ni = 0; ni < 4; ni++) {
                    mma_f16(acc[mi][ni], a[mi], b_hi[ni]);
                    mma_f16(acc[mi][ni], a[mi], b_lo[ni]);
                }
        }
        if (kt + STG - 1 < KTn) LOAD_STAGE(kt + STG - 1);
        CP_COMMIT();
    }
#undef LOAD_STAGE

#pragma unroll
    for (int mi = 0; mi < 4; mi++) {
        int row = m0 + warp_m * 64 + mi * 16 + (lane >> 2);
#pragma unroll
        for (int ni = 0; ni < 4; ni++) {
            int col = n0 + warp_n * 32 + ni * 8 + (lane & 3) * 2;
            if (col < N) {
                *(float2*)(C + (size_t)row * N + col) =
                    make_float2(acc[mi][ni][0], acc[mi][ni][1]);
                *(float2*)(C + (size_t)(row + 8) * N + col) =
                    make_float2(acc[mi][ni][2], acc[mi][ni][3]);
            }
        }
    }
}

// ---------------- dt = softplus(raw + bias) ----------------
__global__ void dt_kernel(const float* __restrict__ dt_bias) {
    int i = blockIdx.x * blockDim.x + threadIdx.x;
    if (i >= ROWS * NH) return;
    int row = i / NH, h = i % NH;
    float x = g_zx[(size_t)row * DIN + (DIN - NH) + h] + dt_bias[h];
    g_dt[i] = softplusf(x);
}

// --- depthwise causal conv w4 + silu + split; 4 channels x 8 timesteps ----
__global__ void conv_kernel(const float* __restrict__ init_conv,
                            const float* __restrict__ conv_w,
                            const float* __restrict__ conv_b)
{
    int d4 = blockIdx.x * blockDim.x + threadIdx.x;
    if (d4 >= CD / 4) return;
    const int d = d4 * 4;
    const int t0 = blockIdx.y * 8;
    const int b = blockIdx.z;
    float4 cw[4];
#pragma unroll
    for (int j = 0; j < 4; j++) cw[j] = *(const float4*)(conv_w + (d + j) * 4);
    float4 bias = *(const float4*)(conv_b + d);
    float4 win[11];
#pragma unroll
    for (int i = 0; i < 11; i++) {
        int ti = t0 - 3 + i;
        if (ti >= 0) {
            win[i] = *(const float4*)(g_zx + (size_t)(b * L_ + ti) * DIN + NI + d);
        } else {
            win[i].x = init_conv[((size_t)b * CD + d + 0) * NCONV + (4 + ti)];
            win[i].y = init_conv[((size_t)b * CD + d + 1) * NCONV + (4 + ti)];
            win[i].z = init_conv[((size_t)b * CD + d + 2) * NCONV + (4 + ti)];
            win[i].w = init_conv[((size_t)b * CD + d + 3) * NCONV + (4 + ti)];
        }
    }
#pragma unroll
    for (int jt = 0; jt < 8; jt++) {
        float4 o;
        o.x = siluf(bias.x + cw[0].x*win[jt].x + cw[0].y*win[jt+1].x + cw[0].z*win[jt+2].x + cw[0].w*win[jt+3].x);
        o.y = siluf(bias.y + cw[1].x*win[jt].y + cw[1].y*win[jt+1].y + cw[1].z*win[jt+2].y + cw[1].w*win[jt+3].y);
        o.z = siluf(bias.z + cw[2].x*win[jt].z + cw[2].y*win[jt+1].z + cw[2].z*win[jt+2].z + cw[2].w*win[jt+3].z);
        o.w = siluf(bias.w + cw[3].x*win[jt].w + cw[3].y*win[jt+1].w + cw[3].z*win[jt+2].w + cw[3].w*win[jt+3].w);
        int row = b * L_ + t0 + jt;
        if (d < NI)           sth4(g_x + (size_t)row * NI + d, o);
        else if (d < NI + NS) *(float4*)(g_Bm + (size_t)row * NS + (d - NI)) = o;
        else                  *(float4*)(g_Cm + (size_t)row * NS + (d - NI - NS)) = o;
    }
}

// ---------------- new_conv_state output ----------------
__global__ void convstate_kernel(float* __restrict__ out) {
    int i = blockIdx.x * blockDim.x + threadIdx.x;
    if (i >= B_ * CD * NCONV) return;
    int k = i % NCONV;
    int d = (i / NCONV) % CD;
    int b = i / (NCONV * CD);
    out[i] = g_zx[(size_t)(b * L_ + (L_ - 4 + k)) * DIN + NI + d];
}

// ---------------- per-chunk Gram matrix G[l][s] = sum_n C[l,n]B[s,n] -------
__global__ void __launch_bounds__(256) gmat_kernel() {
    const int bc = blockIdx.x;
    const int b = bc / NC, c = bc % NC;
    const int row0 = b * L_ + c * CH;
    const int tid = threadIdx.x;
    __shared__ float sC[64 * 33];
    __shared__ float sB[64 * 33];
    const int l = tid >> 2;
    const int s0 = (tid & 3) * 16;
    float acc[16];
#pragma unroll
    for (int j = 0; j < 16; j++) acc[j] = 0.f;
    for (int n0 = 0; n0 < NS; n0 += 32) {
        for (int i = tid; i < 64 * 32; i += 256) {
            int r = i >> 5, nn = i & 31;
            sC[r * 33 + nn] = g_Cm[(size_t)(row0 + r) * NS + n0 + nn];
            sB[r * 33 + nn] = g_Bm[(size_t)(row0 + r) * NS + n0 + nn];
        }
        __syncthreads();
        for (int nn = 0; nn < 32; nn++) {
            float cv = sC[l * 33 + nn];
#pragma unroll
            for (int j = 0; j < 16; j++) acc[j] += cv * sB[(s0 + j) * 33 + nn];
        }
        __syncthreads();
    }
    float* Gp = g_G + (size_t)bc * (CH * CH);
#pragma unroll
    for (int j = 0; j < 16; j++) Gp[l * 64 + s0 + j] = acc[j];
}

// ------- per-chunk states[p][n] = sum_l B[l,n]*decay[l]*dt[l]*x[l,p] -------
#define STATES_SMEM ((64*68 + 64*132) * 4)
__global__ void __launch_bounds__(256) states_kernel(const float* __restrict__ A_log) {
    extern __shared__ float sm[];
    float* xs = sm;             // [64][68]
    float* sB = sm + 64 * 68;   // [64][132]
    __shared__ float sdt[64], w[64];
    __shared__ float asum_s;
    const int h = blockIdx.x, c = blockIdx.y, b = blockIdx.z;
    const int tid = threadIdx.x;
    const int row0 = b * L_ + c * CH;
    if (tid < 64) sdt[tid] = g_dt[(size_t)(row0 + tid) * NH + h];
    __syncthreads();
    if (tid == 0) {
        float A = -expf(A_log[h]);
        float s = 0.f;
        for (int l = 0; l < 64; l++) { s += A * sdt[l]; w[l] = s; }  // w = acs (temp)
        asum_s = s;
        g_asum[(b * NC + c) * NH + h] = s;
    }
    __syncthreads();
    float wv = (tid < 64) ? expf(asum_s - w[tid]) * sdt[tid] : 0.f;
    __syncthreads();
    if (tid < 64) w[tid] = wv;
    __syncthreads();

    for (int i = tid; i < 64 * 16; i += 256) {
        int l = i >> 4, q = i & 15;
        float4 v = ldh4(g_x + (size_t)(row0 + l) * NI + h * HD + q * 4);
        float wl = w[l];
        *(float4*)(xs + l * 68 + q * 4) = make_float4(v.x * wl, v.y * wl, v.z * wl, v.w * wl);
    }
    for (int i = tid; i < 64 * 32; i += 256) {
        int l = i >> 5, q = i & 31;
        *(float4*)(sB + l * 132 + q * 4) =
            *(const float4*)(g_Bm + (size_t)(row0 + l) * NS + q * 4);
    }
    __syncthreads();

    const int pg = tid >> 5;   // 8 p-groups of 8
    const int ng = tid & 31;   // 32 n-pairs (x2 halves)
    uint64_t acc2[4][4];
    const uint64_t z2 = pack2(0.f, 0.f);
#pragma unroll
    for (int i = 0; i < 4; i++)
#pragma unroll
        for (int j = 0; j < 4; j++) acc2[i][j] = z2;

    for (int l = 0; l < 64; l++) {
        const ulonglong2* xr = (const ulonglong2*)(xs + l * 68 + pg * 8);
        ulonglong2 xa = xr[0], xb = xr[1];
        float2 bA = *(const float2*)(sB + l * 132 + 2 * ng);
        float2 bB = *(const float2*)(sB + l * 132 + 64 + 2 * ng);
        uint64_t bb0 = pack2(bA.x, bA.x), bb1 = pack2(bA.y, bA.y);
        uint64_t bb2 = pack2(bB.x, bB.x), bb3 = pack2(bB.y, bB.y);
        uint64_t xv[4] = {xa.x, xa.y, xb.x, xb.y};
#pragma unroll
        for (int i = 0; i < 4; i++) {
            ffma2(acc2[i][0], xv[i], bb0);
            ffma2(acc2[i][1], xv[i], bb1);
            ffma2(acc2[i][2], xv[i], bb2);
            ffma2(acc2[i][3], xv[i], bb3);
        }
    }
    __half* outp = g_st + (size_t)((b * NC + c) * NH + h) * HD * NS;
#pragma unroll
    for (int i = 0; i < 4; i++) {
        float a0e, a0o, a1e, a1o, a2e, a2o, a3e, a3o;
        unpack2(acc2[i][0], a0e, a0o);
        unpack2(acc2[i][1], a1e, a1o);
        unpack2(acc2[i][2], a2e, a2o);
        unpack2(acc2[i][3], a3e, a3o);
        int pe = pg * 8 + i * 2, po = pe + 1;
        *(__half2*)(outp + (size_t)pe * NS + 2 * ng)      = __floats2half2_rn(a0e, a1e);
        *(__half2*)(outp + (size_t)pe * NS + 64 + 2 * ng) = __floats2half2_rn(a2e, a3e);
        *(__half2*)(outp + (size_t)po * NS + 2 * ng)      = __floats2half2_rn(a0o, a1o);
        *(__half2*)(outp + (size_t)po * NS + 64 + 2 * ng) = __floats2half2_rn(a2o, a3o);
    }
}

// ------- cross-chunk state scan (fp16 storage, fp32 accumulate, prefetch) ---
__global__ void __launch_bounds__(256) scan_kernel(const float* __restrict__ init_ssm,
                                                   float* __restrict__ final_out)
{
    const int seg = blockIdx.x;
    const int h = blockIdx.y, b = blockIdx.z;
    const int tid = threadIdx.x;
    const int e = seg * 1024 + tid * 4;
    const size_t base_bh = (size_t)(b * NH + h) * HD * NS;
    const size_t stride_c = (size_t)NH * HD * NS;
    __half* p0 = g_st + (size_t)(b * NC) * stride_c + (size_t)h * HD * NS + e;
    float4 S = *reinterpret_cast<const float4*>(init_ssm + base_bh + e);
    uint2 raw = *reinterpret_cast<uint2*>(p0);
    for (int c = 0; c < NC; c++) {
        uint2 nxt;
        if (c + 1 < NC)
            nxt = *reinterpret_cast<uint2*>(p0 + (size_t)(c + 1) * stride_c);
        float dec = expf(g_asum[(b * NC + c) * NH + h]);
        __half2 h0 = *reinterpret_cast<__half2*>(&raw.x);
        __half2 h1 = *reinterpret_cast<__half2*>(&raw.y);
        float2 f0 = __half22float2(h0);
        float2 f1 = __half22float2(h1);
        __half2 s0 = __floats2half2_rn(S.x, S.y);
        __half2 s1 = __floats2half2_rn(S.z, S.w);
        uint2 sr;
        sr.x = *reinterpret_cast<uint32_t*>(&s0);
        sr.y = *reinterpret_cast<uint32_t*>(&s1);
        *reinterpret_cast<uint2*>(p0 + (size_t)c * stride_c) = sr;
        S.x = dec * S.x + f0.x;
        S.y = dec * S.y + f0.y;
        S.z = dec * S.z + f1.x;
        S.w = dec * S.w + f1.y;
        raw = nxt;
    }
    *reinterpret_cast<float4*>(final_out + base_bh + e) = S;
}

// ---------------- Y = (G∘L)@xdt + exp(Acs)*(C @ Sprev^T) + x*D ------------
#define Y_SMEM ((128*68 + 64*132) * 4)
__global__ void __launch_bounds__(256) y_kernel(const float* __restrict__ A_log,
                                                const float* __restrict__ Dp)
{
    extern __shared__ float sm[];
    float* shA = sm;             // [128][68]
    float* sC  = sm + 128 * 68;  // [64][132]
    __shared__ float acs[64], sdt[64];
    const int h = blockIdx.x, c = blockIdx.y, b = blockIdx.z;
    const int tid = threadIdx.x;
    const int row0 = b * L_ + c * CH;
    if (tid < 64) sdt[tid] = g_dt[(size_t)(row0 + tid) * NH + h];
    __syncthreads();
    if (tid == 0) {
        float A = -expf(A_log[h]);
        float s = 0.f;
        for (int l = 0; l < 64; l++) { s += A * sdt[l]; acs[l] = s; }
    }
    __syncthreads();

    const __half* Sp = g_st + (size_t)((b * NC + c) * NH + h) * HD * NS;
    for (int i = tid; i < 64 * 32; i += 256) {
        int l = i >> 5, q = i & 31;
        *(float4*)(sC + l * 132 + q * 4) =
            *(const float4*)(g_Cm + (size_t)(row0 + l) * NS + q * 4);
    }
    for (int i = tid; i < 64 * 32; i += 256) {
        int p = i >> 5, q = i & 31;
        float4 v = ldh4(Sp + (size_t)p * NS + q * 4);
        shA[(q * 4 + 0) * 68 + p] = v.x;
        shA[(q * 4 + 1) * 68 + p] = v.y;
        shA[(q * 4 + 2) * 68 + p] = v.z;
        shA[(q * 4 + 3) * 68 + p] = v.w;
    }
    __syncthreads();

    const int l = tid >> 2;
    const int p0 = (tid & 3) * 16;
    uint64_t acc2[8];
    const uint64_t z2 = pack2(0.f, 0.f);
#pragma unroll
    for (int j = 0; j < 8; j++) acc2[j] = z2;

    // phase 1: Y_off[l][p] = sum_n C[l][n] * S^T[n][p]
    for (int nn = 0; nn < 128; nn++) {
        float cv = sC[l * 132 + nn];
        uint64_t cc = pack2(cv, cv);
        const ulonglong2* sr = (const ulonglong2*)(shA + nn * 68 + p0);
        ulonglong2 q0 = sr[0], q1 = sr[1], q2 = sr[2], q3 = sr[3];
        ffma2(acc2[0], cc, q0.x); ffma2(acc2[1], cc, q0.y);
        ffma2(acc2[2], cc, q1.x); ffma2(acc2[3], cc, q1.y);
        ffma2(acc2[4], cc, q2.x); ffma2(acc2[5], cc, q2.y);
        ffma2(acc2[6], cc, q3.x); ffma2(acc2[7], cc, q3.y);
    }
    {
        float eAl = expf(acs[l]);
        uint64_t ee = pack2(eAl, eAl);
#pragma unroll
        for (int j = 0; j < 8; j++) fmul2(acc2[j], ee);
    }
    __syncthreads();   // done reading shA as S^T

    // phase 2: build sM = G*exp(acs[r]-acs[s]) masked, sxdt = x*dt [s][p]
    const float* Gp = g_G + (size_t)(b * NC + c) * (CH * CH);
    for (int i = tid; i < 64 * 64; i += 256) {
        int r = i >> 6, s = i & 63;
        shA[r * 68 + s] = (s <= r) ? Gp[r * 64 + s] * expf(acs[r] - acs[s]) : 0.f;
    }
    float* sxdt = shA + 64 * 68;
    for (int i = tid; i < 64 * 16; i += 256) {
        int s = i >> 4, q = i & 15;
        float4 v = ldh4(g_x + (size_t)(row0 + s) * NI + h * HD + q * 4);
        float d = sdt[s];
        *(float4*)(sxdt + s * 68 + q * 4) = make_float4(v.x * d, v.y * d, v.z * d, v.w * d);
    }
    __syncthreads();

    for (int s = 0; s < 64; s++) {
        float gv = shA[l * 68 + s];
        uint64_t gg = pack2(gv, gv);
        const ulonglong2* xr = (const ulonglong2*)(sxdt + s * 68 + p0);
        ulonglong2 q0 = xr[0], q1 = xr[1], q2 = xr[2], q3 = xr[3];
        ffma2(acc2[0], gg, q0.x); ffma2(acc2[1], gg, q0.y);
        ffma2(acc2[2], gg, q1.x); ffma2(acc2[3], gg, q1.y);
        ffma2(acc2[4], gg, q2.x); ffma2(acc2[5], gg, q2.y);
        ffma2(acc2[6], gg, q3.x); ffma2(acc2[7], gg, q3.y);
    }

    float acc[16];
#pragma unroll
    for (int j = 0; j < 8; j++) unpack2(acc2[j], acc[2 * j], acc[2 * j + 1]);

    float Dv = Dp[h];
    __half* yrow = g_yin + (size_t)(row0 + l) * NI + h * HD + p0;
    const __half* xrow = g_x + (size_t)(row0 + l) * NI + h * HD + p0;
#pragma unroll
    for (int j4 = 0; j4 < 4; j4++) {
        float4 xv = ldh4(xrow + j4 * 4);
        float4 o = make_float4(acc[j4*4+0] + xv.x * Dv, acc[j4*4+1] + xv.y * Dv,
                               acc[j4*4+2] + xv.z * Dv, acc[j4*4+3] + xv.w * Dv);
        sth4(yrow + j4 * 4, o);
    }
}

// ------ gate with silu(z), RMSNorm, * norm_w; emit fp16 directly ------
__global__ void __launch_bounds__(256) gate_rms_kernel(const float* __restrict__ norm_w) {
    const int row = blockIdx.x;
    const int tid = threadIdx.x;
    const float* zrow = g_zx + (size_t)row * DIN;
    const __half* yrow = g_yin + (size_t)row * NI;
    float v[8];
    float ss = 0.f;
#pragma unroll
    for (int i = 0; i < 8; i++) {
        int idx = tid + i * 256;
        float z = zrow[idx];
        float val = __half2float(yrow[idx]) * siluf(z);
        v[i] = val;
        ss += val * val;
    }
    __shared__ float red[256];
    red[tid] = ss;
    __syncthreads();
    for (int s = 128; s > 0; s >>= 1) {
        if (tid < s) red[tid] += red[tid + s];
        __syncthreads();
    }
    float scale = rsqrtf(red[0] / (float)NI + 1e-5f);
#pragma unroll
    for (int i = 0; i < 8; i++) {
        int idx = tid + i * 256;
        float o = v[i] * scale * norm_w[idx];
        g_ynb[(size_t)row * NI + idx] = __float2half_rn(o);
    }
}

// ---------------- launch ----------------
template <typename T>
static T* symaddr(const void* sym) {
    void* p = nullptr;
    cudaGetSymbolAddress(&p, sym);
    return (T*)p;
}

extern "C" void kernel_launch(void* const* d_in, const int* in_sizes, int n_in,
                              void* d_out, int out_size)
{
    const float* u         = (const float*)d_in[0];
    const float* init_conv = (const float*)d_in[1];
    const float* init_ssm  = (const float*)d_in[2];
    const float* w_in      = (const float*)d_in[3];
    const float* conv_w    = (const float*)d_in[4];
    const float* conv_b    = (const float*)d_in[5];
    const float* dt_bias   = (const float*)d_in[6];
    const float* A_log     = (const float*)d_in[7];
    const float* Dp        = (const float*)d_in[8];
    const float* norm_w    = (const float*)d_in[9];
    const float* w_out     = (const float*)d_in[10];

    float* out       = (float*)d_out;
    float* out_y     = out;
    float* out_conv  = out + (size_t)ROWS * E_;
    float* out_final = out_conv + (size_t)B_ * CD * NCONV;

    float* pzx = symaddr<float>(g_zx);
    __half* p_u_h     = symaddr<__half>(g_u_h);
    __half* p_win_hi  = symaddr<__half>(g_win_hi);
    __half* p_win_lo  = symaddr<__half>(g_win_lo);
    __half* p_wout_hi = symaddr<__half>(g_wout_hi);
    __half* p_wout_lo = symaddr<__half>(g_wout_lo);
    __half* p_ynb     = symaddr<__half>(g_ynb);

    cudaFuncSetAttribute(gemm_f16, cudaFuncAttributeMaxDynamicSharedMemorySize, GM_SMEM);
    cudaFuncSetAttribute(states_kernel, cudaFuncAttributeMaxDynamicSharedMemorySize, STATES_SMEM);
    cudaFuncSetAttribute(y_kernel, cudaFuncAttributeMaxDynamicSharedMemorySize, Y_SMEM);

    // 0) operand conversions to fp16 (A single, B hi/lo)
    cvt_f16_kernel<<<(ROWS * E_ / 4 + 511) / 512, 512>>>(u, p_u_h, ROWS * E_);
    cvt_win16_kernel<<<(E_ * NPAD / 4 + 511) / 512, 512>>>(w_in);
    cvt_hilo16_kernel<<<(NI * E_ / 4 + 511) / 512, 512>>>(w_out, p_wout_hi, p_wout_lo, NI * E_);

    // 1) in-projection
    gemm_f16<<<dim3(NPAD / 128, ROWS / 256), 512, GM_SMEM>>>(
        p_u_h, p_win_hi, p_win_lo, pzx, ROWS, DIN, E_, NPAD);
    // 2) dt
    dt_kernel<<<(ROWS * NH + 255) / 256, 256>>>(dt_bias);
    // 3) conv + silu + split (4 channels x 8 timesteps per thread)
    conv_kernel<<<dim3((CD / 4 + 255) / 256, L_ / 8, B_), 256>>>(init_conv, conv_w, conv_b);
    // 4) new_conv_state output
    convstate_kernel<<<(B_ * CD * NCONV + 255) / 256, 256>>>(out_conv);
    // 5) per-chunk Gram matrix
    gmat_kernel<<<B_ * NC, 256>>>();
    // 6) per-chunk states (fp16 output)
    states_kernel<<<dim3(NH, NC, B_), 256, STATES_SMEM>>>(A_log);
    // 7) cross-chunk scan (fp16 storage, prefetch)
    scan_kernel<<<dim3(8, NH, B_), 256>>>(init_ssm, out_final);
    // 8) Y (fp16 x/yin)
    y_kernel<<<dim3(NH, NC, B_), 256, Y_SMEM>>>(A_log, Dp);
    // 9) gate + rmsnorm (emits fp16)
    gate_rms_kernel<<<ROWS, 256>>>(norm_w);
    // 10) out-projection
    gemm_f16<<<dim3(E_ / 128, ROWS / 256), 512, GM_SMEM>>>(
        p_ynb, p_wout_hi, p_wout_lo, out_y, ROWS, E_, NI, E_);
}

// round 15
// speedup vs baseline: 2.0415x; 1.5665x over previous
#include <cuda_runtime.h>
#include <cuda_bf16.h>
#include <cuda_fp16.h>
#include <math.h>
#include <stdint.h>

// Problem constants
#define B_    2
#define L_    4096
#define E_    1024
#define NI    2048      // N_INNER
#define NS    128       // N_STATE
#define NH    32        // N_HEAD
#define HD    64        // HEADDIM
#define NCONV 4
#define CH    64        // CHUNK
#define NC    64        // chunks per sequence (L/CHUNK)
#define CD    2304      // CONV_DIM = NI + 2*NS
#define DIN   4384      // 2*NI + 2*NS + NH
#define NPAD  4480      // DIN padded to multiple of 128
#define ROWS  (B_*L_)   // 8192

// ---------------- scratch (device globals; no allocation allowed) ----------
__device__ float g_zx[(size_t)ROWS * DIN];
__device__ __half g_x [(size_t)ROWS * NI];                // fp16 conv output (x part)
__device__ float g_Bm[(size_t)ROWS * NS];
__device__ float g_Cm[(size_t)ROWS * NS];
__device__ float g_dt[(size_t)ROWS * NH];
__device__ float g_G [(size_t)B_ * NC * CH * CH];
__device__ __half g_st[(size_t)B_ * NC * NH * HD * NS];   // fp16 chunk/prev states
__device__ float g_asum[B_ * NC * NH];
__device__ __half g_yin[(size_t)ROWS * NI];               // fp16 pre-gate y

// fp16 operand copies for tensor-core GEMMs (A single, B hi/lo split)
__device__ __half g_u_h [(size_t)ROWS * E_];
__device__ __half g_win_hi[(size_t)E_ * NPAD];
__device__ __half g_win_lo[(size_t)E_ * NPAD];
__device__ __half g_wout_hi[(size_t)NI * E_];
__device__ __half g_wout_lo[(size_t)NI * E_];
__device__ __half g_ynb[(size_t)ROWS * NI];

// ---------------- small helpers ----------------
__device__ __forceinline__ float siluf(float x) { return x / (1.f + expf(-x)); }
__device__ __forceinline__ float softplusf(float x) {
    return (x > 20.f) ? x : log1pf(expf(x));
}
__device__ __forceinline__ uint32_t smem_u32(const void* p) {
    uint32_t a;
    asm("{ .reg .u64 t; cvta.to.shared.u64 t, %1; cvt.u32.u64 %0, t; }" : "=r"(a) : "l"(p));
    return a;
}
// load 4 halves (8B) -> 4 floats
__device__ __forceinline__ float4 ldh4(const __half* p) {
    uint2 raw = *reinterpret_cast<const uint2*>(p);
    __half2 h0 = *reinterpret_cast<__half2*>(&raw.x);
    __half2 h1 = *reinterpret_cast<__half2*>(&raw.y);
    float2 f0 = __half22float2(h0);
    float2 f1 = __half22float2(h1);
    return make_float4(f0.x, f0.y, f1.x, f1.y);
}
// store 4 floats as 4 halves (8B)
__device__ __forceinline__ void sth4(__half* p, float4 v) {
    __half2 h0 = __floats2half2_rn(v.x, v.y);
    __half2 h1 = __floats2half2_rn(v.z, v.w);
    uint2 raw;
    raw.x = *reinterpret_cast<uint32_t*>(&h0);
    raw.y = *reinterpret_cast<uint32_t*>(&h1);
    *reinterpret_cast<uint2*>(p) = raw;
}

// ---------------- packed f32x2 (Blackwell, base sm_100) ----------------
__device__ __forceinline__ uint64_t pack2(float x, float y) {
    uint64_t r;
    asm("mov.b64 %0, {%1, %2};" : "=l"(r) : "f"(x), "f"(y));
    return r;
}
__device__ __forceinline__ void unpack2(uint64_t v, float& x, float& y) {
    asm("mov.b64 {%0, %1}, %2;" : "=f"(x), "=f"(y) : "l"(v));
}
__device__ __forceinline__ void ffma2(uint64_t& d, uint64_t a, uint64_t b) {
    asm("fma.rn.f32x2 %0, %1, %2, %0;" : "+l"(d) : "l"(a), "l"(b));
}
__device__ __forceinline__ void fmul2(uint64_t& d, uint64_t a) {
    asm("mul.rn.f32x2 %0, %0, %1;" : "+l"(d) : "l"(a));
}

// ---------------- warp-MMA primitives (sm_80+, valid on base sm_100) -------
__device__ __forceinline__ void ldm_x4(uint32_t* r, uint32_t addr) {
    asm volatile("ldmatrix.sync.aligned.m8n8.x4.shared.b16 {%0,%1,%2,%3}, [%4];"
        : "=r"(r[0]), "=r"(r[1]), "=r"(r[2]), "=r"(r[3]) : "r"(addr));
}
__device__ __forceinline__ void ldm_x2t(uint32_t* r, uint32_t addr) {
    asm volatile("ldmatrix.sync.aligned.m8n8.x2.trans.shared.b16 {%0,%1}, [%2];"
        : "=r"(r[0]), "=r"(r[1]) : "r"(addr));
}
__device__ __forceinline__ void mma_f16(float* c, const uint32_t* a, const uint32_t* b) {
    asm volatile(
        "mma.sync.aligned.m16n8k16.row.col.f32.f16.f16.f32 "
        "{%0,%1,%2,%3}, {%4,%5,%6,%7}, {%8,%9}, {%0,%1,%2,%3};"
        : "+f"(c[0]), "+f"(c[1]), "+f"(c[2]), "+f"(c[3])
        : "r"(a[0]), "r"(a[1]), "r"(a[2]), "r"(a[3]), "r"(b[0]), "r"(b[1]));
}
__device__ __forceinline__ void cp16(uint32_t dst, const void* src) {
    asm volatile("cp.async.cg.shared.global [%0], [%1], 16;" :: "r"(dst), "l"(src));
}
#define CP_COMMIT() asm volatile("cp.async.commit_group;" ::: "memory")
#define CP_WAIT(n)  asm volatile("cp.async.wait_group %0;" :: "n"(n) : "memory")

// ---------------- fp32 -> fp16 conversion kernels ----------------
__global__ void cvt_f16_kernel(const float* __restrict__ s, __half* __restrict__ dst, int n) {
    int i = (blockIdx.x * blockDim.x + threadIdx.x) * 4;
    if (i >= n) return;
    float4 v = *(const float4*)(s + i);
    sth4(dst + i, v);
}

__global__ void cvt_hilo16_kernel(const float* __restrict__ s,
                                  __half* __restrict__ hi, __half* __restrict__ lo, int n)
{
    int i = (blockIdx.x * blockDim.x + threadIdx.x) * 4;
    if (i >= n) return;
    float4 v = *(const float4*)(s + i);
    float f[4] = {v.x, v.y, v.z, v.w};
    float fh[4], fl[4];
#pragma unroll
    for (int j = 0; j < 4; j++) {
        __half h = __float2half_rn(f[j]);
        fh[j] = __half2float(h);
        fl[j] = f[j] - fh[j];
    }
    sth4(hi + i, make_float4(fh[0], fh[1], fh[2], fh[3]));
    sth4(lo + i, make_float4(fl[0], fl[1], fl[2], fl[3]));
}

// w_in [E_][DIN] -> padded [E_][NPAD] fp16 hi/lo (zero-fill cols >= DIN)
__global__ void cvt_win16_kernel(const float* __restrict__ w) {
    int i4 = (blockIdx.x * blockDim.x + threadIdx.x) * 4;
    if (i4 >= E_ * NPAD) return;
    int row = i4 / NPAD, col = i4 % NPAD;
    float f[4];
    if (col + 3 < DIN) {
        float4 v = *(const float4*)(w + (size_t)row * DIN + col);
        f[0] = v.x; f[1] = v.y; f[2] = v.z; f[3] = v.w;
    } else {
#pragma unroll
        for (int j = 0; j < 4; j++) {
            int cc = col + j;
            f[j] = (cc < DIN) ? w[(size_t)row * DIN + cc] : 0.f;
        }
    }
    float fh[4], fl[4];
#pragma unroll
    for (int j = 0; j < 4; j++) {
        __half h = __float2half_rn(f[j]);
        fh[j] = __half2float(h);
        fl[j] = f[j] - fh[j];
    }
    sth4(g_win_hi + i4, make_float4(fh[0], fh[1], fh[2], fh[3]));
    sth4(g_win_lo + i4, make_float4(fl[0], fl[1], fl[2], fl[3]));
}

// ================= tensor-core GEMM: C[M,N] = A[M,K] @ B[K,N] ==============
// fp16 asymmetric split: A single fp16, B fp16 hi+lo; C = A*(Bhi+Blo), fp32 acc.
#define ST_B_HI 20480
#define ST_B_LO 29184
#define ST_BYTES 37888
#define STG 4
#define GM_SMEM (STG * ST_BYTES)

__global__ void __launch_bounds__(512, 1) gemm_f16(
    const __half* __restrict__ A,
    const __half* __restrict__ Bh, const __half* __restrict__ Bl,
    float* __restrict__ C, int M, int N, int K, int ldB)
{
    extern __shared__ char smem[];
    const uint32_t sb = smem_u32(smem);
    const int tid = threadIdx.x;
    const int wid = tid >> 5, lane = tid & 31;
    const int m0 = blockIdx.y * 256;
    const int n0 = blockIdx.x * 128;
    const int warp_m = wid >> 2;
    const int warp_n = wid & 3;

    float acc[4][4][4];
#pragma unroll
    for (int i = 0; i < 4; i++)
#pragma unroll
        for (int j = 0; j < 4; j++)
#pragma unroll
            for (int k = 0; k < 4; k++) acc[i][j][k] = 0.f;

    const int KTn = K >> 5;

    const int arow0 = tid >> 2, ach0 = tid & 3;
    const int arow1 = (tid + 512) >> 2, ach1 = tid & 3;
    const int bkr = tid >> 4, bch = tid & 15;

#define LOAD_STAGE(KT_) do { \
    const int k0_ = (KT_) << 5; \
    const uint32_t st_ = sb + ((KT_) % STG) * ST_BYTES; \
    { size_t go = (size_t)(m0 + arow0) * K + k0_ + ach0 * 8; \
      cp16(st_ + arow0 * 80 + ach0 * 16, A + go); } \
    { size_t go = (size_t)(m0 + arow1) * K + k0_ + ach1 * 8; \
      cp16(st_ + arow1 * 80 + ach1 * 16, A + go); } \
    { size_t go = (size_t)(k0_ + bkr) * ldB + n0 + bch * 8; \
      uint32_t so = st_ + ST_B_HI + bkr * 272 + bch * 16; \
      cp16(so, Bh + go); cp16(so + 8704, Bl + go); } \
} while (0)

#pragma unroll
    for (int s = 0; s < STG - 1; s++) {
        if (s < KTn) LOAD_STAGE(s);
        CP_COMMIT();
    }

    for (int kt = 0; kt < KTn; kt++) {
        CP_WAIT(STG - 2);
        __syncthreads();
        const uint32_t sA   = sb + (kt % STG) * ST_BYTES;
        const uint32_t sBhi = sA + ST_B_HI;
        const uint32_t sBlo = sA + ST_B_LO;
#pragma unroll
        for (int ks = 0; ks < 2; ks++) {
            uint32_t a[4][4], b_hi[4][2], b_lo[4][2];
#pragma unroll
            for (int mi = 0; mi < 4; mi++) {
                int row = warp_m * 64 + mi * 16 + (lane & 15);
                uint32_t addr = row * 80 + ks * 32 + (lane >> 4) * 16;
                ldm_x4(a[mi], sA + addr);
            }
#pragma unroll
            for (int ni = 0; ni < 4; ni++) {
                int krow = ks * 16 + (lane & 15);
                int ncol = warp_n * 32 + ni * 8;
                uint32_t addr = krow * 272 + ncol * 2;
                ldm_x2t(b_hi[ni], sBhi + addr);
                ldm_x2t(b_lo[ni], sBlo + addr);
            }
#pragma unroll
            for (int mi = 0; mi < 4; mi++)
#pragma unroll
                for (int ni = 0; ni < 4; ni++) {
                    mma_f16(acc[mi][ni], a[mi], b_hi[ni]);
                    mma_f16(acc[mi][ni], a[mi], b_lo[ni]);
                }
        }
        if (kt + STG - 1 < KTn) LOAD_STAGE(kt + STG - 1);
        CP_COMMIT();
    }
#undef LOAD_STAGE

#pragma unroll
    for (int mi = 0; mi < 4; mi++) {
        int row = m0 + warp_m * 64 + mi * 16 + (lane >> 2);
#pragma unroll
        for (int ni = 0; ni < 4; ni++) {
            int col = n0 + warp_n * 32 + ni * 8 + (lane & 3) * 2;
            if (col < N) {
                *(float2*)(C + (size_t)row * N + col) =
                    make_float2(acc[mi][ni][0], acc[mi][ni][1]);
                *(float2*)(C + (size_t)(row + 8) * N + col) =
                    make_float2(acc[mi][ni][2], acc[mi][ni][3]);
            }
        }
    }
}

// ---------------- dt = softplus(raw + bias) ----------------
__global__ void dt_kernel(const float* __restrict__ dt_bias) {
    int i = blockIdx.x * blockDim.x + threadIdx.x;
    if (i >= ROWS * NH) return;
    int row = i / NH, h = i % NH;
    float x = g_zx[(size_t)row * DIN + (DIN - NH) + h] + dt_bias[h];
    g_dt[i] = softplusf(x);
}

// --- depthwise causal conv w4 + silu + split; 4 channels x 8 timesteps ----
__global__ void conv_kernel(const float* __restrict__ init_conv,
                            const float* __restrict__ conv_w,
                            const float* __restrict__ conv_b)
{
    int d4 = blockIdx.x * blockDim.x + threadIdx.x;
    if (d4 >= CD / 4) return;
    const int d = d4 * 4;
    const int t0 = blockIdx.y * 8;
    const int b = blockIdx.z;
    float4 cw[4];
#pragma unroll
    for (int j = 0; j < 4; j++) cw[j] = *(const float4*)(conv_w + (d + j) * 4);
    float4 bias = *(const float4*)(conv_b + d);
    float4 win[11];
#pragma unroll
    for (int i = 0; i < 11; i++) {
        int ti = t0 - 3 + i;
        if (ti >= 0) {
            win[i] = *(const float4*)(g_zx + (size_t)(b * L_ + ti) * DIN + NI + d);
        } else {
            win[i].x = init_conv[((size_t)b * CD + d + 0) * NCONV + (4 + ti)];
            win[i].y = init_conv[((size_t)b * CD + d + 1) * NCONV + (4 + ti)];
            win[i].z = init_conv[((size_t)b * CD + d + 2) * NCONV + (4 + ti)];
            win[i].w = init_conv[((size_t)b * CD + d + 3) * NCONV + (4 + ti)];
        }
    }
#pragma unroll
    for (int jt = 0; jt < 8; jt++) {
        float4 o;
        o.x = siluf(bias.x + cw[0].x*win[jt].x + cw[0].y*win[jt+1].x + cw[0].z*win[jt+2].x + cw[0].w*win[jt+3].x);
        o.y = siluf(bias.y + cw[1].x*win[jt].y + cw[1].y*win[jt+1].y + cw[1].z*win[jt+2].y + cw[1].w*win[jt+3].y);
        o.z = siluf(bias.z + cw[2].x*win[jt].z + cw[2].y*win[jt+1].z + cw[2].z*win[jt+2].z + cw[2].w*win[jt+3].z);
        o.w = siluf(bias.w + cw[3].x*win[jt].w + cw[3].y*win[jt+1].w + cw[3].z*win[jt+2].w + cw[3].w*win[jt+3].w);
        int row = b * L_ + t0 + jt;
        if (d < NI)           sth4(g_x + (size_t)row * NI + d, o);
        else if (d < NI + NS) *(float4*)(g_Bm + (size_t)row * NS + (d - NI)) = o;
        else                  *(float4*)(g_Cm + (size_t)row * NS + (d - NI - NS)) = o;
    }
}

// ---------------- new_conv_state output ----------------
__global__ void convstate_kernel(float* __restrict__ out) {
    int i = blockIdx.x * blockDim.x + threadIdx.x;
    if (i >= B_ * CD * NCONV) return;
    int k = i % NCONV;
    int d = (i / NCONV) % CD;
    int b = i / (NCONV * CD);
    out[i] = g_zx[(size_t)(b * L_ + (L_ - 4 + k)) * DIN + NI + d];
}

// ---------------- per-chunk Gram matrix G[l][s] = sum_n C[l,n]B[s,n] -------
__global__ void __launch_bounds__(256) gmat_kernel() {
    const int bc = blockIdx.x;
    const int b = bc / NC, c = bc % NC;
    const int row0 = b * L_ + c * CH;
    const int tid = threadIdx.x;
    __shared__ float sC[64 * 33];
    __shared__ float sB[64 * 33];
    const int l = tid >> 2;
    const int s0 = (tid & 3) * 16;
    float acc[16];
#pragma unroll
    for (int j = 0; j < 16; j++) acc[j] = 0.f;
    for (int n0 = 0; n0 < NS; n0 += 32) {
        for (int i = tid; i < 64 * 32; i += 256) {
            int r = i >> 5, nn = i & 31;
            sC[r * 33 + nn] = g_Cm[(size_t)(row0 + r) * NS + n0 + nn];
            sB[r * 33 + nn] = g_Bm[(size_t)(row0 + r) * NS + n0 + nn];
        }
        __syncthreads();
        for (int nn = 0; nn < 32; nn++) {
            float cv = sC[l * 33 + nn];
#pragma unroll
            for (int j = 0; j < 16; j++) acc[j] += cv * sB[(s0 + j) * 33 + nn];
        }
        __syncthreads();
    }
    float* Gp = g_G + (size_t)bc * (CH * CH);
#pragma unroll
    for (int j = 0; j < 16; j++) Gp[l * 64 + s0 + j] = acc[j];
}

// ------- per-chunk states[p][n] = sum_l B[l,n]*decay[l]*dt[l]*x[l,p] -------
#define STATES_SMEM ((64*68 + 64*132) * 4)
__global__ void __launch_bounds__(256) states_kernel(const float* __restrict__ A_log) {
    extern __shared__ float sm[];
    float* xs = sm;             // [64][68]
    float* sB = sm + 64 * 68;   // [64][132]
    __shared__ float sdt[64], w[64];
    __shared__ float asum_s;
    const int h = blockIdx.x, c = blockIdx.y, b = blockIdx.z;
    const int tid = threadIdx.x;
    const int row0 = b * L_ + c * CH;
    if (tid < 64) sdt[tid] = g_dt[(size_t)(row0 + tid) * NH + h];
    __syncthreads();
    if (tid == 0) {
        float A = -expf(A_log[h]);
        float s = 0.f;
        for (int l = 0; l < 64; l++) { s += A * sdt[l]; w[l] = s; }  // w = acs (temp)
        asum_s = s;
        g_asum[(b * NC + c) * NH + h] = s;
    }
    __syncthreads();
    float wv = (tid < 64) ? expf(asum_s - w[tid]) * sdt[tid] : 0.f;
    __syncthreads();
    if (tid < 64) w[tid] = wv;
    __syncthreads();

    for (int i = tid; i < 64 * 16; i += 256) {
        int l = i >> 4, q = i & 15;
        float4 v = ldh4(g_x + (size_t)(row0 + l) * NI + h * HD + q * 4);
        float wl = w[l];
        *(float4*)(xs + l * 68 + q * 4) = make_float4(v.x * wl, v.y * wl, v.z * wl, v.w * wl);
    }
    for (int i = tid; i < 64 * 32; i += 256) {
        int l = i >> 5, q = i & 31;
        *(float4*)(sB + l * 132 + q * 4) =
            *(const float4*)(g_Bm + (size_t)(row0 + l) * NS + q * 4);
    }
    __syncthreads();

    const int pg = tid >> 5;   // 8 p-groups of 8
    const int ng = tid & 31;   // 32 n-pairs (x2 halves)
    uint64_t acc2[4][4];
    const uint64_t z2 = pack2(0.f, 0.f);
#pragma unroll
    for (int i = 0; i < 4; i++)
#pragma unroll
        for (int j = 0; j < 4; j++) acc2[i][j] = z2;

    for (int l = 0; l < 64; l++) {
        const ulonglong2* xr = (const ulonglong2*)(xs + l * 68 + pg * 8);
        ulonglong2 xa = xr[0], xb = xr[1];
        float2 bA = *(const float2*)(sB + l * 132 + 2 * ng);
        float2 bB = *(const float2*)(sB + l * 132 + 64 + 2 * ng);
        uint64_t bb0 = pack2(bA.x, bA.x), bb1 = pack2(bA.y, bA.y);
        uint64_t bb2 = pack2(bB.x, bB.x), bb3 = pack2(bB.y, bB.y);
        uint64_t xv[4] = {xa.x, xa.y, xb.x, xb.y};
#pragma unroll
        for (int i = 0; i < 4; i++) {
            ffma2(acc2[i][0], xv[i], bb0);
            ffma2(acc2[i][1], xv[i], bb1);
            ffma2(acc2[i][2], xv[i], bb2);
            ffma2(acc2[i][3], xv[i], bb3);
        }
    }
    __half* outp = g_st + (size_t)((b * NC + c) * NH + h) * HD * NS;
#pragma unroll
    for (int i = 0; i < 4; i++) {
        float a0e, a0o, a1e, a1o, a2e, a2o, a3e, a3o;
        unpack2(acc2[i][0], a0e, a0o);
        unpack2(acc2[i][1], a1e, a1o);
        unpack2(acc2[i][2], a2e, a2o);
        unpack2(acc2[i][3], a3e, a3o);
        int pe = pg * 8 + i * 2, po = pe + 1;
        *(__half2*)(outp + (size_t)pe * NS + 2 * ng)      = __floats2half2_rn(a0e, a1e);
        *(__half2*)(outp + (size_t)pe * NS + 64 + 2 * ng) = __floats2half2_rn(a2e, a3e);
        *(__half2*)(outp + (size_t)po * NS + 2 * ng)      = __floats2half2_rn(a0o, a1o);
        *(__half2*)(outp + (size_t)po * NS + 64 + 2 * ng) = __floats2half2_rn(a2o, a3o);
    }
}

// ------- cross-chunk state scan (fp16 storage, fp32 accumulate, prefetch) ---
__global__ void __launch_bounds__(256) scan_kernel(const float* __restrict__ init_ssm,
                                                   float* __restrict__ final_out)
{
    const int seg = blockIdx.x;
    const int h = blockIdx.y, b = blockIdx.z;
    const int tid = threadIdx.x;
    const int e = seg * 1024 + tid * 4;
    const size_t base_bh = (size_t)(b * NH + h) * HD * NS;
    const size_t stride_c = (size_t)NH * HD * NS;
    __half* p0 = g_st + (size_t)(b * NC) * stride_c + (size_t)h * HD * NS + e;
    float4 S = *reinterpret_cast<const float4*>(init_ssm + base_bh + e);
    uint2 raw = *reinterpret_cast<uint2*>(p0);
    for (int c = 0; c < NC; c++) {
        uint2 nxt;
        if (c + 1 < NC)
            nxt = *reinterpret_cast<uint2*>(p0 + (size_t)(c + 1) * stride_c);
        float dec = expf(g_asum[(b * NC + c) * NH + h]);
        __half2 h0 = *reinterpret_cast<__half2*>(&raw.x);
        __half2 h1 = *reinterpret_cast<__half2*>(&raw.y);
        float2 f0 = __half22float2(h0);
        float2 f1 = __half22float2(h1);
        __half2 s0 = __floats2half2_rn(S.x, S.y);
        __half2 s1 = __floats2half2_rn(S.z, S.w);
        uint2 sr;
        sr.x = *reinterpret_cast<uint32_t*>(&s0);
        sr.y = *reinterpret_cast<uint32_t*>(&s1);
        *reinterpret_cast<uint2*>(p0 + (size_t)c * stride_c) = sr;
        S.x = dec * S.x + f0.x;
        S.y = dec * S.y + f0.y;
        S.z = dec * S.z + f1.x;
        S.w = dec * S.w + f1.y;
        raw = nxt;
    }
    *reinterpret_cast<float4*>(final_out + base_bh + e) = S;
}

// ====== Y = exp(Acs)*(C @ Sprev^T) + (G∘L)@xdt + x*D — tensor-core ========
// Phase1: A = C fp16 hi/lo [64][136]h, B = Sprev^T fp16 [128][72]h (trans-load)
// Phase2: A = M hi/lo [64][72]h, B = xdt hi/lo [64][72]h (exact fp16 pairs)
// 8 warps: 2(m: 32 rows) x 4(n: 16 cols); per warp mi 0..1, ni 0..1.
#define Y_CH 0
#define Y_CL 17408
#define Y_ST 34816
#define Y_SMEM (34816 + 18432)     // 53248 B
// phase2 reuse offsets (within same buffer)
#define Y_MH 0
#define Y_ML 9216
#define Y_XH 18432
#define Y_XL 27648
__global__ void __launch_bounds__(256) y_kernel(const float* __restrict__ A_log,
                                                const float* __restrict__ Dp)
{
    extern __shared__ char ysm[];
    const uint32_t sb = smem_u32(ysm);
    __half* smh = (__half*)ysm;
    __shared__ float acs[64], sdt[64];
    const int h = blockIdx.x, c = blockIdx.y, b = blockIdx.z;
    const int tid = threadIdx.x;
    const int wid = tid >> 5, lane = tid & 31;
    const int warp_m = wid >> 2;       // 0..1 -> rows warp_m*32
    const int warp_n = wid & 3;        // 0..3 -> cols warp_n*16
    const int row0 = b * L_ + c * CH;

    if (tid < 64) sdt[tid] = g_dt[(size_t)(row0 + tid) * NH + h];
    __syncthreads();
    if (tid == 0) {
        float A = -expf(A_log[h]);
        float s = 0.f;
        for (int l = 0; l < 64; l++) { s += A * sdt[l]; acs[l] = s; }
    }
    __syncthreads();

    // ---- phase-1 prep: C -> fp16 hi/lo [l][136]; Sp^T -> fp16 [n][72]
    for (int i = tid; i < 64 * 32; i += 256) {
        int l = i >> 5, q = i & 31;
        float4 v = *(const float4*)(g_Cm + (size_t)(row0 + l) * NS + q * 4);
        float f[4] = {v.x, v.y, v.z, v.w};
        __half* ph = smh + Y_CH / 2 + l * 136 + q * 4;
        __half* pl = smh + Y_CL / 2 + l * 136 + q * 4;
#pragma unroll
        for (int j = 0; j < 4; j++) {
            __half hh = __float2half_rn(f[j]);
            ph[j] = hh;
            pl[j] = __float2half_rn(f[j] - __half2float(hh));
        }
    }
    const __half* Sp = g_st + (size_t)((b * NC + c) * NH + h) * HD * NS;
    for (int i = tid; i < 64 * 32; i += 256) {
        int p = i >> 5, q = i & 31;
        uint2 raw = *reinterpret_cast<const uint2*>(Sp + (size_t)p * NS + q * 4);
        __half2 h0 = *reinterpret_cast<__half2*>(&raw.x);
        __half2 h1 = *reinterpret_cast<__half2*>(&raw.y);
        __half* st = smh + Y_ST / 2;
        st[(q * 4 + 0) * 72 + p] = __low2half(h0);
        st[(q * 4 + 1) * 72 + p] = __high2half(h0);
        st[(q * 4 + 2) * 72 + p] = __low2half(h1);
        st[(q * 4 + 3) * 72 + p] = __high2half(h1);
    }
    __syncthreads();

    float acc[2][2][4];
#pragma unroll
    for (int i = 0; i < 2; i++)
#pragma unroll
        for (int j = 0; j < 2; j++)
#pragma unroll
            for (int k = 0; k < 4; k++) acc[i][j][k] = 0.f;

    // ---- phase 1: Y_off = (Chi+Clo) @ S^T   (k = n_state, 8 k16 steps)
#pragma unroll
    for (int kk = 0; kk < 8; kk++) {
        uint32_t ah[2][4], al[2][4], bb[2][2];
#pragma unroll
        for (int mi = 0; mi < 2; mi++) {
            int row = warp_m * 32 + mi * 16 + (lane & 15);
            uint32_t ad = row * 272 + kk * 32 + (lane >> 4) * 16;
            ldm_x4(ah[mi], sb + Y_CH + ad);
            ldm_x4(al[mi], sb + Y_CL + ad);
        }
#pragma unroll
        for (int ni = 0; ni < 2; ni++) {
            int pc = warp_n * 16 + ni * 8;
            uint32_t bd = (uint32_t)(kk * 16 + (lane & 15)) * 144 + pc * 2;
            ldm_x2t(bb[ni], sb + Y_ST + bd);
        }
#pragma unroll
        for (int mi = 0; mi < 2; mi++)
#pragma unroll
            for (int ni = 0; ni < 2; ni++) {
                mma_f16(acc[mi][ni], ah[mi], bb[ni]);
                mma_f16(acc[mi][ni], al[mi], bb[ni]);
            }
    }
    // scale Y_off by exp(acs[row])
#pragma unroll
    for (int mi = 0; mi < 2; mi++) {
        int r0 = warp_m * 32 + mi * 16 + (lane >> 2);
        float e0 = expf(acs[r0]);
        float e1 = expf(acs[r0 + 8]);
#pragma unroll
        for (int ni = 0; ni < 2; ni++) {
            acc[mi][ni][0] *= e0; acc[mi][ni][1] *= e0;
            acc[mi][ni][2] *= e1; acc[mi][ni][3] *= e1;
        }
    }
    __syncthreads();   // done with phase-1 smem

    // ---- phase-2 prep: M = masked G*exp hi/lo [l][72]; xdt hi/lo [s][72]
    const float* Gp = g_G + (size_t)(b * NC + c) * (CH * CH);
    for (int i = tid; i < 64 * 64; i += 256) {
        int r = i >> 6, s = i & 63;
        float val = (s <= r) ? Gp[r * 64 + s] * expf(acs[r] - acs[s]) : 0.f;
        __half hh = __float2half_rn(val);
        smh[Y_MH / 2 + r * 72 + s] = hh;
        smh[Y_ML / 2 + r * 72 + s] = __float2half_rn(val - __half2float(hh));
    }
    for (int i = tid; i < 64 * 16; i += 256) {
        int s = i >> 4, q = i & 15;
        float4 v = ldh4(g_x + (size_t)(row0 + s) * NI + h * HD + q * 4);
        float d = sdt[s];
        float f[4] = {v.x * d, v.y * d, v.z * d, v.w * d};
        __half* ph = smh + Y_XH / 2 + s * 72 + q * 4;
        __half* pl = smh + Y_XL / 2 + s * 72 + q * 4;
#pragma unroll
        for (int j = 0; j < 4; j++) {
            __half hh = __float2half_rn(f[j]);
            ph[j] = hh;
            pl[j] = __float2half_rn(f[j] - __half2float(hh));
        }
    }
    __syncthreads();

    // ---- phase 2: Y_diag = (Mhi+Mlo) @ (Xhi+Xlo), 3-pass (drop lo*lo)
    // NOTE: B operand = xdt [s][p] row-major over k=s -> trans load
#pragma unroll
    for (int kk = 0; kk < 4; kk++) {
        uint32_t mh[2][4], ml[2][4], xh[2][2], xl[2][2];
#pragma unroll
        for (int mi = 0; mi < 2; mi++) {
            int row = warp_m * 32 + mi * 16 + (lane & 15);
            uint32_t ad = row * 144 + kk * 32 + (lane >> 4) * 16;
            ldm_x4(mh[mi], sb + Y_MH + ad);
            ldm_x4(ml[mi], sb + Y_ML + ad);
        }
#pragma unroll
        for (int ni = 0; ni < 2; ni++) {
            int pc = warp_n * 16 + ni * 8;
            uint32_t bd = (uint32_t)(kk * 16 + (lane & 15)) * 144 + pc * 2;
            ldm_x2t(xh[ni], sb + Y_XH + bd);
            ldm_x2t(xl[ni], sb + Y_XL + bd);
        }
#pragma unroll
        for (int mi = 0; mi < 2; mi++)
#pragma unroll
            for (int ni = 0; ni < 2; ni++) {
                mma_f16(acc[mi][ni], mh[mi], xh[ni]);
                mma_f16(acc[mi][ni], mh[mi], xl[ni]);
                mma_f16(acc[mi][ni], ml[mi], xh[ni]);
            }
    }

    // ---- epilogue: + x*D, store fp16
    float Dv = Dp[h];
#pragma unroll
    for (int mi = 0; mi < 2; mi++) {
        int r0 = warp_m * 32 + mi * 16 + (lane >> 2);
#pragma unroll
        for (int ni = 0; ni < 2; ni++) {
            int col = warp_n * 16 + ni * 8 + (lane & 3) * 2;
#pragma unroll
            for (int half = 0; half < 2; half++) {
                int r = r0 + half * 8;
                const __half* xp = g_x + (size_t)(row0 + r) * NI + h * HD + col;
                __half2 xh2 = *reinterpret_cast<const __half2*>(xp);
                float2 xf = __half22float2(xh2);
                float o0 = acc[mi][ni][half * 2 + 0] + xf.x * Dv;
                float o1 = acc[mi][ni][half * 2 + 1] + xf.y * Dv;
                __half2 oo = __floats2half2_rn(o0, o1);
                *reinterpret_cast<__half2*>(
                    g_yin + (size_t)(row0 + r) * NI + h * HD + col) = oo;
            }
        }
    }
}

// ------ gate with silu(z), RMSNorm, * norm_w; emit fp16 directly ------
__global__ void __launch_bounds__(256) gate_rms_kernel(const float* __restrict__ norm_w) {
    const int row = blockIdx.x;
    const int tid = threadIdx.x;
    const float* zrow = g_zx + (size_t)row * DIN;
    const __half* yrow = g_yin + (size_t)row * NI;
    float v[8];
    float ss = 0.f;
#pragma unroll
    for (int i = 0; i < 8; i++) {
        int idx = tid + i * 256;
        float z = zrow[idx];
        float val = __half2float(yrow[idx]) * siluf(z);
        v[i] = val;
        ss += val * val;
    }
    __shared__ float red[256];
    red[tid] = ss;
    __syncthreads();
    for (int s = 128; s > 0; s >>= 1) {
        if (tid < s) red[tid] += red[tid + s];
        __syncthreads();
    }
    float scale = rsqrtf(red[0] / (float)NI + 1e-5f);
#pragma unroll
    for (int i = 0; i < 8; i++) {
        int idx = tid + i * 256;
        float o = v[i] * scale * norm_w[idx];
        g_ynb[(size_t)row * NI + idx] = __float2half_rn(o);
    }
}

// ---------------- launch ----------------
template <typename T>
static T* symaddr(const void* sym) {
    void* p = nullptr;
    cudaGetSymbolAddress(&p, sym);
    return (T*)p;
}

extern "C" void kernel_launch(void* const* d_in, const int* in_sizes, int n_in,
                              void* d_out, int out_size)
{
    const float* u         = (const float*)d_in[0];
    const float* init_conv = (const float*)d_in[1];
    const float* init_ssm  = (const float*)d_in[2];
    const float* w_in      = (const float*)d_in[3];
    const float* conv_w    = (const float*)d_in[4];
    const float* conv_b    = (const float*)d_in[5];
    const float* dt_bias   = (const float*)d_in[6];
    const float* A_log     = (const float*)d_in[7];
    const float* Dp        = (const float*)d_in[8];
    const float* norm_w    = (const float*)d_in[9];
    const float* w_out     = (const float*)d_in[10];

    float* out       = (float*)d_out;
    float* out_y     = out;
    float* out_conv  = out + (size_t)ROWS * E_;
    float* out_final = out_conv + (size_t)B_ * CD * NCONV;

    float* pzx = symaddr<float>(g_zx);
    __half* p_u_h     = symaddr<__half>(g_u_h);
    __half* p_win_hi  = symaddr<__half>(g_win_hi);
    __half* p_win_lo  = symaddr<__half>(g_win_lo);
    __half* p_wout_hi = symaddr<__half>(g_wout_hi);
    __half* p_wout_lo = symaddr<__half>(g_wout_lo);
    __half* p_ynb     = symaddr<__half>(g_ynb);

    cudaFuncSetAttribute(gemm_f16, cudaFuncAttributeMaxDynamicSharedMemorySize, GM_SMEM);
    cudaFuncSetAttribute(states_kernel, cudaFuncAttributeMaxDynamicSharedMemorySize, STATES_SMEM);
    cudaFuncSetAttribute(y_kernel, cudaFuncAttributeMaxDynamicSharedMemorySize, Y_SMEM);

    // 0) operand conversions to fp16 (A single, B hi/lo)
    cvt_f16_kernel<<<(ROWS * E_ / 4 + 511) / 512, 512>>>(u, p_u_h, ROWS * E_);
    cvt_win16_kernel<<<(E_ * NPAD / 4 + 511) / 512, 512>>>(w_in);
    cvt_hilo16_kernel<<<(NI * E_ / 4 + 511) / 512, 512>>>(w_out, p_wout_hi, p_wout_lo, NI * E_);

    // 1) in-projection
    gemm_f16<<<dim3(NPAD / 128, ROWS / 256), 512, GM_SMEM>>>(
        p_u_h, p_win_hi, p_win_lo, pzx, ROWS, DIN, E_, NPAD);
    // 2) dt
    dt_kernel<<<(ROWS * NH + 255) / 256, 256>>>(dt_bias);
    // 3) conv + silu + split
    conv_kernel<<<dim3((CD / 4 + 255) / 256, L_ / 8, B_), 256>>>(init_conv, conv_w, conv_b);
    // 4) new_conv_state output
    convstate_kernel<<<(B_ * CD * NCONV + 255) / 256, 256>>>(out_conv);
    // 5) per-chunk Gram matrix
    gmat_kernel<<<B_ * NC, 256>>>();
    // 6) per-chunk states (fp16 output)
    states_kernel<<<dim3(NH, NC, B_), 256, STATES_SMEM>>>(A_log);
    // 7) cross-chunk scan (fp16 storage, prefetch)
    scan_kernel<<<dim3(8, NH, B_), 256>>>(init_ssm, out_final);
    // 8) Y via tensor cores (exact hi/lo fp16 pairs)
    y_kernel<<<dim3(NH, NC, B_), 256, Y_SMEM>>>(A_log, Dp);
    // 9) gate + rmsnorm (emits fp16)
    gate_rms_kernel<<<ROWS, 256>>>(norm_w);
    // 10) out-projection
    gemm_f16<<<dim3(E_ / 128, ROWS / 256), 512, GM_SMEM>>>(
        p_ynb, p_wout_hi, p_wout_lo, out_y, ROWS, E_, NI, E_);
}

// round 17
// speedup vs baseline: 2.1073x; 1.0322x over previous
#include <cuda_runtime.h>
#include <cuda_bf16.h>
#include <cuda_fp16.h>
#include <math.h>
#include <stdint.h>

// Problem constants
#define B_    2
#define L_    4096
#define E_    1024
#define NI    2048      // N_INNER
#define NS    128       // N_STATE
#define NH    32        // N_HEAD
#define HD    64        // HEADDIM
#define NCONV 4
#define CH    64        // CHUNK
#define NC    64        // chunks per sequence (L/CHUNK)
#define CD    2304      // CONV_DIM = NI + 2*NS
#define DIN   4384      // 2*NI + 2*NS + NH
#define NPAD  4480      // DIN padded to multiple of 128
#define ROWS  (B_*L_)   // 8192

// ---------------- scratch (device globals; no allocation allowed) ----------
__device__ float g_zx[(size_t)ROWS * DIN];
__device__ __half g_x [(size_t)ROWS * NI];                // fp16 conv output (x part)
__device__ float g_Bm[(size_t)ROWS * NS];
__device__ float g_Cm[(size_t)ROWS * NS];
__device__ float g_dt[(size_t)ROWS * NH];
__device__ float g_G [(size_t)B_ * NC * CH * CH];
__device__ __half g_st[(size_t)B_ * NC * NH * HD * NS];   // fp16 chunk/prev states
__device__ float g_asum[B_ * NC * NH];
__device__ __half g_yin[(size_t)ROWS * NI];               // fp16 pre-gate y

// fp16 operand copies for tensor-core GEMMs (A single, B hi/lo split)
__device__ __half g_u_h [(size_t)ROWS * E_];
__device__ __half g_win_hi[(size_t)E_ * NPAD];
__device__ __half g_win_lo[(size_t)E_ * NPAD];
__device__ __half g_wout_hi[(size_t)NI * E_];
__device__ __half g_wout_lo[(size_t)NI * E_];
__device__ __half g_ynb[(size_t)ROWS * NI];

// ---------------- small helpers ----------------
__device__ __forceinline__ float siluf(float x) { return x / (1.f + expf(-x)); }
__device__ __forceinline__ float softplusf(float x) {
    return (x > 20.f) ? x : log1pf(expf(x));
}
__device__ __forceinline__ uint32_t smem_u32(const void* p) {
    uint32_t a;
    asm("{ .reg .u64 t; cvta.to.shared.u64 t, %1; cvt.u32.u64 %0, t; }" : "=r"(a) : "l"(p));
    return a;
}
// load 4 halves (8B) -> 4 floats
__device__ __forceinline__ float4 ldh4(const __half* p) {
    uint2 raw = *reinterpret_cast<const uint2*>(p);
    __half2 h0 = *reinterpret_cast<__half2*>(&raw.x);
    __half2 h1 = *reinterpret_cast<__half2*>(&raw.y);
    float2 f0 = __half22float2(h0);
    float2 f1 = __half22float2(h1);
    return make_float4(f0.x, f0.y, f1.x, f1.y);
}
// store 4 floats as 4 halves (8B)
__device__ __forceinline__ void sth4(__half* p, float4 v) {
    __half2 h0 = __floats2half2_rn(v.x, v.y);
    __half2 h1 = __floats2half2_rn(v.z, v.w);
    uint2 raw;
    raw.x = *reinterpret_cast<uint32_t*>(&h0);
    raw.y = *reinterpret_cast<uint32_t*>(&h1);
    *reinterpret_cast<uint2*>(p) = raw;
}

// ---------------- packed f32x2 (Blackwell, base sm_100) ----------------
__device__ __forceinline__ uint64_t pack2(float x, float y) {
    uint64_t r;
    asm("mov.b64 %0, {%1, %2};" : "=l"(r) : "f"(x), "f"(y));
    return r;
}
__device__ __forceinline__ void unpack2(uint64_t v, float& x, float& y) {
    asm("mov.b64 {%0, %1}, %2;" : "=f"(x), "=f"(y) : "l"(v));
}
__device__ __forceinline__ void ffma2(uint64_t& d, uint64_t a, uint64_t b) {
    asm("fma.rn.f32x2 %0, %1, %2, %0;" : "+l"(d) : "l"(a), "l"(b));
}
__device__ __forceinline__ void fmul2(uint64_t& d, uint64_t a) {
    asm("mul.rn.f32x2 %0, %0, %1;" : "+l"(d) : "l"(a));
}

// ---------------- warp-MMA primitives (sm_80+, valid on base sm_100) -------
__device__ __forceinline__ void ldm_x4(uint32_t* r, uint32_t addr) {
    asm volatile("ldmatrix.sync.aligned.m8n8.x4.shared.b16 {%0,%1,%2,%3}, [%4];"
        : "=r"(r[0]), "=r"(r[1]), "=r"(r[2]), "=r"(r[3]) : "r"(addr));
}
__device__ __forceinline__ void ldm_x2t(uint32_t* r, uint32_t addr) {
    asm volatile("ldmatrix.sync.aligned.m8n8.x2.trans.shared.b16 {%0,%1}, [%2];"
        : "=r"(r[0]), "=r"(r[1]) : "r"(addr));
}
__device__ __forceinline__ void mma_f16(float* c, const uint32_t* a, const uint32_t* b) {
    asm volatile(
        "mma.sync.aligned.m16n8k16.row.col.f32.f16.f16.f32 "
        "{%0,%1,%2,%3}, {%4,%5,%6,%7}, {%8,%9}, {%0,%1,%2,%3};"
        : "+f"(c[0]), "+f"(c[1]), "+f"(c[2]), "+f"(c[3])
        : "r"(a[0]), "r"(a[1]), "r"(a[2]), "r"(a[3]), "r"(b[0]), "r"(b[1]));
}
__device__ __forceinline__ void cp16(uint32_t dst, const void* src) {
    asm volatile("cp.async.cg.shared.global [%0], [%1], 16;" :: "r"(dst), "l"(src));
}
#define CP_COMMIT() asm volatile("cp.async.commit_group;" ::: "memory")
#define CP_WAIT(n)  asm volatile("cp.async.wait_group %0;" :: "n"(n) : "memory")

// ---------------- fp32 -> fp16 conversion kernels ----------------
__global__ void cvt_f16_kernel(const float* __restrict__ s, __half* __restrict__ dst, int n) {
    int i = (blockIdx.x * blockDim.x + threadIdx.x) * 4;
    if (i >= n) return;
    float4 v = *(const float4*)(s + i);
    sth4(dst + i, v);
}

__global__ void cvt_hilo16_kernel(const float* __restrict__ s,
                                  __half* __restrict__ hi, __half* __restrict__ lo, int n)
{
    int i = (blockIdx.x * blockDim.x + threadIdx.x) * 4;
    if (i >= n) return;
    float4 v = *(const float4*)(s + i);
    float f[4] = {v.x, v.y, v.z, v.w};
    float fh[4], fl[4];
#pragma unroll
    for (int j = 0; j < 4; j++) {
        __half h = __float2half_rn(f[j]);
        fh[j] = __half2float(h);
        fl[j] = f[j] - fh[j];
    }
    sth4(hi + i, make_float4(fh[0], fh[1], fh[2], fh[3]));
    sth4(lo + i, make_float4(fl[0], fl[1], fl[2], fl[3]));
}

// w_in [E_][DIN] -> padded [E_][NPAD] fp16 hi/lo (zero-fill cols >= DIN)
__global__ void cvt_win16_kernel(const float* __restrict__ w) {
    int i4 = (blockIdx.x * blockDim.x + threadIdx.x) * 4;
    if (i4 >= E_ * NPAD) return;
    int row = i4 / NPAD, col = i4 % NPAD;
    float f[4];
    if (col + 3 < DIN) {
        float4 v = *(const float4*)(w + (size_t)row * DIN + col);
        f[0] = v.x; f[1] = v.y; f[2] = v.z; f[3] = v.w;
    } else {
#pragma unroll
        for (int j = 0; j < 4; j++) {
            int cc = col + j;
            f[j] = (cc < DIN) ? w[(size_t)row * DIN + cc] : 0.f;
        }
    }
    float fh[4], fl[4];
#pragma unroll
    for (int j = 0; j < 4; j++) {
        __half h = __float2half_rn(f[j]);
        fh[j] = __half2float(h);
        fl[j] = f[j] - fh[j];
    }
    sth4(g_win_hi + i4, make_float4(fh[0], fh[1], fh[2], fh[3]));
    sth4(g_win_lo + i4, make_float4(fl[0], fl[1], fl[2], fl[3]));
}

// ================= tensor-core GEMM: C[M,N] = A[M,K] @ B[K,N] ==============
// fp16 asymmetric split: A single fp16, B fp16 hi+lo; C = A*(Bhi+Blo), fp32 acc.
// Block tile 256x128, 512 threads (16 warps 4x4, 64x32/warp).
// K-tile 64 (4 k16 steps), 3-stage cp.async.
// Stage: A[256][72]h (36864) | Bhi[64][136]h (17408) | Blo (17408) = 71680 B
#define ST_B_HI 36864
#define ST_B_LO 54272
#define ST_BYTES 71680
#define STG 3
#define GM_SMEM (STG * ST_BYTES)    // 215040 B

__global__ void __launch_bounds__(512, 1) gemm_f16(
    const __half* __restrict__ A,
    const __half* __restrict__ Bh, const __half* __restrict__ Bl,
    float* __restrict__ C, int M, int N, int K, int ldB)
{
    extern __shared__ char smem[];
    const uint32_t sb = smem_u32(smem);
    const int tid = threadIdx.x;
    const int wid = tid >> 5, lane = tid & 31;
    const int m0 = blockIdx.y * 256;
    const int n0 = blockIdx.x * 128;
    const int warp_m = wid >> 2;
    const int warp_n = wid & 3;

    float acc[4][4][4];
#pragma unroll
    for (int i = 0; i < 4; i++)
#pragma unroll
        for (int j = 0; j < 4; j++)
#pragma unroll
            for (int k = 0; k < 4; k++) acc[i][j][k] = 0.f;

    const int KTn = K >> 6;   // K-tiles of 64

    // A: 2048 chunks (256 rows x 8x16B); thread c = tid + j*512, j=0..3
    // B: 1024 positions (64 rows x 16x16B); thread p = tid, tid+512 (hi+lo each)
#define LOAD_STAGE(KT_) do { \
    const int k0_ = (KT_) << 6; \
    const uint32_t st_ = sb + ((KT_) % STG) * ST_BYTES; \
    _Pragma("unroll") \
    for (int j_ = 0; j_ < 4; j_++) { \
        int c_ = tid + j_ * 512; \
        int ar_ = c_ >> 3, ac_ = c_ & 7; \
        size_t go = (size_t)(m0 + ar_) * K + k0_ + ac_ * 8; \
        cp16(st_ + ar_ * 144 + ac_ * 16, A + go); \
    } \
    _Pragma("unroll") \
    for (int j_ = 0; j_ < 2; j_++) { \
        int p_ = tid + j_ * 512; \
        int bkr_ = p_ >> 4, bch_ = p_ & 15; \
        size_t go = (size_t)(k0_ + bkr_) * ldB + n0 + bch_ * 8; \
        uint32_t so = st_ + ST_B_HI + bkr_ * 272 + bch_ * 16; \
        cp16(so, Bh + go); cp16(so + 17408, Bl + go); \
    } \
} while (0)

#pragma unroll
    for (int s = 0; s < STG - 1; s++) {
        if (s < KTn) LOAD_STAGE(s);
        CP_COMMIT();
    }

    for (int kt = 0; kt < KTn; kt++) {
        CP_WAIT(STG - 2);
        __syncthreads();
        const uint32_t sA   = sb + (kt % STG) * ST_BYTES;
        const uint32_t sBhi = sA + ST_B_HI;
        const uint32_t sBlo = sA + ST_B_LO;
#pragma unroll
        for (int ks = 0; ks < 4; ks++) {
            uint32_t a[4][4], b_hi[4][2], b_lo[4][2];
#pragma unroll
            for (int mi = 0; mi < 4; mi++) {
                int row = warp_m * 64 + mi * 16 + (lane & 15);
                uint32_t addr = row * 144 + ks * 32 + (lane >> 4) * 16;
                ldm_x4(a[mi], sA + addr);
            }
#pragma unroll
            for (int ni = 0; ni < 4; ni++) {
                int krow = ks * 16 + (lane & 15);
                int ncol = warp_n * 32 + ni * 8;
                uint32_t addr = krow * 272 + ncol * 2;
                ldm_x2t(b_hi[ni], sBhi + addr);
                ldm_x2t(b_lo[ni], sBlo + addr);
            }
#pragma unroll
            for (int mi = 0; mi < 4; mi++)
#pragma unroll
                for (int ni = 0; ni < 4; ni++) {
                    mma_f16(acc[mi][ni], a[mi], b_hi[ni]);
                    mma_f16(acc[mi][ni], a[mi], b_lo[ni]);
                }
        }
        if (kt + STG - 1 < KTn) LOAD_STAGE(kt + STG - 1);
        CP_COMMIT();
    }
#undef LOAD_STAGE

#pragma unroll
    for (int mi = 0; mi < 4; mi++) {
        int row = m0 + warp_m * 64 + mi * 16 + (lane >> 2);
#pragma unroll
        for (int ni = 0; ni < 4; ni++) {
            int col = n0 + warp_n * 32 + ni * 8 + (lane & 3) * 2;
            if (col < N) {
                *(float2*)(C + (size_t)row * N + col) =
                    make_float2(acc[mi][ni][0], acc[mi][ni][1]);
                *(float2*)(C + (size_t)(row + 8) * N + col) =
                    make_float2(acc[mi][ni][2], acc[mi][ni][3]);
            }
        }
    }
}

// ---------------- dt = softplus(raw + bias) ----------------
__global__ void dt_kernel(const float* __restrict__ dt_bias) {
    int i = blockIdx.x * blockDim.x + threadIdx.x;
    if (i >= ROWS * NH) return;
    int row = i / NH, h = i % NH;
    float x = g_zx[(size_t)row * DIN + (DIN - NH) + h] + dt_bias[h];
    g_dt[i] = softplusf(x);
}

// --- depthwise causal conv w4 + silu + split; 4 channels x 8 timesteps ----
__global__ void conv_kernel(const float* __restrict__ init_conv,
                            const float* __restrict__ conv_w,
                            const float* __restrict__ conv_b)
{
    int d4 = blockIdx.x * blockDim.x + threadIdx.x;
    if (d4 >= CD / 4) return;
    const int d = d4 * 4;
    const int t0 = blockIdx.y * 8;
    const int b = blockIdx.z;
    float4 cw[4];
#pragma unroll
    for (int j = 0; j < 4; j++) cw[j] = *(const float4*)(conv_w + (d + j) * 4);
    float4 bias = *(const float4*)(conv_b + d);
    float4 win[11];
#pragma unroll
    for (int i = 0; i < 11; i++) {
        int ti = t0 - 3 + i;
        if (ti >= 0) {
            win[i] = *(const float4*)(g_zx + (size_t)(b * L_ + ti) * DIN + NI + d);
        } else {
            win[i].x = init_conv[((size_t)b * CD + d + 0) * NCONV + (4 + ti)];
            win[i].y = init_conv[((size_t)b * CD + d + 1) * NCONV + (4 + ti)];
            win[i].z = init_conv[((size_t)b * CD + d + 2) * NCONV + (4 + ti)];
            win[i].w = init_conv[((size_t)b * CD + d + 3) * NCONV + (4 + ti)];
        }
    }
#pragma unroll
    for (int jt = 0; jt < 8; jt++) {
        float4 o;
        o.x = siluf(bias.x + cw[0].x*win[jt].x + cw[0].y*win[jt+1].x + cw[0].z*win[jt+2].x + cw[0].w*win[jt+3].x);
        o.y = siluf(bias.y + cw[1].x*win[jt].y + cw[1].y*win[jt+1].y + cw[1].z*win[jt+2].y + cw[1].w*win[jt+3].y);
        o.z = siluf(bias.z + cw[2].x*win[jt].z + cw[2].y*win[jt+1].z + cw[2].z*win[jt+2].z + cw[2].w*win[jt+3].z);
        o.w = siluf(bias.w + cw[3].x*win[jt].w + cw[3].y*win[jt+1].w + cw[3].z*win[jt+2].w + cw[3].w*win[jt+3].w);
        int row = b * L_ + t0 + jt;
        if (d < NI)           sth4(g_x + (size_t)row * NI + d, o);
        else if (d < NI + NS) *(float4*)(g_Bm + (size_t)row * NS + (d - NI)) = o;
        else                  *(float4*)(g_Cm + (size_t)row * NS + (d - NI - NS)) = o;
    }
}

// ---------------- new_conv_state output ----------------
__global__ void convstate_kernel(float* __restrict__ out) {
    int i = blockIdx.x * blockDim.x + threadIdx.x;
    if (i >= B_ * CD * NCONV) return;
    int k = i % NCONV;
    int d = (i / NCONV) % CD;
    int b = i / (NCONV * CD);
    out[i] = g_zx[(size_t)(b * L_ + (L_ - 4 + k)) * DIN + NI + d];
}

// ---------------- per-chunk Gram matrix G[l][s] = sum_n C[l,n]B[s,n] -------
__global__ void __launch_bounds__(256) gmat_kernel() {
    const int bc = blockIdx.x;
    const int b = bc / NC, c = bc % NC;
    const int row0 = b * L_ + c * CH;
    const int tid = threadIdx.x;
    __shared__ float sC[64 * 33];
    __shared__ float sB[64 * 33];
    const int l = tid >> 2;
    const int s0 = (tid & 3) * 16;
    float acc[16];
#pragma unroll
    for (int j = 0; j < 16; j++) acc[j] = 0.f;
    for (int n0 = 0; n0 < NS; n0 += 32) {
        for (int i = tid; i < 64 * 32; i += 256) {
            int r = i >> 5, nn = i & 31;
            sC[r * 33 + nn] = g_Cm[(size_t)(row0 + r) * NS + n0 + nn];
            sB[r * 33 + nn] = g_Bm[(size_t)(row0 + r) * NS + n0 + nn];
        }
        __syncthreads();
        for (int nn = 0; nn < 32; nn++) {
            float cv = sC[l * 33 + nn];
#pragma unroll
            for (int j = 0; j < 16; j++) acc[j] += cv * sB[(s0 + j) * 33 + nn];
        }
        __syncthreads();
    }
    float* Gp = g_G + (size_t)bc * (CH * CH);
#pragma unroll
    for (int j = 0; j < 16; j++) Gp[l * 64 + s0 + j] = acc[j];
}

// ------- per-chunk states[p][n] = sum_l B[l,n]*decay[l]*dt[l]*x[l,p] -------
#define STATES_SMEM ((64*68 + 64*132) * 4)
__global__ void __launch_bounds__(256) states_kernel(const float* __restrict__ A_log) {
    extern __shared__ float sm[];
    float* xs = sm;             // [64][68]
    float* sB = sm + 64 * 68;   // [64][132]
    __shared__ float sdt[64], w[64];
    __shared__ float asum_s;
    const int h = blockIdx.x, c = blockIdx.y, b = blockIdx.z;
    const int tid = threadIdx.x;
    const int row0 = b * L_ + c * CH;
    if (tid < 64) sdt[tid] = g_dt[(size_t)(row0 + tid) * NH + h];
    __syncthreads();
    if (tid == 0) {
        float A = -expf(A_log[h]);
        float s = 0.f;
        for (int l = 0; l < 64; l++) { s += A * sdt[l]; w[l] = s; }  // w = acs (temp)
        asum_s = s;
        g_asum[(b * NC + c) * NH + h] = s;
    }
    __syncthreads();
    float wv = (tid < 64) ? expf(asum_s - w[tid]) * sdt[tid] : 0.f;
    __syncthreads();
    if (tid < 64) w[tid] = wv;
    __syncthreads();

    for (int i = tid; i < 64 * 16; i += 256) {
        int l = i >> 4, q = i & 15;
        float4 v = ldh4(g_x + (size_t)(row0 + l) * NI + h * HD + q * 4);
        float wl = w[l];
        *(float4*)(xs + l * 68 + q * 4) = make_float4(v.x * wl, v.y * wl, v.z * wl, v.w * wl);
    }
    for (int i = tid; i < 64 * 32; i += 256) {
        int l = i >> 5, q = i & 31;
        *(float4*)(sB + l * 132 + q * 4) =
            *(const float4*)(g_Bm + (size_t)(row0 + l) * NS + q * 4);
    }
    __syncthreads();

    const int pg = tid >> 5;   // 8 p-groups of 8
    const int ng = tid & 31;   // 32 n-pairs (x2 halves)
    uint64_t acc2[4][4];
    const uint64_t z2 = pack2(0.f, 0.f);
#pragma unroll
    for (int i = 0; i < 4; i++)
#pragma unroll
        for (int j = 0; j < 4; j++) acc2[i][j] = z2;

    for (int l = 0; l < 64; l++) {
        const ulonglong2* xr = (const ulonglong2*)(xs + l * 68 + pg * 8);
        ulonglong2 xa = xr[0], xb = xr[1];
        float2 bA = *(const float2*)(sB + l * 132 + 2 * ng);
        float2 bB = *(const float2*)(sB + l * 132 + 64 + 2 * ng);
        uint64_t bb0 = pack2(bA.x, bA.x), bb1 = pack2(bA.y, bA.y);
        uint64_t bb2 = pack2(bB.x, bB.x), bb3 = pack2(bB.y, bB.y);
        uint64_t xv[4] = {xa.x, xa.y, xb.x, xb.y};
#pragma unroll
        for (int i = 0; i < 4; i++) {
            ffma2(acc2[i][0], xv[i], bb0);
            ffma2(acc2[i][1], xv[i], bb1);
            ffma2(acc2[i][2], xv[i], bb2);
            ffma2(acc2[i][3], xv[i], bb3);
        }
    }
    __half* outp = g_st + (size_t)((b * NC + c) * NH + h) * HD * NS;
#pragma unroll
    for (int i = 0; i < 4; i++) {
        float a0e, a0o, a1e, a1o, a2e, a2o, a3e, a3o;
        unpack2(acc2[i][0], a0e, a0o);
        unpack2(acc2[i][1], a1e, a1o);
        unpack2(acc2[i][2], a2e, a2o);
        unpack2(acc2[i][3], a3e, a3o);
        int pe = pg * 8 + i * 2, po = pe + 1;
        *(__half2*)(outp + (size_t)pe * NS + 2 * ng)      = __floats2half2_rn(a0e, a1e);
        *(__half2*)(outp + (size_t)pe * NS + 64 + 2 * ng) = __floats2half2_rn(a2e, a3e);
        *(__half2*)(outp + (size_t)po * NS + 2 * ng)      = __floats2half2_rn(a0o, a1o);
        *(__half2*)(outp + (size_t)po * NS + 64 + 2 * ng) = __floats2half2_rn(a2o, a3o);
    }
}

// ------- cross-chunk state scan (fp16 storage, fp32 accumulate, prefetch) ---
__global__ void __launch_bounds__(256) scan_kernel(const float* __restrict__ init_ssm,
                                                   float* __restrict__ final_out)
{
    const int seg = blockIdx.x;
    const int h = blockIdx.y, b = blockIdx.z;
    const int tid = threadIdx.x;
    const int e = seg * 1024 + tid * 4;
    const size_t base_bh = (size_t)(b * NH + h) * HD * NS;
    const size_t stride_c = (size_t)NH * HD * NS;
    __half* p0 = g_st + (size_t)(b * NC) * stride_c + (size_t)h * HD * NS + e;
    float4 S = *reinterpret_cast<const float4*>(init_ssm + base_bh + e);
    uint2 raw = *reinterpret_cast<uint2*>(p0);
    for (int c = 0; c < NC; c++) {
        uint2 nxt;
        if (c + 1 < NC)
            nxt = *reinterpret_cast<uint2*>(p0 + (size_t)(c + 1) * stride_c);
        float dec = expf(g_asum[(b * NC + c) * NH + h]);
        __half2 h0 = *reinterpret_cast<__half2*>(&raw.x);
        __half2 h1 = *reinterpret_cast<__half2*>(&raw.y);
        float2 f0 = __half22float2(h0);
        float2 f1 = __half22float2(h1);
        __half2 s0 = __floats2half2_rn(S.x, S.y);
        __half2 s1 = __floats2half2_rn(S.z, S.w);
        uint2 sr;
        sr.x = *reinterpret_cast<uint32_t*>(&s0);
        sr.y = *reinterpret_cast<uint32_t*>(&s1);
        *reinterpret_cast<uint2*>(p0 + (size_t)c * stride_c) = sr;
        S.x = dec * S.x + f0.x;
        S.y = dec * S.y + f0.y;
        S.z = dec * S.z + f1.x;
        S.w = dec * S.w + f1.y;
        raw = nxt;
    }
    *reinterpret_cast<float4*>(final_out + base_bh + e) = S;
}

// ====== Y = exp(Acs)*(C @ Sprev^T) + (G∘L)@xdt + x*D — tensor-core ========
#define Y_CH 0
#define Y_CL 17408
#define Y_ST 34816
#define Y_SMEM (34816 + 18432)     // 53248 B
#define Y_MH 0
#define Y_ML 9216
#define Y_XH 18432
#define Y_XL 27648
__global__ void __launch_bounds__(256) y_kernel(const float* __restrict__ A_log,
                                                const float* __restrict__ Dp)
{
    extern __shared__ char ysm[];
    const uint32_t sb = smem_u32(ysm);
    __half* smh = (__half*)ysm;
    __shared__ float acs[64], sdt[64];
    const int h = blockIdx.x, c = blockIdx.y, b = blockIdx.z;
    const int tid = threadIdx.x;
    const int wid = tid >> 5, lane = tid & 31;
    const int warp_m = wid >> 2;
    const int warp_n = wid & 3;
    const int row0 = b * L_ + c * CH;

    if (tid < 64) sdt[tid] = g_dt[(size_t)(row0 + tid) * NH + h];
    __syncthreads();
    if (tid == 0) {
        float A = -expf(A_log[h]);
        float s = 0.f;
        for (int l = 0; l < 64; l++) { s += A * sdt[l]; acs[l] = s; }
    }
    __syncthreads();

    for (int i = tid; i < 64 * 32; i += 256) {
        int l = i >> 5, q = i & 31;
        float4 v = *(const float4*)(g_Cm + (size_t)(row0 + l) * NS + q * 4);
        float f[4] = {v.x, v.y, v.z, v.w};
        __half* ph = smh + Y_CH / 2 + l * 136 + q * 4;
        __half* pl = smh + Y_CL / 2 + l * 136 + q * 4;
#pragma unroll
        for (int j = 0; j < 4; j++) {
            __half hh = __float2half_rn(f[j]);
            ph[j] = hh;
            pl[j] = __float2half_rn(f[j] - __half2float(hh));
        }
    }
    const __half* Sp = g_st + (size_t)((b * NC + c) * NH + h) * HD * NS;
    for (int i = tid; i < 64 * 32; i += 256) {
        int p = i >> 5, q = i & 31;
        uint2 raw = *reinterpret_cast<const uint2*>(Sp + (size_t)p * NS + q * 4);
        __half2 h0 = *reinterpret_cast<__half2*>(&raw.x);
        __half2 h1 = *reinterpret_cast<__half2*>(&raw.y);
        __half* st = smh + Y_ST / 2;
        st[(q * 4 + 0) * 72 + p] = __low2half(h0);
        st[(q * 4 + 1) * 72 + p] = __high2half(h0);
        st[(q * 4 + 2) * 72 + p] = __low2half(h1);
        st[(q * 4 + 3) * 72 + p] = __high2half(h1);
    }
    __syncthreads();

    float acc[2][2][4];
#pragma unroll
    for (int i = 0; i < 2; i++)
#pragma unroll
        for (int j = 0; j < 2; j++)
#pragma unroll
            for (int k = 0; k < 4; k++) acc[i][j][k] = 0.f;

#pragma unroll
    for (int kk = 0; kk < 8; kk++) {
        uint32_t ah[2][4], al[2][4], bb[2][2];
#pragma unroll
        for (int mi = 0; mi < 2; mi++) {
            int row = warp_m * 32 + mi * 16 + (lane & 15);
            uint32_t ad = row * 272 + kk * 32 + (lane >> 4) * 16;
            ldm_x4(ah[mi], sb + Y_CH + ad);
            ldm_x4(al[mi], sb + Y_CL + ad);
        }
#pragma unroll
        for (int ni = 0; ni < 2; ni++) {
            int pc = warp_n * 16 + ni * 8;
            uint32_t bd = (uint32_t)(kk * 16 + (lane & 15)) * 144 + pc * 2;
            ldm_x2t(bb[ni], sb + Y_ST + bd);
        }
#pragma unroll
        for (int mi = 0; mi < 2; mi++)
#pragma unroll
            for (int ni = 0; ni < 2; ni++) {
                mma_f16(acc[mi][ni], ah[mi], bb[ni]);
                mma_f16(acc[mi][ni], al[mi], bb[ni]);
            }
    }
#pragma unroll
    for (int mi = 0; mi < 2; mi++) {
        int r0 = warp_m * 32 + mi * 16 + (lane >> 2);
        float e0 = expf(acs[r0]);
        float e1 = expf(acs[r0 + 8]);
#pragma unroll
        for (int ni = 0; ni < 2; ni++) {
            acc[mi][ni][0] *= e0; acc[mi][ni][1] *= e0;
            acc[mi][ni][2] *= e1; acc[mi][ni][3] *= e1;
        }
    }
    __syncthreads();

    const float* Gp = g_G + (size_t)(b * NC + c) * (CH * CH);
    for (int i = tid; i < 64 * 64; i += 256) {
        int r = i >> 6, s = i & 63;
        float val = (s <= r) ? Gp[r * 64 + s] * expf(acs[r] - acs[s]) : 0.f;
        __half hh = __float2half_rn(val);
        smh[Y_MH / 2 + r * 72 + s] = hh;
        smh[Y_ML / 2 + r * 72 + s] = __float2half_rn(val - __half2float(hh));
    }
    for (int i = tid; i < 64 * 16; i += 256) {
        int s = i >> 4, q = i & 15;
        float4 v = ldh4(g_x + (size_t)(row0 + s) * NI + h * HD + q * 4);
        float d = sdt[s];
        float f[4] = {v.x * d, v.y * d, v.z * d, v.w * d};
        __half* ph = smh + Y_XH / 2 + s * 72 + q * 4;
        __half* pl = smh + Y_XL / 2 + s * 72 + q * 4;
#pragma unroll
        for (int j = 0; j < 4; j++) {
            __half hh = __float2half_rn(f[j]);
            ph[j] = hh;
            pl[j] = __float2half_rn(f[j] - __half2float(hh));
        }
    }
    __syncthreads();

#pragma unroll
    for (int kk = 0; kk < 4; kk++) {
        uint32_t mh[2][4], ml[2][4], xh[2][2], xl[2][2];
#pragma unroll
        for (int mi = 0; mi < 2; mi++) {
            int row = warp_m * 32 + mi * 16 + (lane & 15);
            uint32_t ad = row * 144 + kk * 32 + (lane >> 4) * 16;
            ldm_x4(mh[mi], sb + Y_MH + ad);
            ldm_x4(ml[mi], sb + Y_ML + ad);
        }
#pragma unroll
        for (int ni = 0; ni < 2; ni++) {
            int pc = warp_n * 16 + ni * 8;
            uint32_t bd = (uint32_t)(kk * 16 + (lane & 15)) * 144 + pc * 2;
            ldm_x2t(xh[ni], sb + Y_XH + bd);
            ldm_x2t(xl[ni], sb + Y_XL + bd);
        }
#pragma unroll
        for (int mi = 0; mi < 2; mi++)
#pragma unroll
            for (int ni = 0; ni < 2; ni++) {
                mma_f16(acc[mi][ni], mh[mi], xh[ni]);
                mma_f16(acc[mi][ni], mh[mi], xl[ni]);
                mma_f16(acc[mi][ni], ml[mi], xh[ni]);
            }
    }

    float Dv = Dp[h];
#pragma unroll
    for (int mi = 0; mi < 2; mi++) {
        int r0 = warp_m * 32 + mi * 16 + (lane >> 2);
#pragma unroll
        for (int ni = 0; ni < 2; ni++) {
            int col = warp_n * 16 + ni * 8 + (lane & 3) * 2;
#pragma unroll
            for (int half = 0; half < 2; half++) {
                int r = r0 + half * 8;
                const __half* xp = g_x + (size_t)(row0 + r) * NI + h * HD + col;
                __half2 xh2 = *reinterpret_cast<const __half2*>(xp);
                float2 xf = __half22float2(xh2);
                float o0 = acc[mi][ni][half * 2 + 0] + xf.x * Dv;
                float o1 = acc[mi][ni][half * 2 + 1] + xf.y * Dv;
                __half2 oo = __floats2half2_rn(o0, o1);
                *reinterpret_cast<__half2*>(
                    g_yin + (size_t)(row0 + r) * NI + h * HD + col) = oo;
            }
        }
    }
}

// ------ gate with silu(z), RMSNorm, * norm_w; emit fp16 directly ------
__global__ void __launch_bounds__(256) gate_rms_kernel(const float* __restrict__ norm_w) {
    const int row = blockIdx.x;
    const int tid = threadIdx.x;
    const float* zrow = g_zx + (size_t)row * DIN;
    const __half* yrow = g_yin + (size_t)row * NI;
    float v[8];
    float ss = 0.f;
#pragma unroll
    for (int i = 0; i < 8; i++) {
        int idx = tid + i * 256;
        float z = zrow[idx];
        float val = __half2float(yrow[idx]) * siluf(z);
        v[i] = val;
        ss += val * val;
    }
    __shared__ float red[256];
    red[tid] = ss;
    __syncthreads();
    for (int s = 128; s > 0; s >>= 1) {
        if (tid < s) red[tid] += red[tid + s];
        __syncthreads();
    }
    float scale = rsqrtf(red[0] / (float)NI + 1e-5f);
#pragma unroll
    for (int i = 0; i < 8; i++) {
        int idx = tid + i * 256;
        float o = v[i] * scale * norm_w[idx];
        g_ynb[(size_t)row * NI + idx] = __float2half_rn(o);
    }
}

// ---------------- launch ----------------
template <typename T>
static T* symaddr(const void* sym) {
    void* p = nullptr;
    cudaGetSymbolAddress(&p, sym);
    return (T*)p;
}

extern "C" void kernel_launch(void* const* d_in, const int* in_sizes, int n_in,
                              void* d_out, int out_size)
{
    const float* u         = (const float*)d_in[0];
    const float* init_conv = (const float*)d_in[1];
    const float* init_ssm  = (const float*)d_in[2];
    const float* w_in      = (const float*)d_in[3];
    const float* conv_w    = (const float*)d_in[4];
    const float* conv_b    = (const float*)d_in[5];
    const float* dt_bias   = (const float*)d_in[6];
    const float* A_log     = (const float*)d_in[7];
    const float* Dp        = (const float*)d_in[8];
    const float* norm_w    = (const float*)d_in[9];
    const float* w_out     = (const float*)d_in[10];

    float* out       = (float*)d_out;
    float* out_y     = out;
    float* out_conv  = out + (size_t)ROWS * E_;
    float* out_final = out_conv + (size_t)B_ * CD * NCONV;

    float* pzx = symaddr<float>(g_zx);
    __half* p_u_h     = symaddr<__half>(g_u_h);
    __half* p_win_hi  = symaddr<__half>(g_win_hi);
    __half* p_win_lo  = symaddr<__half>(g_win_lo);
    __half* p_wout_hi = symaddr<__half>(g_wout_hi);
    __half* p_wout_lo = symaddr<__half>(g_wout_lo);
    __half* p_ynb     = symaddr<__half>(g_ynb);

    cudaFuncSetAttribute(gemm_f16, cudaFuncAttributeMaxDynamicSharedMemorySize, GM_SMEM);
    cudaFuncSetAttribute(states_kernel, cudaFuncAttributeMaxDynamicSharedMemorySize, STATES_SMEM);
    cudaFuncSetAttribute(y_kernel, cudaFuncAttributeMaxDynamicSharedMemorySize, Y_SMEM);

    // 0) operand conversions to fp16 (A single, B hi/lo)
    cvt_f16_kernel<<<(ROWS * E_ / 4 + 511) / 512, 512>>>(u, p_u_h, ROWS * E_);
    cvt_win16_kernel<<<(E_ * NPAD / 4 + 511) / 512, 512>>>(w_in);
    cvt_hilo16_kernel<<<(NI * E_ / 4 + 511) / 512, 512>>>(w_out, p_wout_hi, p_wout_lo, NI * E_);

    // 1) in-projection
    gemm_f16<<<dim3(NPAD / 128, ROWS / 256), 512, GM_SMEM>>>(
        p_u_h, p_win_hi, p_win_lo, pzx, ROWS, DIN, E_, NPAD);
    // 2) dt
    dt_kernel<<<(ROWS * NH + 255) / 256, 256>>>(dt_bias);
    // 3) conv + silu + split
    conv_kernel<<<dim3((CD / 4 + 255) / 256, L_ / 8, B_), 256>>>(init_conv, conv_w, conv_b);
    // 4) new_conv_state output
    convstate_kernel<<<(B_ * CD * NCONV + 255) / 256, 256>>>(out_conv);
    // 5) per-chunk Gram matrix
    gmat_kernel<<<B_ * NC, 256>>>();
    // 6) per-chunk states (fp16 output)
    states_kernel<<<dim3(NH, NC, B_), 256, STATES_SMEM>>>(A_log);
    // 7) cross-chunk scan (fp16 storage, prefetch)
    scan_kernel<<<dim3(8, NH, B_), 256>>>(init_ssm, out_final);
    // 8) Y via tensor cores (exact hi/lo fp16 pairs)
    y_kernel<<<dim3(NH, NC, B_), 256, Y_SMEM>>>(A_log, Dp);
    // 9) gate + rmsnorm (emits fp16)
    gate_rms_kernel<<<ROWS, 256>>>(norm_w);
    // 10) out-projection
    gemm_f16<<<dim3(E_ / 128, ROWS / 256), 512, GM_SMEM>>>(
        p_ynb, p_wout_hi, p_wout_lo, out_y, ROWS, E_, NI, E_);
}